// round 4
// baseline (speedup 1.0000x reference)
#include <cuda_runtime.h>
#include <math.h>
#include <stdint.h>

// ---------------------------------------------------------------------------
// Problem constants
// ---------------------------------------------------------------------------
#define BWIN   64
#define NTOK   512
#define CDIM   384
#define NHEAD  12
#define HDIM   32
#define LPOS   3375
#define PDIM   24
#define SCALE  0.17677669529663687f

// ---------------------------------------------------------------------------
// Scratch
// ---------------------------------------------------------------------------
__device__ float g_pos[LPOS * NHEAD];
__device__ float g_bias[NHEAD * NTOK * NTOK];
__device__ float g_Q[BWIN * NHEAD * NTOK * HDIM];
__device__ float g_K[BWIN * NHEAD * NTOK * HDIM];
__device__ float g_V[BWIN * NHEAD * NTOK * HDIM];
__device__ float g_att[BWIN * NTOK * CDIM];

// ---------------------------------------------------------------------------
// tf32 helpers (portable HMMA path — works on base sm_103 PTX target)
// ---------------------------------------------------------------------------
__device__ __forceinline__ uint32_t f2tf32(float f) {
    uint32_t r;
    asm("cvt.rna.tf32.f32 %0, %1;" : "=r"(r) : "f"(f));
    return r;
}
__device__ __forceinline__ void mma_tf32(float c[4], const uint32_t a[4],
                                         const uint32_t b[2]) {
    asm volatile(
        "mma.sync.aligned.m16n8k8.row.col.f32.tf32.tf32.f32 "
        "{%0,%1,%2,%3}, {%4,%5,%6,%7}, {%8,%9}, {%0,%1,%2,%3};"
        : "+f"(c[0]), "+f"(c[1]), "+f"(c[2]), "+f"(c[3])
        : "r"(a[0]), "r"(a[1]), "r"(a[2]), "r"(a[3]),
          "r"(b[0]), "r"(b[1]));
}

// ---------------------------------------------------------------------------
// Kernel 1: dynamic position-bias MLP
// ---------------------------------------------------------------------------
__device__ __forceinline__ void ln_relu(const float* in, float* t,
                                        const float* g, const float* bt) {
    float m = 0.f;
    #pragma unroll
    for (int i = 0; i < PDIM; i++) m += in[i];
    m *= (1.0f / PDIM);
    float v = 0.f;
    #pragma unroll
    for (int i = 0; i < PDIM; i++) { float d = in[i] - m; v += d * d; }
    v *= (1.0f / PDIM);
    float inv = rsqrtf(v + 1e-5f);
    #pragma unroll
    for (int i = 0; i < PDIM; i++) {
        float y = (in[i] - m) * inv * g[i] + bt[i];
        t[i] = fmaxf(y, 0.f);
    }
}

__global__ void pos_mlp_kernel(
    const float* __restrict__ pw,  const float* __restrict__ pb,
    const float* __restrict__ g1,  const float* __restrict__ b1,
    const float* __restrict__ w1,  const float* __restrict__ wb1,
    const float* __restrict__ g2,  const float* __restrict__ b2,
    const float* __restrict__ w2,  const float* __restrict__ wb2,
    const float* __restrict__ g3,  const float* __restrict__ b3,
    const float* __restrict__ w3,  const float* __restrict__ wb3)
{
    int l = blockIdx.x * blockDim.x + threadIdx.x;
    if (l >= LPOS) return;
    float c0 = (float)(l / 225 - 7);
    float c1 = (float)((l / 15) % 15 - 7);
    float c2 = (float)(l % 15 - 7);

    float v0[PDIM], v1[PDIM], v2[PDIM], t[PDIM];
    #pragma unroll
    for (int o = 0; o < PDIM; o++)
        v0[o] = c0 * pw[o] + c1 * pw[PDIM + o] + c2 * pw[2 * PDIM + o] + pb[o];

    ln_relu(v0, t, g1, b1);
    #pragma unroll
    for (int o = 0; o < PDIM; o++) {
        float s = wb1[o];
        #pragma unroll
        for (int i = 0; i < PDIM; i++) s = fmaf(t[i], w1[i * PDIM + o], s);
        v1[o] = s;
    }
    ln_relu(v1, t, g2, b2);
    #pragma unroll
    for (int o = 0; o < PDIM; o++) {
        float s = wb2[o];
        #pragma unroll
        for (int i = 0; i < PDIM; i++) s = fmaf(t[i], w2[i * PDIM + o], s);
        v2[o] = s;
    }
    ln_relu(v2, t, g3, b3);
    #pragma unroll
    for (int o = 0; o < NHEAD; o++) {
        float s = wb3[o];
        #pragma unroll
        for (int i = 0; i < PDIM; i++) s = fmaf(t[i], w3[i * NHEAD + o], s);
        g_pos[l * NHEAD + o] = s;
    }
}

// ---------------------------------------------------------------------------
// Kernel 2: expand bias table
// ---------------------------------------------------------------------------
__global__ void bias_fill_kernel() {
    int t = blockIdx.x * blockDim.x + threadIdx.x;
    int n = t >> 9, m = t & 511;
    int i1 = n >> 6, j1 = (n >> 3) & 7, k1 = n & 7;
    int i2 = m >> 6, j2 = (m >> 3) & 7, k2 = m & 7;
    int idx = ((i1 - i2 + 7) * 15 + (j1 - j2 + 7)) * 15 + (k1 - k2 + 7);
    #pragma unroll
    for (int h = 0; h < NHEAD; h++)
        g_bias[((size_t)h * NTOK + n) * NTOK + m] = g_pos[idx * NHEAD + h];
}

// ---------------------------------------------------------------------------
// Kernel 3/5: tf32 mma.sync GEMM.  C = A(32768xK) @ W(K x Ntot) + bias
// CTA tile 128x128, 8 warps (2m x 4n), warp tile 64x32, K chunks of 32.
// W is [K][N] row-major == col-major B operand directly (no transpose).
// mode 0: A=x, W=qkv_w (Ntot=1152) -> scatter g_Q/g_K/g_V
// mode 1: A=g_att, W=proj_w (Ntot=384) -> out row-major
// ---------------------------------------------------------------------------
__global__ __launch_bounds__(256, 2)
void mma_gemm(const float* __restrict__ Ain, const float* __restrict__ W,
              const float* __restrict__ bias, int Ntot, int mode,
              float* __restrict__ out)
{
    __shared__ float As[128][36];   // [m][k], pad 36 -> conflict-free frag loads
    __shared__ float Bs[32][128];   // [k][n], broadcast frag loads

    const float* A = (mode == 1) ? g_att : Ain;
    int tid = threadIdx.x;
    int wid = tid >> 5, lane = tid & 31;
    int g = lane >> 2, t = lane & 3;
    int wm = (wid & 1) * 64;      // warp m offset in CTA tile
    int wn = (wid >> 1) * 32;     // warp n offset

    int m0 = blockIdx.y * 128;
    int n0 = blockIdx.x * 128;

    float acc[4][4][4];
    #pragma unroll
    for (int mf = 0; mf < 4; mf++)
        #pragma unroll
        for (int nf = 0; nf < 4; nf++)
            #pragma unroll
            for (int e = 0; e < 4; e++) acc[mf][nf][e] = 0.f;

    for (int k0 = 0; k0 < CDIM; k0 += 32) {
        __syncthreads();
        // stage A: 128 rows x 32 cols = 1024 float4, 4 per thread
        #pragma unroll
        for (int i = 0; i < 4; i++) {
            int lin = tid + i * 256;
            int r = lin >> 3, q = lin & 7;
            float4 v = *(const float4*)(A + (size_t)(m0 + r) * CDIM + k0 + q * 4);
            *(float4*)&As[r][q * 4] = v;
        }
        // stage B: 32 rows x 128 cols = 1024 float4, 4 per thread
        #pragma unroll
        for (int i = 0; i < 4; i++) {
            int lin = tid + i * 256;
            int r = lin >> 5, q = lin & 31;
            float4 v = *(const float4*)(W + (size_t)(k0 + r) * Ntot + n0 + q * 4);
            *(float4*)&Bs[r][q * 4] = v;
        }
        __syncthreads();

        #pragma unroll
        for (int ks = 0; ks < 4; ks++) {
            int kb = ks * 8;
            uint32_t bf[4][2];
            #pragma unroll
            for (int nf = 0; nf < 4; nf++) {
                bf[nf][0] = f2tf32(Bs[kb + t][wn + nf * 8 + g]);
                bf[nf][1] = f2tf32(Bs[kb + t + 4][wn + nf * 8 + g]);
            }
            uint32_t af[4][4];
            #pragma unroll
            for (int mf = 0; mf < 4; mf++) {
                int r = wm + mf * 16 + g;
                af[mf][0] = f2tf32(As[r][kb + t]);
                af[mf][1] = f2tf32(As[r + 8][kb + t]);
                af[mf][2] = f2tf32(As[r][kb + t + 4]);
                af[mf][3] = f2tf32(As[r + 8][kb + t + 4]);
            }
            #pragma unroll
            for (int mf = 0; mf < 4; mf++)
                #pragma unroll
                for (int nf = 0; nf < 4; nf++)
                    mma_tf32(acc[mf][nf], af[mf], bf[nf]);
        }
    }

    // epilogue: c0: (g, 2t) c1: (g, 2t+1) c2: (g+8, 2t) c3: (g+8, 2t+1)
    #pragma unroll
    for (int mf = 0; mf < 4; mf++) {
        #pragma unroll
        for (int nf = 0; nf < 4; nf++) {
            int rbase = m0 + wm + mf * 16 + g;
            int cbase = n0 + wn + nf * 8 + 2 * t;
            #pragma unroll
            for (int e = 0; e < 4; e++) {
                int gm = rbase + (e >> 1) * 8;
                int gn = cbase + (e & 1);
                float val = acc[mf][nf][e] + __ldg(bias + gn);
                if (mode == 0) {
                    int which = gn / CDIM;
                    int r = gn - which * CDIM;
                    int h = r >> 5, dd = r & 31;
                    int b = gm >> 9, tok = gm & 511;
                    size_t off = (((size_t)b * NHEAD + h) * NTOK + tok) * HDIM + dd;
                    if (which == 0)      g_Q[off] = val * SCALE;
                    else if (which == 1) g_K[off] = val;
                    else                 g_V[off] = val;
                } else {
                    out[(size_t)gm * CDIM + gn] = val;
                }
            }
        }
    }
}

// ---------------------------------------------------------------------------
// Kernel 4: fused flash attention (unchanged from R2)
// ---------------------------------------------------------------------------
__global__ __launch_bounds__(256, 2)
void attn_kernel(const float* __restrict__ mask)
{
    __shared__ float Qt[32][128];
    __shared__ float Kt[32][64];
    __shared__ float Vs[64][36];
    __shared__ float Ps[128][67];

    int qb = blockIdx.x, h = blockIdx.y, b = blockIdx.z;
    int q0 = qb * 128;
    int tid = threadIdx.x;
    int ty = tid >> 3;
    int tx = tid & 7;

    const float* Qbase = g_Q + (((size_t)b * NHEAD + h) * NTOK + q0) * HDIM;
    const float* Kbase = g_K + ((size_t)b * NHEAD + h) * NTOK * HDIM;
    const float* Vbase = g_V + ((size_t)b * NHEAD + h) * NTOK * HDIM;
    const float* biasb = g_bias + ((size_t)h * NTOK + q0) * NTOK;
    const float* maskb = mask + ((size_t)(b & 7) * NTOK + q0) * NTOK;

    {
        int r = tid & 127;
        int kb = (tid >> 7) * 16;
        const float* qp = Qbase + (size_t)r * HDIM + kb;
        #pragma unroll
        for (int u = 0; u < 16; u += 4) {
            float4 v = *(const float4*)(qp + u);
            Qt[kb + u + 0][r] = v.x;
            Qt[kb + u + 1][r] = v.y;
            Qt[kb + u + 2][r] = v.z;
            Qt[kb + u + 3][r] = v.w;
        }
    }

    float m_r[4], l_r[4], o[4][4];
    #pragma unroll
    for (int i = 0; i < 4; i++) {
        m_r[i] = -1e30f; l_r[i] = 0.f;
        #pragma unroll
        for (int j = 0; j < 4; j++) o[i][j] = 0.f;
    }

    for (int kt = 0; kt < 8; kt++) {
        __syncthreads();
        {
            int j = tid & 63, kb = (tid >> 6) * 8;
            const float* kp = Kbase + (size_t)(kt * 64 + j) * HDIM + kb;
            float4 a = *(const float4*)kp;
            float4 c = *(const float4*)(kp + 4);
            Kt[kb + 0][j] = a.x; Kt[kb + 1][j] = a.y;
            Kt[kb + 2][j] = a.z; Kt[kb + 3][j] = a.w;
            Kt[kb + 4][j] = c.x; Kt[kb + 5][j] = c.y;
            Kt[kb + 6][j] = c.z; Kt[kb + 7][j] = c.w;
        }
        {
            int j = tid >> 2, cb = (tid & 3) * 8;
            const float* vp = Vbase + (size_t)(kt * 64 + j) * HDIM + cb;
            *(float4*)&Vs[j][cb]     = *(const float4*)vp;
            *(float4*)&Vs[j][cb + 4] = *(const float4*)(vp + 4);
        }
        __syncthreads();

        float s[4][8];
        #pragma unroll
        for (int i = 0; i < 4; i++)
            #pragma unroll
            for (int j = 0; j < 8; j++) s[i][j] = 0.f;

        #pragma unroll 4
        for (int kk = 0; kk < 32; kk++) {
            float a0[4], bv[8];
            *(float4*)&a0[0] = *(const float4*)&Qt[kk][ty * 4];
            *(float4*)&bv[0] = *(const float4*)&Kt[kk][tx * 8];
            *(float4*)&bv[4] = *(const float4*)&Kt[kk][tx * 8 + 4];
            #pragma unroll
            for (int i = 0; i < 4; i++)
                #pragma unroll
                for (int j = 0; j < 8; j++)
                    s[i][j] = fmaf(a0[i], bv[j], s[i][j]);
        }

        #pragma unroll
        for (int i = 0; i < 4; i++) {
            int row = ty * 4 + i;
            const float* bp = biasb + (size_t)row * NTOK + kt * 64 + tx * 8;
            const float* mp = maskb + (size_t)row * NTOK + kt * 64 + tx * 8;
            float4 b0 = *(const float4*)bp;
            float4 b1 = *(const float4*)(bp + 4);
            float4 mm0 = *(const float4*)mp;
            float4 mm1 = *(const float4*)(mp + 4);
            s[i][0] += b0.x + mm0.x;  s[i][1] += b0.y + mm0.y;
            s[i][2] += b0.z + mm0.z;  s[i][3] += b0.w + mm0.w;
            s[i][4] += b1.x + mm1.x;  s[i][5] += b1.y + mm1.y;
            s[i][6] += b1.z + mm1.z;  s[i][7] += b1.w + mm1.w;

            float lm = s[i][0];
            #pragma unroll
            for (int j = 1; j < 8; j++) lm = fmaxf(lm, s[i][j]);
            lm = fmaxf(lm, __shfl_xor_sync(0xffffffffu, lm, 1));
            lm = fmaxf(lm, __shfl_xor_sync(0xffffffffu, lm, 2));
            lm = fmaxf(lm, __shfl_xor_sync(0xffffffffu, lm, 4));

            float nm = fmaxf(m_r[i], lm);
            float cr = __expf(m_r[i] - nm);
            float ls = 0.f;
            #pragma unroll
            for (int j = 0; j < 8; j++) {
                float p = __expf(s[i][j] - nm);
                s[i][j] = p;
                ls += p;
            }
            ls += __shfl_xor_sync(0xffffffffu, ls, 1);
            ls += __shfl_xor_sync(0xffffffffu, ls, 2);
            ls += __shfl_xor_sync(0xffffffffu, ls, 4);

            l_r[i] = l_r[i] * cr + ls;
            m_r[i] = nm;
            #pragma unroll
            for (int j = 0; j < 4; j++) o[i][j] *= cr;

            #pragma unroll
            for (int j = 0; j < 8; j++) Ps[row][tx * 8 + j] = s[i][j];
        }
        __syncthreads();

        #pragma unroll 4
        for (int j = 0; j < 64; j++) {
            float4 vv = *(const float4*)&Vs[j][tx * 4];
            float p0 = Ps[ty * 4 + 0][j];
            float p1 = Ps[ty * 4 + 1][j];
            float p2 = Ps[ty * 4 + 2][j];
            float p3 = Ps[ty * 4 + 3][j];
            o[0][0] = fmaf(p0, vv.x, o[0][0]);
            o[0][1] = fmaf(p0, vv.y, o[0][1]);
            o[0][2] = fmaf(p0, vv.z, o[0][2]);
            o[0][3] = fmaf(p0, vv.w, o[0][3]);
            o[1][0] = fmaf(p1, vv.x, o[1][0]);
            o[1][1] = fmaf(p1, vv.y, o[1][1]);
            o[1][2] = fmaf(p1, vv.z, o[1][2]);
            o[1][3] = fmaf(p1, vv.w, o[1][3]);
            o[2][0] = fmaf(p2, vv.x, o[2][0]);
            o[2][1] = fmaf(p2, vv.y, o[2][1]);
            o[2][2] = fmaf(p2, vv.z, o[2][2]);
            o[2][3] = fmaf(p2, vv.w, o[2][3]);
            o[3][0] = fmaf(p3, vv.x, o[3][0]);
            o[3][1] = fmaf(p3, vv.y, o[3][1]);
            o[3][2] = fmaf(p3, vv.z, o[3][2]);
            o[3][3] = fmaf(p3, vv.w, o[3][3]);
        }
    }

    float* op = g_att + ((size_t)b * NTOK + q0) * CDIM + (size_t)h * HDIM;
    #pragma unroll
    for (int i = 0; i < 4; i++) {
        int row = ty * 4 + i;
        float inv = 1.f / l_r[i];
        float4 r4 = make_float4(o[i][0] * inv, o[i][1] * inv,
                                o[i][2] * inv, o[i][3] * inv);
        *(float4*)(op + (size_t)row * CDIM + tx * 4) = r4;
    }
}

// ---------------------------------------------------------------------------
// Host launch
// ---------------------------------------------------------------------------
extern "C" void kernel_launch(void* const* d_in, const int* in_sizes, int n_in,
                              void* d_out, int out_size)
{
    const float *x = nullptr, *mask = nullptr, *qkv_w = nullptr, *qkv_b = nullptr;
    const float *proj_w = nullptr, *proj_b = nullptr;
    const float *pos_proj_w = nullptr, *pos_proj_b = nullptr;
    const float *ln1_g = nullptr, *ln1_b = nullptr, *pos1_w = nullptr, *pos1_b = nullptr;
    const float *ln2_g = nullptr, *ln2_b = nullptr, *pos2_w = nullptr, *pos2_b = nullptr;
    const float *ln3_g = nullptr, *ln3_b = nullptr, *pos3_w = nullptr, *pos3_b = nullptr;

    int cnt24 = 0, cnt576 = 0;
    for (int i = 0; i < n_in; i++) {
        int sz = in_sizes[i];
        const float* p = (const float*)d_in[i];
        switch (sz) {
            case 12582912: x = p; break;
            case 2097152:  mask = p; break;
            case 442368:   qkv_w = p; break;
            case 1152:     qkv_b = p; break;
            case 147456:   proj_w = p; break;
            case 384:      proj_b = p; break;
            case 72:       pos_proj_w = p; break;
            case 288:      pos3_w = p; break;
            case 12:       pos3_b = p; break;
            case 576:
                if (cnt576 == 0) pos1_w = p; else pos2_w = p;
                cnt576++;
                break;
            case 24: {
                switch (cnt24) {
                    case 0: pos_proj_b = p; break;
                    case 1: ln1_g = p; break;
                    case 2: ln1_b = p; break;
                    case 3: pos1_b = p; break;
                    case 4: ln2_g = p; break;
                    case 5: ln2_b = p; break;
                    case 6: pos2_b = p; break;
                    case 7: ln3_g = p; break;
                    case 8: ln3_b = p; break;
                }
                cnt24++;
                break;
            }
            default: break;
        }
    }

    // 1. pos MLP table
    pos_mlp_kernel<<<(LPOS + 127) / 128, 128>>>(
        pos_proj_w, pos_proj_b,
        ln1_g, ln1_b, pos1_w, pos1_b,
        ln2_g, ln2_b, pos2_w, pos2_b,
        ln3_g, ln3_b, pos3_w, pos3_b);

    // 2. expand to per-head bias table
    bias_fill_kernel<<<(NTOK * NTOK) / 256, 256>>>();

    // 3. QKV GEMM (tf32 mma.sync) + scatter
    mma_gemm<<<dim3(3 * CDIM / 128, (BWIN * NTOK) / 128), 256>>>(
        x, qkv_w, qkv_b, 3 * CDIM, 0, nullptr);

    // 4. fused attention
    attn_kernel<<<dim3(NTOK / 128, NHEAD, BWIN), 256>>>(mask);

    // 5. output projection (tf32 mma.sync)
    mma_gemm<<<dim3(CDIM / 128, (BWIN * NTOK) / 128), 256>>>(
        nullptr, proj_w, proj_b, CDIM, 1, (float*)d_out);

    (void)out_size;
}

// round 5
// speedup vs baseline: 1.7544x; 1.7544x over previous
#include <cuda_runtime.h>
#include <math.h>
#include <stdint.h>

// ---------------------------------------------------------------------------
// Problem constants
// ---------------------------------------------------------------------------
#define BWIN   64
#define NTOK   512
#define CDIM   384
#define NHEAD  12
#define HDIM   32
#define LPOS   3375
#define PDIM   24
#define SCALE  0.17677669529663687f
#define NCH    12            // 384 / 32 k-chunks

// ---------------------------------------------------------------------------
// Scratch
// ---------------------------------------------------------------------------
__device__ float    g_pos[LPOS * NHEAD];
__device__ float    g_bias[NHEAD * NTOK * NTOK];
__device__ float    g_Q[BWIN * NHEAD * NTOK * HDIM];
__device__ float    g_K[BWIN * NHEAD * NTOK * HDIM];
__device__ float    g_V[BWIN * NHEAD * NTOK * HDIM];
__device__ float    g_att[BWIN * NTOK * CDIM];      // attn out, tf32-rounded
__device__ float    g_x32[BWIN * NTOK * CDIM];      // x pre-rounded to tf32
__device__ uint32_t g_wqkv[CDIM * 3 * CDIM];        // qkv_w permuted tf32
__device__ uint32_t g_wproj[CDIM * CDIM];           // proj_w permuted tf32

// ---------------------------------------------------------------------------
// helpers
// ---------------------------------------------------------------------------
__device__ __forceinline__ uint32_t f2tf32(float f) {
    uint32_t r;
    asm("cvt.rna.tf32.f32 %0, %1;" : "=r"(r) : "f"(f));
    return r;
}
__device__ __forceinline__ void mma_tf32(float c[4], const uint32_t a[4],
                                         const uint32_t b[2]) {
    asm volatile(
        "mma.sync.aligned.m16n8k8.row.col.f32.tf32.tf32.f32 "
        "{%0,%1,%2,%3}, {%4,%5,%6,%7}, {%8,%9}, {%0,%1,%2,%3};"
        : "+f"(c[0]), "+f"(c[1]), "+f"(c[2]), "+f"(c[3])
        : "r"(a[0]), "r"(a[1]), "r"(a[2]), "r"(a[3]),
          "r"(b[0]), "r"(b[1]));
}
__device__ __forceinline__ uint32_t smem_u32(const void* p) {
    uint32_t a;
    asm("{ .reg .u64 t; cvta.to.shared.u64 t, %1; cvt.u32.u64 %0, t; }"
        : "=r"(a) : "l"(p));
    return a;
}
__device__ __forceinline__ void cp16(uint32_t dst, const void* src) {
    asm volatile("cp.async.cg.shared.global [%0], [%1], 16;"
                 :: "r"(dst), "l"(src) : "memory");
}
__device__ __forceinline__ void cp_commit() {
    asm volatile("cp.async.commit_group;" ::: "memory");
}
__device__ __forceinline__ void cp_wait0() {
    asm volatile("cp.async.wait_group 0;" ::: "memory");
}
__device__ __forceinline__ void cp_wait1() {
    asm volatile("cp.async.wait_group 1;" ::: "memory");
}

// ---------------------------------------------------------------------------
// Pre-pass: round fp32 -> tf32 (store as fp32 bits with low mantissa zeroed)
// ---------------------------------------------------------------------------
__global__ void cvt_tf32_kernel(const float* __restrict__ in,
                                float* __restrict__ out, int n) {
    int i = (blockIdx.x * blockDim.x + threadIdx.x) * 4;
    if (i >= n) return;
    float4 v = *(const float4*)(in + i);
    float4 r;
    r.x = __uint_as_float(f2tf32(v.x));
    r.y = __uint_as_float(f2tf32(v.y));
    r.z = __uint_as_float(f2tf32(v.z));
    r.w = __uint_as_float(f2tf32(v.w));
    *(float4*)(out + i) = r;
}

// ---------------------------------------------------------------------------
// Pre-pass: permute weight [K][Ntot] into per-(ntile,kchunk) mma fragment order
// layout per 128n x 32k chunk: [wn(4)][ks(4)][nf(4)][lane(32)][2]
// ---------------------------------------------------------------------------
__global__ void permute_w_kernel(const float* __restrict__ W,
                                 uint32_t* __restrict__ out, int K, int Ntot) {
    int idx = blockIdx.x * blockDim.x + threadIdx.x;
    if (idx >= K * Ntot) return;
    int k = idx / Ntot, n = idx % Ntot;
    uint32_t val = f2tf32(W[(size_t)k * Ntot + n]);
    int kc = k >> 5, ks = (k >> 3) & 3, kt = k & 7;
    int t = kt & 3, hi = kt >> 2;
    int n0 = n >> 7, wn = (n >> 5) & 3, nf = (n >> 3) & 3, g = n & 7;
    int lane = g * 4 + t;
    size_t chunk = (size_t)n0 * NCH + kc;
    size_t off = chunk * 4096 + (((wn * 4 + ks) * 4 + nf) * 32 + lane) * 2 + hi;
    out[off] = val;
}

// ---------------------------------------------------------------------------
// Kernel 1: dynamic position-bias MLP
// ---------------------------------------------------------------------------
__device__ __forceinline__ void ln_relu(const float* in, float* t,
                                        const float* g, const float* bt) {
    float m = 0.f;
    #pragma unroll
    for (int i = 0; i < PDIM; i++) m += in[i];
    m *= (1.0f / PDIM);
    float v = 0.f;
    #pragma unroll
    for (int i = 0; i < PDIM; i++) { float d = in[i] - m; v += d * d; }
    v *= (1.0f / PDIM);
    float inv = rsqrtf(v + 1e-5f);
    #pragma unroll
    for (int i = 0; i < PDIM; i++) {
        float y = (in[i] - m) * inv * g[i] + bt[i];
        t[i] = fmaxf(y, 0.f);
    }
}

__global__ void pos_mlp_kernel(
    const float* __restrict__ pw,  const float* __restrict__ pb,
    const float* __restrict__ g1,  const float* __restrict__ b1,
    const float* __restrict__ w1,  const float* __restrict__ wb1,
    const float* __restrict__ g2,  const float* __restrict__ b2,
    const float* __restrict__ w2,  const float* __restrict__ wb2,
    const float* __restrict__ g3,  const float* __restrict__ b3,
    const float* __restrict__ w3,  const float* __restrict__ wb3)
{
    int l = blockIdx.x * blockDim.x + threadIdx.x;
    if (l >= LPOS) return;
    float c0 = (float)(l / 225 - 7);
    float c1 = (float)((l / 15) % 15 - 7);
    float c2 = (float)(l % 15 - 7);

    float v0[PDIM], v1[PDIM], v2[PDIM], t[PDIM];
    #pragma unroll
    for (int o = 0; o < PDIM; o++)
        v0[o] = c0 * pw[o] + c1 * pw[PDIM + o] + c2 * pw[2 * PDIM + o] + pb[o];

    ln_relu(v0, t, g1, b1);
    #pragma unroll
    for (int o = 0; o < PDIM; o++) {
        float s = wb1[o];
        #pragma unroll
        for (int i = 0; i < PDIM; i++) s = fmaf(t[i], w1[i * PDIM + o], s);
        v1[o] = s;
    }
    ln_relu(v1, t, g2, b2);
    #pragma unroll
    for (int o = 0; o < PDIM; o++) {
        float s = wb2[o];
        #pragma unroll
        for (int i = 0; i < PDIM; i++) s = fmaf(t[i], w2[i * PDIM + o], s);
        v2[o] = s;
    }
    ln_relu(v2, t, g3, b3);
    #pragma unroll
    for (int o = 0; o < NHEAD; o++) {
        float s = wb3[o];
        #pragma unroll
        for (int i = 0; i < PDIM; i++) s = fmaf(t[i], w3[i * NHEAD + o], s);
        g_pos[l * NHEAD + o] = s;
    }
}

// ---------------------------------------------------------------------------
// Kernel 2: expand bias table
// ---------------------------------------------------------------------------
__global__ void bias_fill_kernel() {
    int t = blockIdx.x * blockDim.x + threadIdx.x;
    int n = t >> 9, m = t & 511;
    int i1 = n >> 6, j1 = (n >> 3) & 7, k1 = n & 7;
    int i2 = m >> 6, j2 = (m >> 3) & 7, k2 = m & 7;
    int idx = ((i1 - i2 + 7) * 15 + (j1 - j2 + 7)) * 15 + (k1 - k2 + 7);
    #pragma unroll
    for (int h = 0; h < NHEAD; h++)
        g_bias[((size_t)h * NTOK + n) * NTOK + m] = g_pos[idx * NHEAD + h];
}

// ---------------------------------------------------------------------------
// Kernel 3/5: tf32 mma.sync GEMM, pipelined cp.async, fragment-order B.
// CTA tile 128x128, 8 warps (2m x 4n), warp tile 64x32.
// mode 0: A=g_x32, W=g_wqkv (Ntot=1152) -> scatter g_Q/g_K/g_V
// mode 1: A=g_att, W=g_wproj (Ntot=384) -> out row-major
// ---------------------------------------------------------------------------
#define AWORDS 4608   // 128 * 36
#define BWORDS 4096   // 128n * 32k

__global__ __launch_bounds__(256, 2)
void mma_gemm(const float* __restrict__ Aglob, const uint32_t* __restrict__ Wperm,
              const float* __restrict__ bias, int Ntot, int mode,
              float* __restrict__ out)
{
    extern __shared__ uint32_t sbuf[];
    uint32_t* Abuf = sbuf;                 // 2 * AWORDS
    uint32_t* Bbuf = sbuf + 2 * AWORDS;    // 2 * BWORDS

    const float* A = (mode == 1) ? g_att : Aglob;
    int tid = threadIdx.x;
    int wid = tid >> 5, lane = tid & 31;
    int g = lane >> 2, t = lane & 3;
    int wm = (wid & 1) * 64;
    int wn_idx = wid >> 1;

    int m0 = blockIdx.y * 128;
    int n0t = blockIdx.x;          // n tile index
    int n0 = n0t * 128;

    uint32_t aAddr = smem_u32(Abuf);
    uint32_t bAddr = smem_u32(Bbuf);
    const float* Arow = A + (size_t)m0 * CDIM;
    const uint32_t* Wbase = Wperm + (size_t)n0t * NCH * BWORDS;

    float acc[4][4][4];
    #pragma unroll
    for (int mf = 0; mf < 4; mf++)
        #pragma unroll
        for (int nf = 0; nf < 4; nf++)
            #pragma unroll
            for (int e = 0; e < 4; e++) acc[mf][nf][e] = 0.f;

    // ---- issue stage 0 ----
    {
        uint32_t ad = aAddr;                      // buf 0
        #pragma unroll
        for (int i = 0; i < 4; i++) {
            int c = tid + i * 256;                // 0..1023
            int r = c >> 3, q = c & 7;
            cp16(ad + (uint32_t)(r * 36 + q * 4) * 4, Arow + (size_t)r * CDIM + q * 4);
        }
        uint32_t bd = bAddr;
        const uint32_t* src = Wbase;              // chunk 0
        #pragma unroll
        for (int i = 0; i < 4; i++) {
            int c = tid + i * 256;
            cp16(bd + (uint32_t)c * 16, src + (size_t)c * 4);
        }
        cp_commit();
    }

    for (int kc = 0; kc < NCH; kc++) {
        int cur = kc & 1;
        if (kc + 1 < NCH) {
            int nxt = cur ^ 1;
            uint32_t ad = aAddr + (uint32_t)nxt * AWORDS * 4;
            const float* arow = Arow + (kc + 1) * 32;
            #pragma unroll
            for (int i = 0; i < 4; i++) {
                int c = tid + i * 256;
                int r = c >> 3, q = c & 7;
                cp16(ad + (uint32_t)(r * 36 + q * 4) * 4,
                     arow + (size_t)r * CDIM + q * 4);
            }
            uint32_t bd = bAddr + (uint32_t)nxt * BWORDS * 4;
            const uint32_t* src = Wbase + (size_t)(kc + 1) * BWORDS;
            #pragma unroll
            for (int i = 0; i < 4; i++) {
                int c = tid + i * 256;
                cp16(bd + (uint32_t)c * 16, src + (size_t)c * 4);
            }
            cp_commit();
            cp_wait1();
        } else {
            cp_wait0();
        }
        __syncthreads();

        const uint32_t* ab = Abuf + cur * AWORDS;
        const uint32_t* bb = Bbuf + cur * BWORDS + wn_idx * 1024;

        #pragma unroll
        for (int ks = 0; ks < 4; ks++) {
            uint32_t bf[4][2];
            const uint32_t* bks = bb + ks * 256 + lane * 2;
            #pragma unroll
            for (int nf = 0; nf < 4; nf++) {
                uint2 v = *(const uint2*)(bks + nf * 64);
                bf[nf][0] = v.x; bf[nf][1] = v.y;
            }
            uint32_t af[4][4];
            #pragma unroll
            for (int mf = 0; mf < 4; mf++) {
                int r = wm + mf * 16 + g;
                const uint32_t* a0 = ab + r * 36 + ks * 8 + t;
                af[mf][0] = a0[0];
                af[mf][1] = a0[8 * 36];
                af[mf][2] = a0[4];
                af[mf][3] = a0[8 * 36 + 4];
            }
            #pragma unroll
            for (int mf = 0; mf < 4; mf++)
                #pragma unroll
                for (int nf = 0; nf < 4; nf++)
                    mma_tf32(acc[mf][nf], af[mf], bf[nf]);
        }
        __syncthreads();
    }

    // epilogue
    #pragma unroll
    for (int mf = 0; mf < 4; mf++) {
        #pragma unroll
        for (int nf = 0; nf < 4; nf++) {
            int rbase = m0 + wm + mf * 16 + g;
            int cbase = n0 + wn_idx * 32 + nf * 8 + 2 * t;
            #pragma unroll
            for (int e = 0; e < 4; e++) {
                int gm = rbase + (e >> 1) * 8;
                int gn = cbase + (e & 1);
                float val = acc[mf][nf][e] + bias[gn];
                if (mode == 0) {
                    int which = gn / CDIM;
                    int r = gn - which * CDIM;
                    int h = r >> 5, dd = r & 31;
                    int b = gm >> 9, tok = gm & 511;
                    size_t off = (((size_t)b * NHEAD + h) * NTOK + tok) * HDIM + dd;
                    if (which == 0)      g_Q[off] = val * SCALE;
                    else if (which == 1) g_K[off] = val;
                    else                 g_V[off] = val;
                } else {
                    out[(size_t)gm * CDIM + gn] = val;
                }
            }
        }
    }
}

// ---------------------------------------------------------------------------
// Kernel 4: fused flash attention (R2 version; output tf32-rounded for proj)
// ---------------------------------------------------------------------------
__global__ __launch_bounds__(256, 2)
void attn_kernel(const float* __restrict__ mask)
{
    __shared__ float Qt[32][128];
    __shared__ float Kt[32][64];
    __shared__ float Vs[64][36];
    __shared__ float Ps[128][67];

    int qb = blockIdx.x, h = blockIdx.y, b = blockIdx.z;
    int q0 = qb * 128;
    int tid = threadIdx.x;
    int ty = tid >> 3;
    int tx = tid & 7;

    const float* Qbase = g_Q + (((size_t)b * NHEAD + h) * NTOK + q0) * HDIM;
    const float* Kbase = g_K + ((size_t)b * NHEAD + h) * NTOK * HDIM;
    const float* Vbase = g_V + ((size_t)b * NHEAD + h) * NTOK * HDIM;
    const float* biasb = g_bias + ((size_t)h * NTOK + q0) * NTOK;
    const float* maskb = mask + ((size_t)(b & 7) * NTOK + q0) * NTOK;

    {
        int r = tid & 127;
        int kb = (tid >> 7) * 16;
        const float* qp = Qbase + (size_t)r * HDIM + kb;
        #pragma unroll
        for (int u = 0; u < 16; u += 4) {
            float4 v = *(const float4*)(qp + u);
            Qt[kb + u + 0][r] = v.x;
            Qt[kb + u + 1][r] = v.y;
            Qt[kb + u + 2][r] = v.z;
            Qt[kb + u + 3][r] = v.w;
        }
    }

    float m_r[4], l_r[4], o[4][4];
    #pragma unroll
    for (int i = 0; i < 4; i++) {
        m_r[i] = -1e30f; l_r[i] = 0.f;
        #pragma unroll
        for (int j = 0; j < 4; j++) o[i][j] = 0.f;
    }

    for (int kt = 0; kt < 8; kt++) {
        __syncthreads();
        {
            int j = tid & 63, kb = (tid >> 6) * 8;
            const float* kp = Kbase + (size_t)(kt * 64 + j) * HDIM + kb;
            float4 a = *(const float4*)kp;
            float4 c = *(const float4*)(kp + 4);
            Kt[kb + 0][j] = a.x; Kt[kb + 1][j] = a.y;
            Kt[kb + 2][j] = a.z; Kt[kb + 3][j] = a.w;
            Kt[kb + 4][j] = c.x; Kt[kb + 5][j] = c.y;
            Kt[kb + 6][j] = c.z; Kt[kb + 7][j] = c.w;
        }
        {
            int j = tid >> 2, cb = (tid & 3) * 8;
            const float* vp = Vbase + (size_t)(kt * 64 + j) * HDIM + cb;
            *(float4*)&Vs[j][cb]     = *(const float4*)vp;
            *(float4*)&Vs[j][cb + 4] = *(const float4*)(vp + 4);
        }
        __syncthreads();

        float s[4][8];
        #pragma unroll
        for (int i = 0; i < 4; i++)
            #pragma unroll
            for (int j = 0; j < 8; j++) s[i][j] = 0.f;

        #pragma unroll 4
        for (int kk = 0; kk < 32; kk++) {
            float a0[4], bv[8];
            *(float4*)&a0[0] = *(const float4*)&Qt[kk][ty * 4];
            *(float4*)&bv[0] = *(const float4*)&Kt[kk][tx * 8];
            *(float4*)&bv[4] = *(const float4*)&Kt[kk][tx * 8 + 4];
            #pragma unroll
            for (int i = 0; i < 4; i++)
                #pragma unroll
                for (int j = 0; j < 8; j++)
                    s[i][j] = fmaf(a0[i], bv[j], s[i][j]);
        }

        #pragma unroll
        for (int i = 0; i < 4; i++) {
            int row = ty * 4 + i;
            const float* bp = biasb + (size_t)row * NTOK + kt * 64 + tx * 8;
            const float* mp = maskb + (size_t)row * NTOK + kt * 64 + tx * 8;
            float4 b0 = *(const float4*)bp;
            float4 b1 = *(const float4*)(bp + 4);
            float4 mm0 = *(const float4*)mp;
            float4 mm1 = *(const float4*)(mp + 4);
            s[i][0] += b0.x + mm0.x;  s[i][1] += b0.y + mm0.y;
            s[i][2] += b0.z + mm0.z;  s[i][3] += b0.w + mm0.w;
            s[i][4] += b1.x + mm1.x;  s[i][5] += b1.y + mm1.y;
            s[i][6] += b1.z + mm1.z;  s[i][7] += b1.w + mm1.w;

            float lm = s[i][0];
            #pragma unroll
            for (int j = 1; j < 8; j++) lm = fmaxf(lm, s[i][j]);
            lm = fmaxf(lm, __shfl_xor_sync(0xffffffffu, lm, 1));
            lm = fmaxf(lm, __shfl_xor_sync(0xffffffffu, lm, 2));
            lm = fmaxf(lm, __shfl_xor_sync(0xffffffffu, lm, 4));

            float nm = fmaxf(m_r[i], lm);
            float cr = __expf(m_r[i] - nm);
            float ls = 0.f;
            #pragma unroll
            for (int j = 0; j < 8; j++) {
                float p = __expf(s[i][j] - nm);
                s[i][j] = p;
                ls += p;
            }
            ls += __shfl_xor_sync(0xffffffffu, ls, 1);
            ls += __shfl_xor_sync(0xffffffffu, ls, 2);
            ls += __shfl_xor_sync(0xffffffffu, ls, 4);

            l_r[i] = l_r[i] * cr + ls;
            m_r[i] = nm;
            #pragma unroll
            for (int j = 0; j < 4; j++) o[i][j] *= cr;

            #pragma unroll
            for (int j = 0; j < 8; j++) Ps[row][tx * 8 + j] = s[i][j];
        }
        __syncthreads();

        #pragma unroll 4
        for (int j = 0; j < 64; j++) {
            float4 vv = *(const float4*)&Vs[j][tx * 4];
            float p0 = Ps[ty * 4 + 0][j];
            float p1 = Ps[ty * 4 + 1][j];
            float p2 = Ps[ty * 4 + 2][j];
            float p3 = Ps[ty * 4 + 3][j];
            o[0][0] = fmaf(p0, vv.x, o[0][0]);
            o[0][1] = fmaf(p0, vv.y, o[0][1]);
            o[0][2] = fmaf(p0, vv.z, o[0][2]);
            o[0][3] = fmaf(p0, vv.w, o[0][3]);
            o[1][0] = fmaf(p1, vv.x, o[1][0]);
            o[1][1] = fmaf(p1, vv.y, o[1][1]);
            o[1][2] = fmaf(p1, vv.z, o[1][2]);
            o[1][3] = fmaf(p1, vv.w, o[1][3]);
            o[2][0] = fmaf(p2, vv.x, o[2][0]);
            o[2][1] = fmaf(p2, vv.y, o[2][1]);
            o[2][2] = fmaf(p2, vv.z, o[2][2]);
            o[2][3] = fmaf(p2, vv.w, o[2][3]);
            o[3][0] = fmaf(p3, vv.x, o[3][0]);
            o[3][1] = fmaf(p3, vv.y, o[3][1]);
            o[3][2] = fmaf(p3, vv.z, o[3][2]);
            o[3][3] = fmaf(p3, vv.w, o[3][3]);
        }
    }

    float* op = g_att + ((size_t)b * NTOK + q0) * CDIM + (size_t)h * HDIM;
    #pragma unroll
    for (int i = 0; i < 4; i++) {
        int row = ty * 4 + i;
        float inv = 1.f / l_r[i];
        float4 r4;
        r4.x = __uint_as_float(f2tf32(o[i][0] * inv));
        r4.y = __uint_as_float(f2tf32(o[i][1] * inv));
        r4.z = __uint_as_float(f2tf32(o[i][2] * inv));
        r4.w = __uint_as_float(f2tf32(o[i][3] * inv));
        *(float4*)(op + (size_t)row * CDIM + tx * 4) = r4;
    }
}

// ---------------------------------------------------------------------------
// Host launch
// ---------------------------------------------------------------------------
extern "C" void kernel_launch(void* const* d_in, const int* in_sizes, int n_in,
                              void* d_out, int out_size)
{
    const float *x = nullptr, *mask = nullptr, *qkv_w = nullptr, *qkv_b = nullptr;
    const float *proj_w = nullptr, *proj_b = nullptr;
    const float *pos_proj_w = nullptr, *pos_proj_b = nullptr;
    const float *ln1_g = nullptr, *ln1_b = nullptr, *pos1_w = nullptr, *pos1_b = nullptr;
    const float *ln2_g = nullptr, *ln2_b = nullptr, *pos2_w = nullptr, *pos2_b = nullptr;
    const float *ln3_g = nullptr, *ln3_b = nullptr, *pos3_w = nullptr, *pos3_b = nullptr;

    int cnt24 = 0, cnt576 = 0;
    for (int i = 0; i < n_in; i++) {
        int sz = in_sizes[i];
        const float* p = (const float*)d_in[i];
        switch (sz) {
            case 12582912: x = p; break;
            case 2097152:  mask = p; break;
            case 442368:   qkv_w = p; break;
            case 1152:     qkv_b = p; break;
            case 147456:   proj_w = p; break;
            case 384:      proj_b = p; break;
            case 72:       pos_proj_w = p; break;
            case 288:      pos3_w = p; break;
            case 12:       pos3_b = p; break;
            case 576:
                if (cnt576 == 0) pos1_w = p; else pos2_w = p;
                cnt576++;
                break;
            case 24: {
                switch (cnt24) {
                    case 0: pos_proj_b = p; break;
                    case 1: ln1_g = p; break;
                    case 2: ln1_b = p; break;
                    case 3: pos1_b = p; break;
                    case 4: ln2_g = p; break;
                    case 5: ln2_b = p; break;
                    case 6: pos2_b = p; break;
                    case 7: ln3_g = p; break;
                    case 8: ln3_b = p; break;
                }
                cnt24++;
                break;
            }
            default: break;
        }
    }

    float* x32;      cudaGetSymbolAddress((void**)&x32, g_x32);
    uint32_t* wqkv;  cudaGetSymbolAddress((void**)&wqkv, g_wqkv);
    uint32_t* wproj; cudaGetSymbolAddress((void**)&wproj, g_wproj);

    const int SMEM_GEMM = (2 * AWORDS + 2 * BWORDS) * 4;   // 69632 B
    cudaFuncSetAttribute(mma_gemm, cudaFuncAttributeMaxDynamicSharedMemorySize,
                         SMEM_GEMM);

    // 1. pos MLP table
    pos_mlp_kernel<<<(LPOS + 127) / 128, 128>>>(
        pos_proj_w, pos_proj_b,
        ln1_g, ln1_b, pos1_w, pos1_b,
        ln2_g, ln2_b, pos2_w, pos2_b,
        ln3_g, ln3_b, pos3_w, pos3_b);

    // 2. expand to per-head bias table
    bias_fill_kernel<<<(NTOK * NTOK) / 256, 256>>>();

    // 2b. pre-convert / pre-permute operands
    cvt_tf32_kernel<<<(BWIN * NTOK * CDIM / 4 + 255) / 256, 256>>>(
        x, x32, BWIN * NTOK * CDIM);
    permute_w_kernel<<<(CDIM * 3 * CDIM + 255) / 256, 256>>>(
        qkv_w, wqkv, CDIM, 3 * CDIM);
    permute_w_kernel<<<(CDIM * CDIM + 255) / 256, 256>>>(
        proj_w, wproj, CDIM, CDIM);

    // 3. QKV GEMM (tf32 mma.sync, pipelined) + scatter
    mma_gemm<<<dim3(3 * CDIM / 128, (BWIN * NTOK) / 128), 256, SMEM_GEMM>>>(
        x32, wqkv, qkv_b, 3 * CDIM, 0, nullptr);

    // 4. fused attention
    attn_kernel<<<dim3(NTOK / 128, NHEAD, BWIN), 256>>>(mask);

    // 5. output projection (tf32 mma.sync, pipelined)
    mma_gemm<<<dim3(CDIM / 128, (BWIN * NTOK) / 128), 256, SMEM_GEMM>>>(
        nullptr, wproj, proj_b, CDIM, 1, (float*)d_out);

    (void)out_size;
}

// round 6
// speedup vs baseline: 2.8887x; 1.6465x over previous
#include <cuda_runtime.h>
#include <math.h>
#include <stdint.h>

// ---------------------------------------------------------------------------
// Problem constants
// ---------------------------------------------------------------------------
#define BWIN   64
#define NTOK   512
#define CDIM   384
#define NHEAD  12
#define HDIM   32
#define LPOS   3375
#define PDIM   24
#define SCALE  0.17677669529663687f
#define NCH    12            // 384 / 32 k-chunks

// ---------------------------------------------------------------------------
// Scratch
// ---------------------------------------------------------------------------
__device__ float    g_pos[LPOS * NHEAD];
__device__ float    g_bias[NHEAD * NTOK * NTOK];
__device__ float    g_Q[BWIN * NHEAD * NTOK * HDIM];   // tf32-rounded, *scale
__device__ float    g_K[BWIN * NHEAD * NTOK * HDIM];   // tf32-rounded
__device__ float    g_V[BWIN * NHEAD * NTOK * HDIM];   // tf32-rounded
__device__ float    g_att[BWIN * NTOK * CDIM];         // attn out, tf32-rounded
__device__ float    g_x32[BWIN * NTOK * CDIM];         // x pre-rounded to tf32
__device__ uint32_t g_wqkv[CDIM * 3 * CDIM];           // qkv_w permuted tf32
__device__ uint32_t g_wproj[CDIM * CDIM];              // proj_w permuted tf32

// ---------------------------------------------------------------------------
// helpers
// ---------------------------------------------------------------------------
__device__ __forceinline__ uint32_t f2tf32(float f) {
    uint32_t r;
    asm("cvt.rna.tf32.f32 %0, %1;" : "=r"(r) : "f"(f));
    return r;
}
__device__ __forceinline__ void mma_tf32(float c[4], const uint32_t a[4],
                                         const uint32_t b[2]) {
    asm volatile(
        "mma.sync.aligned.m16n8k8.row.col.f32.tf32.tf32.f32 "
        "{%0,%1,%2,%3}, {%4,%5,%6,%7}, {%8,%9}, {%0,%1,%2,%3};"
        : "+f"(c[0]), "+f"(c[1]), "+f"(c[2]), "+f"(c[3])
        : "r"(a[0]), "r"(a[1]), "r"(a[2]), "r"(a[3]),
          "r"(b[0]), "r"(b[1]));
}
__device__ __forceinline__ uint32_t smem_u32(const void* p) {
    uint32_t a;
    asm("{ .reg .u64 t; cvta.to.shared.u64 t, %1; cvt.u32.u64 %0, t; }"
        : "=r"(a) : "l"(p));
    return a;
}
__device__ __forceinline__ void cp16(uint32_t dst, const void* src) {
    asm volatile("cp.async.cg.shared.global [%0], [%1], 16;"
                 :: "r"(dst), "l"(src) : "memory");
}
__device__ __forceinline__ void cp_commit() {
    asm volatile("cp.async.commit_group;" ::: "memory");
}
__device__ __forceinline__ void cp_wait0() {
    asm volatile("cp.async.wait_group 0;" ::: "memory");
}
__device__ __forceinline__ void cp_wait1() {
    asm volatile("cp.async.wait_group 1;" ::: "memory");
}

// ---------------------------------------------------------------------------
// Pre-pass: round fp32 -> tf32 bits
// ---------------------------------------------------------------------------
__global__ void cvt_tf32_kernel(const float* __restrict__ in,
                                float* __restrict__ out, int n) {
    int i = (blockIdx.x * blockDim.x + threadIdx.x) * 4;
    if (i >= n) return;
    float4 v = *(const float4*)(in + i);
    float4 r;
    r.x = __uint_as_float(f2tf32(v.x));
    r.y = __uint_as_float(f2tf32(v.y));
    r.z = __uint_as_float(f2tf32(v.z));
    r.w = __uint_as_float(f2tf32(v.w));
    *(float4*)(out + i) = r;
}

// ---------------------------------------------------------------------------
// Pre-pass: permute weight [K][Ntot] into mma fragment order
// ---------------------------------------------------------------------------
__global__ void permute_w_kernel(const float* __restrict__ W,
                                 uint32_t* __restrict__ out, int K, int Ntot) {
    int idx = blockIdx.x * blockDim.x + threadIdx.x;
    if (idx >= K * Ntot) return;
    int k = idx / Ntot, n = idx % Ntot;
    uint32_t val = f2tf32(W[(size_t)k * Ntot + n]);
    int kc = k >> 5, ks = (k >> 3) & 3, kt = k & 7;
    int t = kt & 3, hi = kt >> 2;
    int n0 = n >> 7, wn = (n >> 5) & 3, nf = (n >> 3) & 3, g = n & 7;
    int lane = g * 4 + t;
    size_t chunk = (size_t)n0 * NCH + kc;
    size_t off = chunk * 4096 + (((wn * 4 + ks) * 4 + nf) * 32 + lane) * 2 + hi;
    out[off] = val;
}

// ---------------------------------------------------------------------------
// Kernel 1: dynamic position-bias MLP
// ---------------------------------------------------------------------------
__device__ __forceinline__ void ln_relu(const float* in, float* t,
                                        const float* g, const float* bt) {
    float m = 0.f;
    #pragma unroll
    for (int i = 0; i < PDIM; i++) m += in[i];
    m *= (1.0f / PDIM);
    float v = 0.f;
    #pragma unroll
    for (int i = 0; i < PDIM; i++) { float d = in[i] - m; v += d * d; }
    v *= (1.0f / PDIM);
    float inv = rsqrtf(v + 1e-5f);
    #pragma unroll
    for (int i = 0; i < PDIM; i++) {
        float y = (in[i] - m) * inv * g[i] + bt[i];
        t[i] = fmaxf(y, 0.f);
    }
}

__global__ void pos_mlp_kernel(
    const float* __restrict__ pw,  const float* __restrict__ pb,
    const float* __restrict__ g1,  const float* __restrict__ b1,
    const float* __restrict__ w1,  const float* __restrict__ wb1,
    const float* __restrict__ g2,  const float* __restrict__ b2,
    const float* __restrict__ w2,  const float* __restrict__ wb2,
    const float* __restrict__ g3,  const float* __restrict__ b3,
    const float* __restrict__ w3,  const float* __restrict__ wb3)
{
    int l = blockIdx.x * blockDim.x + threadIdx.x;
    if (l >= LPOS) return;
    float c0 = (float)(l / 225 - 7);
    float c1 = (float)((l / 15) % 15 - 7);
    float c2 = (float)(l % 15 - 7);

    float v0[PDIM], v1[PDIM], v2[PDIM], t[PDIM];
    #pragma unroll
    for (int o = 0; o < PDIM; o++)
        v0[o] = c0 * pw[o] + c1 * pw[PDIM + o] + c2 * pw[2 * PDIM + o] + pb[o];

    ln_relu(v0, t, g1, b1);
    #pragma unroll
    for (int o = 0; o < PDIM; o++) {
        float s = wb1[o];
        #pragma unroll
        for (int i = 0; i < PDIM; i++) s = fmaf(t[i], w1[i * PDIM + o], s);
        v1[o] = s;
    }
    ln_relu(v1, t, g2, b2);
    #pragma unroll
    for (int o = 0; o < PDIM; o++) {
        float s = wb2[o];
        #pragma unroll
        for (int i = 0; i < PDIM; i++) s = fmaf(t[i], w2[i * PDIM + o], s);
        v2[o] = s;
    }
    ln_relu(v2, t, g3, b3);
    #pragma unroll
    for (int o = 0; o < NHEAD; o++) {
        float s = wb3[o];
        #pragma unroll
        for (int i = 0; i < PDIM; i++) s = fmaf(t[i], w3[i * NHEAD + o], s);
        g_pos[l * NHEAD + o] = s;
    }
}

// ---------------------------------------------------------------------------
// Kernel 2: expand bias table
// ---------------------------------------------------------------------------
__global__ void bias_fill_kernel() {
    int t = blockIdx.x * blockDim.x + threadIdx.x;
    int n = t >> 9, m = t & 511;
    int i1 = n >> 6, j1 = (n >> 3) & 7, k1 = n & 7;
    int i2 = m >> 6, j2 = (m >> 3) & 7, k2 = m & 7;
    int idx = ((i1 - i2 + 7) * 15 + (j1 - j2 + 7)) * 15 + (k1 - k2 + 7);
    #pragma unroll
    for (int h = 0; h < NHEAD; h++)
        g_bias[((size_t)h * NTOK + n) * NTOK + m] = g_pos[idx * NHEAD + h];
}

// ---------------------------------------------------------------------------
// Kernel 3/5: tf32 mma.sync GEMM (R5 design, QKV epilogue rounds to tf32)
// ---------------------------------------------------------------------------
#define AWORDS 4608   // 128 * 36
#define BWORDS 4096   // 128n * 32k

__global__ __launch_bounds__(256, 2)
void mma_gemm(const float* __restrict__ Aglob, const uint32_t* __restrict__ Wperm,
              const float* __restrict__ bias, int Ntot, int mode,
              float* __restrict__ out)
{
    extern __shared__ uint32_t sbuf[];
    uint32_t* Abuf = sbuf;
    uint32_t* Bbuf = sbuf + 2 * AWORDS;

    const float* A = (mode == 1) ? g_att : Aglob;
    int tid = threadIdx.x;
    int wid = tid >> 5, lane = tid & 31;
    int g = lane >> 2, t = lane & 3;
    int wm = (wid & 1) * 64;
    int wn_idx = wid >> 1;

    int m0 = blockIdx.y * 128;
    int n0t = blockIdx.x;
    int n0 = n0t * 128;

    uint32_t aAddr = smem_u32(Abuf);
    uint32_t bAddr = smem_u32(Bbuf);
    const float* Arow = A + (size_t)m0 * CDIM;
    const uint32_t* Wbase = Wperm + (size_t)n0t * NCH * BWORDS;

    float acc[4][4][4];
    #pragma unroll
    for (int mf = 0; mf < 4; mf++)
        #pragma unroll
        for (int nf = 0; nf < 4; nf++)
            #pragma unroll
            for (int e = 0; e < 4; e++) acc[mf][nf][e] = 0.f;

    {
        uint32_t ad = aAddr;
        #pragma unroll
        for (int i = 0; i < 4; i++) {
            int c = tid + i * 256;
            int r = c >> 3, q = c & 7;
            cp16(ad + (uint32_t)(r * 36 + q * 4) * 4, Arow + (size_t)r * CDIM + q * 4);
        }
        uint32_t bd = bAddr;
        const uint32_t* src = Wbase;
        #pragma unroll
        for (int i = 0; i < 4; i++) {
            int c = tid + i * 256;
            cp16(bd + (uint32_t)c * 16, src + (size_t)c * 4);
        }
        cp_commit();
    }

    for (int kc = 0; kc < NCH; kc++) {
        int cur = kc & 1;
        if (kc + 1 < NCH) {
            int nxt = cur ^ 1;
            uint32_t ad = aAddr + (uint32_t)nxt * AWORDS * 4;
            const float* arow = Arow + (kc + 1) * 32;
            #pragma unroll
            for (int i = 0; i < 4; i++) {
                int c = tid + i * 256;
                int r = c >> 3, q = c & 7;
                cp16(ad + (uint32_t)(r * 36 + q * 4) * 4,
                     arow + (size_t)r * CDIM + q * 4);
            }
            uint32_t bd = bAddr + (uint32_t)nxt * BWORDS * 4;
            const uint32_t* src = Wbase + (size_t)(kc + 1) * BWORDS;
            #pragma unroll
            for (int i = 0; i < 4; i++) {
                int c = tid + i * 256;
                cp16(bd + (uint32_t)c * 16, src + (size_t)c * 4);
            }
            cp_commit();
            cp_wait1();
        } else {
            cp_wait0();
        }
        __syncthreads();

        const uint32_t* ab = Abuf + cur * AWORDS;
        const uint32_t* bb = Bbuf + cur * BWORDS + wn_idx * 1024;

        #pragma unroll
        for (int ks = 0; ks < 4; ks++) {
            uint32_t bf[4][2];
            const uint32_t* bks = bb + ks * 256 + lane * 2;
            #pragma unroll
            for (int nf = 0; nf < 4; nf++) {
                uint2 v = *(const uint2*)(bks + nf * 64);
                bf[nf][0] = v.x; bf[nf][1] = v.y;
            }
            uint32_t af[4][4];
            #pragma unroll
            for (int mf = 0; mf < 4; mf++) {
                int r = wm + mf * 16 + g;
                const uint32_t* a0 = ab + r * 36 + ks * 8 + t;
                af[mf][0] = a0[0];
                af[mf][1] = a0[8 * 36];
                af[mf][2] = a0[4];
                af[mf][3] = a0[8 * 36 + 4];
            }
            #pragma unroll
            for (int mf = 0; mf < 4; mf++)
                #pragma unroll
                for (int nf = 0; nf < 4; nf++)
                    mma_tf32(acc[mf][nf], af[mf], bf[nf]);
        }
        __syncthreads();
    }

    #pragma unroll
    for (int mf = 0; mf < 4; mf++) {
        #pragma unroll
        for (int nf = 0; nf < 4; nf++) {
            int rbase = m0 + wm + mf * 16 + g;
            int cbase = n0 + wn_idx * 32 + nf * 8 + 2 * t;
            #pragma unroll
            for (int e = 0; e < 4; e++) {
                int gm = rbase + (e >> 1) * 8;
                int gn = cbase + (e & 1);
                float val = acc[mf][nf][e] + bias[gn];
                if (mode == 0) {
                    int which = gn / CDIM;
                    int r = gn - which * CDIM;
                    int h = r >> 5, dd = r & 31;
                    int b = gm >> 9, tok = gm & 511;
                    size_t off = (((size_t)b * NHEAD + h) * NTOK + tok) * HDIM + dd;
                    if (which == 0)
                        g_Q[off] = __uint_as_float(f2tf32(val * SCALE));
                    else if (which == 1)
                        g_K[off] = __uint_as_float(f2tf32(val));
                    else
                        g_V[off] = __uint_as_float(f2tf32(val));
                } else {
                    out[(size_t)gm * CDIM + gn] = val;
                }
            }
        }
    }
}

// ---------------------------------------------------------------------------
// Kernel 4: fused flash attention on tensor cores (tf32 mma.sync).
// CTA: 128 queries x (b,h). 8 warps, warp owns 16 query rows end-to-end.
// Per 64-key tile: S = Q@K^T (mma), bias+mask+online softmax in regs,
// P -> SMEM (warp-private rows), O += P@V^T (mma, V staged transposed).
// SMEM floats: Qs[128][36] @0, Ks 2x[64][36] @4608, Vt[32][68] @9216,
//              Ps[128][68] @11392. Total 20096 floats = 80384 B.
// ---------------------------------------------------------------------------
#define ATT_SMEM_FLOATS 20096

__global__ __launch_bounds__(256, 2)
void attn_kernel(const float* __restrict__ mask)
{
    extern __shared__ float sm[];
    float* Qs = sm;                 // [128][36]
    float* Ks = sm + 4608;          // 2 x [64][36]
    float* Vt = sm + 9216;          // [32][68]
    float* Ps = sm + 11392;         // [128][68]

    int tid = threadIdx.x;
    int wid = tid >> 5, lane = tid & 31;
    int g = lane >> 2, t = lane & 3;
    int q0 = blockIdx.x * 128, h = blockIdx.y, b = blockIdx.z;

    const float* Qb = g_Q + (((size_t)b * NHEAD + h) * NTOK + q0) * HDIM;
    const float* Kb = g_K + ((size_t)b * NHEAD + h) * NTOK * HDIM;
    const float* Vb = g_V + ((size_t)b * NHEAD + h) * NTOK * HDIM;
    const float* biasb = g_bias + (size_t)h * NTOK * NTOK;
    const float* maskb = mask + (size_t)(b & 7) * NTOK * NTOK;

    uint32_t qAddr = smem_u32(Qs);
    uint32_t kAddr = smem_u32(Ks);

    // prime: cp.async Q (128x32) + K tile 0 into buf 0
    #pragma unroll
    for (int i = 0; i < 4; i++) {
        int c = tid + i * 256;
        int r = c >> 3, q = c & 7;
        cp16(qAddr + (uint32_t)(r * 36 + q * 4) * 4, Qb + (size_t)r * HDIM + q * 4);
    }
    #pragma unroll
    for (int i = 0; i < 2; i++) {
        int c = tid + i * 256;
        int r = c >> 3, q = c & 7;
        cp16(kAddr + (uint32_t)(r * 36 + q * 4) * 4, Kb + (size_t)r * HDIM + q * 4);
    }
    cp_commit();

    // preload V tile 0 to regs
    float4 vr0, vr1;
    {
        int c0 = tid, c1 = tid + 256;
        vr0 = *(const float4*)(Vb + (size_t)(c0 >> 3) * HDIM + (c0 & 7) * 4);
        vr1 = *(const float4*)(Vb + (size_t)(c1 >> 3) * HDIM + (c1 & 7) * 4);
    }

    int row_l = wid * 16 + g;               // local row (in 0..127)
    float m0r = -1e30f, m1r = -1e30f, l0r = 0.f, l1r = 0.f;
    float o[4][4];
    #pragma unroll
    for (int nf = 0; nf < 4; nf++)
        #pragma unroll
        for (int e = 0; e < 4; e++) o[nf][e] = 0.f;

    for (int kt = 0; kt < 8; kt++) {
        int cur = kt & 1;
        cp_wait0();
        // transpose-store V tile (loaded last iter) into Vt[d][key]
        {
            int c0 = tid, c1 = tid + 256;
            int key0 = c0 >> 3, seg0 = (c0 & 7) * 4;
            int key1 = c1 >> 3, seg1 = (c1 & 7) * 4;
            Vt[(seg0 + 0) * 68 + key0] = vr0.x;
            Vt[(seg0 + 1) * 68 + key0] = vr0.y;
            Vt[(seg0 + 2) * 68 + key0] = vr0.z;
            Vt[(seg0 + 3) * 68 + key0] = vr0.w;
            Vt[(seg1 + 0) * 68 + key1] = vr1.x;
            Vt[(seg1 + 1) * 68 + key1] = vr1.y;
            Vt[(seg1 + 2) * 68 + key1] = vr1.z;
            Vt[(seg1 + 3) * 68 + key1] = vr1.w;
        }
        __syncthreads();

        if (kt < 7) {
            // prefetch next K tile into other buffer; next V into regs
            int nxt = cur ^ 1;
            const float* ksrc = Kb + (size_t)(kt + 1) * 64 * HDIM;
            #pragma unroll
            for (int i = 0; i < 2; i++) {
                int c = tid + i * 256;
                int r = c >> 3, q = c & 7;
                cp16(kAddr + (uint32_t)(nxt * 2304 + r * 36 + q * 4) * 4,
                     ksrc + (size_t)r * HDIM + q * 4);
            }
            cp_commit();
            const float* vsrc = Vb + (size_t)(kt + 1) * 64 * HDIM;
            int c0 = tid, c1 = tid + 256;
            vr0 = *(const float4*)(vsrc + (size_t)(c0 >> 3) * HDIM + (c0 & 7) * 4);
            vr1 = *(const float4*)(vsrc + (size_t)(c1 >> 3) * HDIM + (c1 & 7) * 4);
        }

        // ---- S = Q @ K^T : warp computes [16 q][64 key] ----
        float s[8][4];
        #pragma unroll
        for (int nf = 0; nf < 8; nf++)
            #pragma unroll
            for (int e = 0; e < 4; e++) s[nf][e] = 0.f;

        const float* kc = Ks + cur * 2304;
        #pragma unroll
        for (int ks = 0; ks < 4; ks++) {
            uint32_t af[4];
            const float* a0 = Qs + row_l * 36 + ks * 8 + t;
            af[0] = __float_as_uint(a0[0]);
            af[1] = __float_as_uint(a0[8 * 36]);
            af[2] = __float_as_uint(a0[4]);
            af[3] = __float_as_uint(a0[8 * 36 + 4]);
            #pragma unroll
            for (int nf = 0; nf < 8; nf++) {
                const float* bp = kc + (nf * 8 + g) * 36 + ks * 8 + t;
                uint32_t bf[2] = { __float_as_uint(bp[0]), __float_as_uint(bp[4]) };
                mma_tf32(s[nf], af, bf);
            }
        }

        // ---- bias + mask + online softmax ----
        int row0 = q0 + row_l, row1 = row0 + 8;
        int key0 = kt * 64;
        float lm0 = -1e30f, lm1 = -1e30f;
        #pragma unroll
        for (int nf = 0; nf < 8; nf++) {
            int col = key0 + nf * 8 + 2 * t;
            float2 b0 = *(const float2*)(biasb + (size_t)row0 * NTOK + col);
            float2 b1 = *(const float2*)(biasb + (size_t)row1 * NTOK + col);
            float2 k0 = *(const float2*)(maskb + (size_t)row0 * NTOK + col);
            float2 k1 = *(const float2*)(maskb + (size_t)row1 * NTOK + col);
            s[nf][0] += b0.x + k0.x;  s[nf][1] += b0.y + k0.y;
            s[nf][2] += b1.x + k1.x;  s[nf][3] += b1.y + k1.y;
            lm0 = fmaxf(lm0, fmaxf(s[nf][0], s[nf][1]));
            lm1 = fmaxf(lm1, fmaxf(s[nf][2], s[nf][3]));
        }
        lm0 = fmaxf(lm0, __shfl_xor_sync(0xffffffffu, lm0, 1));
        lm0 = fmaxf(lm0, __shfl_xor_sync(0xffffffffu, lm0, 2));
        lm1 = fmaxf(lm1, __shfl_xor_sync(0xffffffffu, lm1, 1));
        lm1 = fmaxf(lm1, __shfl_xor_sync(0xffffffffu, lm1, 2));

        float nm0 = fmaxf(m0r, lm0), nm1 = fmaxf(m1r, lm1);
        float cr0 = __expf(m0r - nm0), cr1 = __expf(m1r - nm1);
        m0r = nm0; m1r = nm1;

        float ls0 = 0.f, ls1 = 0.f;
        #pragma unroll
        for (int nf = 0; nf < 8; nf++) {
            float p0 = __expf(s[nf][0] - nm0);
            float p1 = __expf(s[nf][1] - nm0);
            float p2 = __expf(s[nf][2] - nm1);
            float p3 = __expf(s[nf][3] - nm1);
            ls0 += p0 + p1; ls1 += p2 + p3;
            float2 w0, w1;
            w0.x = __uint_as_float(f2tf32(p0));
            w0.y = __uint_as_float(f2tf32(p1));
            w1.x = __uint_as_float(f2tf32(p2));
            w1.y = __uint_as_float(f2tf32(p3));
            *(float2*)(Ps + row_l * 68 + nf * 8 + 2 * t) = w0;
            *(float2*)(Ps + (row_l + 8) * 68 + nf * 8 + 2 * t) = w1;
        }
        ls0 += __shfl_xor_sync(0xffffffffu, ls0, 1);
        ls0 += __shfl_xor_sync(0xffffffffu, ls0, 2);
        ls1 += __shfl_xor_sync(0xffffffffu, ls1, 1);
        ls1 += __shfl_xor_sync(0xffffffffu, ls1, 2);
        l0r = l0r * cr0 + ls0;
        l1r = l1r * cr1 + ls1;

        #pragma unroll
        for (int nf = 0; nf < 4; nf++) {
            o[nf][0] *= cr0; o[nf][1] *= cr0;
            o[nf][2] *= cr1; o[nf][3] *= cr1;
        }
        __syncwarp();   // Ps rows are warp-private

        // ---- O += P @ V : warp computes [16 q][32 d] ----
        #pragma unroll
        for (int ks = 0; ks < 8; ks++) {
            uint32_t af[4];
            const float* pa = Ps + row_l * 68 + ks * 8 + t;
            af[0] = __float_as_uint(pa[0]);
            af[1] = __float_as_uint(pa[8 * 68]);
            af[2] = __float_as_uint(pa[4]);
            af[3] = __float_as_uint(pa[8 * 68 + 4]);
            #pragma unroll
            for (int nf = 0; nf < 4; nf++) {
                const float* vp = Vt + (nf * 8 + g) * 68 + ks * 8 + t;
                uint32_t bf[2] = { __float_as_uint(vp[0]), __float_as_uint(vp[4]) };
                mma_tf32(o[nf], af, bf);
            }
        }
        __syncthreads();   // all PV reads done before next tile overwrites Vt/Ks
    }

    // epilogue
    float inv0 = 1.f / l0r, inv1 = 1.f / l1r;
    int tok0 = q0 + row_l, tok1 = tok0 + 8;
    float* ob0 = g_att + ((size_t)b * NTOK + tok0) * CDIM + h * HDIM;
    float* ob1 = g_att + ((size_t)b * NTOK + tok1) * CDIM + h * HDIM;
    #pragma unroll
    for (int nf = 0; nf < 4; nf++) {
        float2 w0, w1;
        w0.x = __uint_as_float(f2tf32(o[nf][0] * inv0));
        w0.y = __uint_as_float(f2tf32(o[nf][1] * inv0));
        w1.x = __uint_as_float(f2tf32(o[nf][2] * inv1));
        w1.y = __uint_as_float(f2tf32(o[nf][3] * inv1));
        *(float2*)(ob0 + nf * 8 + 2 * t) = w0;
        *(float2*)(ob1 + nf * 8 + 2 * t) = w1;
    }
}

// ---------------------------------------------------------------------------
// Host launch
// ---------------------------------------------------------------------------
extern "C" void kernel_launch(void* const* d_in, const int* in_sizes, int n_in,
                              void* d_out, int out_size)
{
    const float *x = nullptr, *mask = nullptr, *qkv_w = nullptr, *qkv_b = nullptr;
    const float *proj_w = nullptr, *proj_b = nullptr;
    const float *pos_proj_w = nullptr, *pos_proj_b = nullptr;
    const float *ln1_g = nullptr, *ln1_b = nullptr, *pos1_w = nullptr, *pos1_b = nullptr;
    const float *ln2_g = nullptr, *ln2_b = nullptr, *pos2_w = nullptr, *pos2_b = nullptr;
    const float *ln3_g = nullptr, *ln3_b = nullptr, *pos3_w = nullptr, *pos3_b = nullptr;

    int cnt24 = 0, cnt576 = 0;
    for (int i = 0; i < n_in; i++) {
        int sz = in_sizes[i];
        const float* p = (const float*)d_in[i];
        switch (sz) {
            case 12582912: x = p; break;
            case 2097152:  mask = p; break;
            case 442368:   qkv_w = p; break;
            case 1152:     qkv_b = p; break;
            case 147456:   proj_w = p; break;
            case 384:      proj_b = p; break;
            case 72:       pos_proj_w = p; break;
            case 288:      pos3_w = p; break;
            case 12:       pos3_b = p; break;
            case 576:
                if (cnt576 == 0) pos1_w = p; else pos2_w = p;
                cnt576++;
                break;
            case 24: {
                switch (cnt24) {
                    case 0: pos_proj_b = p; break;
                    case 1: ln1_g = p; break;
                    case 2: ln1_b = p; break;
                    case 3: pos1_b = p; break;
                    case 4: ln2_g = p; break;
                    case 5: ln2_b = p; break;
                    case 6: pos2_b = p; break;
                    case 7: ln3_g = p; break;
                    case 8: ln3_b = p; break;
                }
                cnt24++;
                break;
            }
            default: break;
        }
    }

    float* x32;      cudaGetSymbolAddress((void**)&x32, g_x32);
    uint32_t* wqkv;  cudaGetSymbolAddress((void**)&wqkv, g_wqkv);
    uint32_t* wproj; cudaGetSymbolAddress((void**)&wproj, g_wproj);

    const int SMEM_GEMM = (2 * AWORDS + 2 * BWORDS) * 4;
    const int SMEM_ATT = ATT_SMEM_FLOATS * 4;
    cudaFuncSetAttribute(mma_gemm, cudaFuncAttributeMaxDynamicSharedMemorySize,
                         SMEM_GEMM);
    cudaFuncSetAttribute(attn_kernel, cudaFuncAttributeMaxDynamicSharedMemorySize,
                         SMEM_ATT);

    // 1. pos MLP table
    pos_mlp_kernel<<<(LPOS + 127) / 128, 128>>>(
        pos_proj_w, pos_proj_b,
        ln1_g, ln1_b, pos1_w, pos1_b,
        ln2_g, ln2_b, pos2_w, pos2_b,
        ln3_g, ln3_b, pos3_w, pos3_b);

    // 2. expand to per-head bias table
    bias_fill_kernel<<<(NTOK * NTOK) / 256, 256>>>();

    // 2b. pre-convert / pre-permute operands
    cvt_tf32_kernel<<<(BWIN * NTOK * CDIM / 4 + 255) / 256, 256>>>(
        x, x32, BWIN * NTOK * CDIM);
    permute_w_kernel<<<(CDIM * 3 * CDIM + 255) / 256, 256>>>(
        qkv_w, wqkv, CDIM, 3 * CDIM);
    permute_w_kernel<<<(CDIM * CDIM + 255) / 256, 256>>>(
        proj_w, wproj, CDIM, CDIM);

    // 3. QKV GEMM + scatter (rounds Q/K/V to tf32)
    mma_gemm<<<dim3(3 * CDIM / 128, (BWIN * NTOK) / 128), 256, SMEM_GEMM>>>(
        x32, wqkv, qkv_b, 3 * CDIM, 0, nullptr);

    // 4. fused attention (tensor cores)
    attn_kernel<<<dim3(NTOK / 128, NHEAD, BWIN), 256, SMEM_ATT>>>(mask);

    // 5. output projection
    mma_gemm<<<dim3(CDIM / 128, (BWIN * NTOK) / 128), 256, SMEM_GEMM>>>(
        nullptr, wproj, proj_b, CDIM, 1, (float*)d_out);

    (void)out_size;
}

// round 7
// speedup vs baseline: 3.0497x; 1.0557x over previous
#include <cuda_runtime.h>
#include <math.h>
#include <stdint.h>

// ---------------------------------------------------------------------------
// Problem constants
// ---------------------------------------------------------------------------
#define BWIN   64
#define NTOK   512
#define CDIM   384
#define NHEAD  12
#define HDIM   32
#define LPOS   3375
#define PDIM   24
#define NGRP   8
#define SCALE  0.17677669529663687f
#define NCH    12            // 384 / 32 k-chunks

// ---------------------------------------------------------------------------
// Scratch
// ---------------------------------------------------------------------------
__device__ float    g_pos[LPOS * NHEAD];
__device__ float    g_bm[(size_t)NGRP * NHEAD * NTOK * NTOK];  // bias+mask fused
__device__ float    g_Q[BWIN * NHEAD * NTOK * HDIM];   // tf32-rounded, *scale
__device__ float    g_K[BWIN * NHEAD * NTOK * HDIM];   // tf32-rounded
__device__ float    g_V[BWIN * NHEAD * NTOK * HDIM];   // tf32-rounded
__device__ float    g_att[BWIN * NTOK * CDIM];         // attn out, tf32-rounded
__device__ float    g_x32[BWIN * NTOK * CDIM];         // x pre-rounded to tf32
__device__ uint32_t g_wqkv[CDIM * 3 * CDIM];           // qkv_w permuted tf32
__device__ uint32_t g_wproj[CDIM * CDIM];              // proj_w permuted tf32

// ---------------------------------------------------------------------------
// helpers
// ---------------------------------------------------------------------------
__device__ __forceinline__ uint32_t f2tf32(float f) {
    uint32_t r;
    asm("cvt.rna.tf32.f32 %0, %1;" : "=r"(r) : "f"(f));
    return r;
}
__device__ __forceinline__ void mma_tf32(float c[4], const uint32_t a[4],
                                         const uint32_t b[2]) {
    asm volatile(
        "mma.sync.aligned.m16n8k8.row.col.f32.tf32.tf32.f32 "
        "{%0,%1,%2,%3}, {%4,%5,%6,%7}, {%8,%9}, {%0,%1,%2,%3};"
        : "+f"(c[0]), "+f"(c[1]), "+f"(c[2]), "+f"(c[3])
        : "r"(a[0]), "r"(a[1]), "r"(a[2]), "r"(a[3]),
          "r"(b[0]), "r"(b[1]));
}
__device__ __forceinline__ uint32_t smem_u32(const void* p) {
    uint32_t a;
    asm("{ .reg .u64 t; cvta.to.shared.u64 t, %1; cvt.u32.u64 %0, t; }"
        : "=r"(a) : "l"(p));
    return a;
}
__device__ __forceinline__ void cp16(uint32_t dst, const void* src) {
    asm volatile("cp.async.cg.shared.global [%0], [%1], 16;"
                 :: "r"(dst), "l"(src) : "memory");
}
__device__ __forceinline__ void cp_commit() {
    asm volatile("cp.async.commit_group;" ::: "memory");
}
__device__ __forceinline__ void cp_wait0() {
    asm volatile("cp.async.wait_group 0;" ::: "memory");
}
__device__ __forceinline__ void cp_wait1() {
    asm volatile("cp.async.wait_group 1;" ::: "memory");
}

// ---------------------------------------------------------------------------
// Pre-pass: round fp32 -> tf32 bits
// ---------------------------------------------------------------------------
__global__ void cvt_tf32_kernel(const float* __restrict__ in,
                                float* __restrict__ out, int n) {
    int i = (blockIdx.x * blockDim.x + threadIdx.x) * 4;
    if (i >= n) return;
    float4 v = *(const float4*)(in + i);
    float4 r;
    r.x = __uint_as_float(f2tf32(v.x));
    r.y = __uint_as_float(f2tf32(v.y));
    r.z = __uint_as_float(f2tf32(v.z));
    r.w = __uint_as_float(f2tf32(v.w));
    *(float4*)(out + i) = r;
}

// ---------------------------------------------------------------------------
// Pre-pass: permute weight [K][Ntot] into mma fragment order
// ---------------------------------------------------------------------------
__global__ void permute_w_kernel(const float* __restrict__ W,
                                 uint32_t* __restrict__ out, int K, int Ntot) {
    int idx = blockIdx.x * blockDim.x + threadIdx.x;
    if (idx >= K * Ntot) return;
    int k = idx / Ntot, n = idx % Ntot;
    uint32_t val = f2tf32(W[(size_t)k * Ntot + n]);
    int kc = k >> 5, ks = (k >> 3) & 3, kt = k & 7;
    int t = kt & 3, hi = kt >> 2;
    int n0 = n >> 7, wn = (n >> 5) & 3, nf = (n >> 3) & 3, g = n & 7;
    int lane = g * 4 + t;
    size_t chunk = (size_t)n0 * NCH + kc;
    size_t off = chunk * 4096 + (((wn * 4 + ks) * 4 + nf) * 32 + lane) * 2 + hi;
    out[off] = val;
}

// ---------------------------------------------------------------------------
// Kernel 1: dynamic position-bias MLP
// ---------------------------------------------------------------------------
__device__ __forceinline__ void ln_relu(const float* in, float* t,
                                        const float* g, const float* bt) {
    float m = 0.f;
    #pragma unroll
    for (int i = 0; i < PDIM; i++) m += in[i];
    m *= (1.0f / PDIM);
    float v = 0.f;
    #pragma unroll
    for (int i = 0; i < PDIM; i++) { float d = in[i] - m; v += d * d; }
    v *= (1.0f / PDIM);
    float inv = rsqrtf(v + 1e-5f);
    #pragma unroll
    for (int i = 0; i < PDIM; i++) {
        float y = (in[i] - m) * inv * g[i] + bt[i];
        t[i] = fmaxf(y, 0.f);
    }
}

__global__ void pos_mlp_kernel(
    const float* __restrict__ pw,  const float* __restrict__ pb,
    const float* __restrict__ g1,  const float* __restrict__ b1,
    const float* __restrict__ w1,  const float* __restrict__ wb1,
    const float* __restrict__ g2,  const float* __restrict__ b2,
    const float* __restrict__ w2,  const float* __restrict__ wb2,
    const float* __restrict__ g3,  const float* __restrict__ b3,
    const float* __restrict__ w3,  const float* __restrict__ wb3)
{
    int l = blockIdx.x * blockDim.x + threadIdx.x;
    if (l >= LPOS) return;
    float c0 = (float)(l / 225 - 7);
    float c1 = (float)((l / 15) % 15 - 7);
    float c2 = (float)(l % 15 - 7);

    float v0[PDIM], v1[PDIM], v2[PDIM], t[PDIM];
    #pragma unroll
    for (int o = 0; o < PDIM; o++)
        v0[o] = c0 * pw[o] + c1 * pw[PDIM + o] + c2 * pw[2 * PDIM + o] + pb[o];

    ln_relu(v0, t, g1, b1);
    #pragma unroll
    for (int o = 0; o < PDIM; o++) {
        float s = wb1[o];
        #pragma unroll
        for (int i = 0; i < PDIM; i++) s = fmaf(t[i], w1[i * PDIM + o], s);
        v1[o] = s;
    }
    ln_relu(v1, t, g2, b2);
    #pragma unroll
    for (int o = 0; o < PDIM; o++) {
        float s = wb2[o];
        #pragma unroll
        for (int i = 0; i < PDIM; i++) s = fmaf(t[i], w2[i * PDIM + o], s);
        v2[o] = s;
    }
    ln_relu(v2, t, g3, b3);
    #pragma unroll
    for (int o = 0; o < NHEAD; o++) {
        float s = wb3[o];
        #pragma unroll
        for (int i = 0; i < PDIM; i++) s = fmaf(t[i], w3[i * NHEAD + o], s);
        g_pos[l * NHEAD + o] = s;
    }
}

// ---------------------------------------------------------------------------
// Kernel 2: fused bias+mask table  bm[grp][h][n][m] = pos[rpi(n,m)][h] + mask
// ---------------------------------------------------------------------------
__global__ void bm_fill_kernel(const float* __restrict__ mask) {
    int t = blockIdx.x * blockDim.x + threadIdx.x;   // 512*512 threads
    int n = t >> 9, m = t & 511;
    int i1 = n >> 6, j1 = (n >> 3) & 7, k1 = n & 7;
    int i2 = m >> 6, j2 = (m >> 3) & 7, k2 = m & 7;
    int idx = ((i1 - i2 + 7) * 15 + (j1 - j2 + 7)) * 15 + (k1 - k2 + 7);
    float pv[NHEAD];
    #pragma unroll
    for (int h = 0; h < NHEAD; h++) pv[h] = g_pos[idx * NHEAD + h];
    #pragma unroll
    for (int grp = 0; grp < NGRP; grp++) {
        float mv = mask[((size_t)grp * NTOK + n) * NTOK + m];
        #pragma unroll
        for (int h = 0; h < NHEAD; h++)
            g_bm[(((size_t)grp * NHEAD + h) * NTOK + n) * NTOK + m] = pv[h] + mv;
    }
}

// ---------------------------------------------------------------------------
// Kernel 3/5: tf32 mma.sync GEMM (R5 design, QKV epilogue rounds to tf32)
// ---------------------------------------------------------------------------
#define AWORDS 4608   // 128 * 36
#define BWORDS 4096   // 128n * 32k

__global__ __launch_bounds__(256, 2)
void mma_gemm(const float* __restrict__ Aglob, const uint32_t* __restrict__ Wperm,
              const float* __restrict__ bias, int Ntot, int mode,
              float* __restrict__ out)
{
    extern __shared__ uint32_t sbuf[];
    uint32_t* Abuf = sbuf;
    uint32_t* Bbuf = sbuf + 2 * AWORDS;

    const float* A = (mode == 1) ? g_att : Aglob;
    int tid = threadIdx.x;
    int wid = tid >> 5, lane = tid & 31;
    int g = lane >> 2, t = lane & 3;
    int wm = (wid & 1) * 64;
    int wn_idx = wid >> 1;

    int m0 = blockIdx.y * 128;
    int n0t = blockIdx.x;
    int n0 = n0t * 128;

    uint32_t aAddr = smem_u32(Abuf);
    uint32_t bAddr = smem_u32(Bbuf);
    const float* Arow = A + (size_t)m0 * CDIM;
    const uint32_t* Wbase = Wperm + (size_t)n0t * NCH * BWORDS;

    float acc[4][4][4];
    #pragma unroll
    for (int mf = 0; mf < 4; mf++)
        #pragma unroll
        for (int nf = 0; nf < 4; nf++)
            #pragma unroll
            for (int e = 0; e < 4; e++) acc[mf][nf][e] = 0.f;

    {
        uint32_t ad = aAddr;
        #pragma unroll
        for (int i = 0; i < 4; i++) {
            int c = tid + i * 256;
            int r = c >> 3, q = c & 7;
            cp16(ad + (uint32_t)(r * 36 + q * 4) * 4, Arow + (size_t)r * CDIM + q * 4);
        }
        uint32_t bd = bAddr;
        const uint32_t* src = Wbase;
        #pragma unroll
        for (int i = 0; i < 4; i++) {
            int c = tid + i * 256;
            cp16(bd + (uint32_t)c * 16, src + (size_t)c * 4);
        }
        cp_commit();
    }

    for (int kc = 0; kc < NCH; kc++) {
        int cur = kc & 1;
        if (kc + 1 < NCH) {
            int nxt = cur ^ 1;
            uint32_t ad = aAddr + (uint32_t)nxt * AWORDS * 4;
            const float* arow = Arow + (kc + 1) * 32;
            #pragma unroll
            for (int i = 0; i < 4; i++) {
                int c = tid + i * 256;
                int r = c >> 3, q = c & 7;
                cp16(ad + (uint32_t)(r * 36 + q * 4) * 4,
                     arow + (size_t)r * CDIM + q * 4);
            }
            uint32_t bd = bAddr + (uint32_t)nxt * BWORDS * 4;
            const uint32_t* src = Wbase + (size_t)(kc + 1) * BWORDS;
            #pragma unroll
            for (int i = 0; i < 4; i++) {
                int c = tid + i * 256;
                cp16(bd + (uint32_t)c * 16, src + (size_t)c * 4);
            }
            cp_commit();
            cp_wait1();
        } else {
            cp_wait0();
        }
        __syncthreads();

        const uint32_t* ab = Abuf + cur * AWORDS;
        const uint32_t* bb = Bbuf + cur * BWORDS + wn_idx * 1024;

        #pragma unroll
        for (int ks = 0; ks < 4; ks++) {
            uint32_t bf[4][2];
            const uint32_t* bks = bb + ks * 256 + lane * 2;
            #pragma unroll
            for (int nf = 0; nf < 4; nf++) {
                uint2 v = *(const uint2*)(bks + nf * 64);
                bf[nf][0] = v.x; bf[nf][1] = v.y;
            }
            uint32_t af[4][4];
            #pragma unroll
            for (int mf = 0; mf < 4; mf++) {
                int r = wm + mf * 16 + g;
                const uint32_t* a0 = ab + r * 36 + ks * 8 + t;
                af[mf][0] = a0[0];
                af[mf][1] = a0[8 * 36];
                af[mf][2] = a0[4];
                af[mf][3] = a0[8 * 36 + 4];
            }
            #pragma unroll
            for (int mf = 0; mf < 4; mf++)
                #pragma unroll
                for (int nf = 0; nf < 4; nf++)
                    mma_tf32(acc[mf][nf], af[mf], bf[nf]);
        }
        __syncthreads();
    }

    #pragma unroll
    for (int mf = 0; mf < 4; mf++) {
        #pragma unroll
        for (int nf = 0; nf < 4; nf++) {
            int rbase = m0 + wm + mf * 16 + g;
            int cbase = n0 + wn_idx * 32 + nf * 8 + 2 * t;
            #pragma unroll
            for (int e = 0; e < 4; e++) {
                int gm = rbase + (e >> 1) * 8;
                int gn = cbase + (e & 1);
                float val = acc[mf][nf][e] + bias[gn];
                if (mode == 0) {
                    int which = gn / CDIM;
                    int r = gn - which * CDIM;
                    int h = r >> 5, dd = r & 31;
                    int b = gm >> 9, tok = gm & 511;
                    size_t off = (((size_t)b * NHEAD + h) * NTOK + tok) * HDIM + dd;
                    if (which == 0)
                        g_Q[off] = __uint_as_float(f2tf32(val * SCALE));
                    else if (which == 1)
                        g_K[off] = __uint_as_float(f2tf32(val));
                    else
                        g_V[off] = __uint_as_float(f2tf32(val));
                } else {
                    out[(size_t)gm * CDIM + gn] = val;
                }
            }
        }
    }
}

// ---------------------------------------------------------------------------
// Kernel 4: fused flash attention on tensor cores (tf32 mma.sync).
// R6 design + : Q fragments hoisted to registers (loaded once), and the
// bias+mask additive term comes from the fused g_bm table (half the LDGs).
// SMEM floats: Qs[128][36] @0, Ks 2x[64][36] @4608, Vt[32][68] @9216,
//              Ps[128][68] @11392. Total 20096 floats = 80384 B.
// ---------------------------------------------------------------------------
#define ATT_SMEM_FLOATS 20096

__global__ __launch_bounds__(256, 2)
void attn_kernel()
{
    extern __shared__ float sm[];
    float* Qs = sm;                 // [128][36]
    float* Ks = sm + 4608;          // 2 x [64][36]
    float* Vt = sm + 9216;          // [32][68]
    float* Ps = sm + 11392;         // [128][68]

    int tid = threadIdx.x;
    int wid = tid >> 5, lane = tid & 31;
    int g = lane >> 2, t = lane & 3;
    int q0 = blockIdx.x * 128, h = blockIdx.y, b = blockIdx.z;

    const float* Qb = g_Q + (((size_t)b * NHEAD + h) * NTOK + q0) * HDIM;
    const float* Kb = g_K + ((size_t)b * NHEAD + h) * NTOK * HDIM;
    const float* Vb = g_V + ((size_t)b * NHEAD + h) * NTOK * HDIM;
    const float* bmb = g_bm + ((size_t)((b & 7) * NHEAD + h)) * NTOK * NTOK;

    uint32_t qAddr = smem_u32(Qs);
    uint32_t kAddr = smem_u32(Ks);

    // prime: cp.async Q (128x32) + K tile 0 into buf 0
    #pragma unroll
    for (int i = 0; i < 4; i++) {
        int c = tid + i * 256;
        int r = c >> 3, q = c & 7;
        cp16(qAddr + (uint32_t)(r * 36 + q * 4) * 4, Qb + (size_t)r * HDIM + q * 4);
    }
    #pragma unroll
    for (int i = 0; i < 2; i++) {
        int c = tid + i * 256;
        int r = c >> 3, q = c & 7;
        cp16(kAddr + (uint32_t)(r * 36 + q * 4) * 4, Kb + (size_t)r * HDIM + q * 4);
    }
    cp_commit();

    // preload V tile 0 to regs
    float4 vr0, vr1;
    {
        int c0 = tid, c1 = tid + 256;
        vr0 = *(const float4*)(Vb + (size_t)(c0 >> 3) * HDIM + (c0 & 7) * 4);
        vr1 = *(const float4*)(Vb + (size_t)(c1 >> 3) * HDIM + (c1 & 7) * 4);
    }

    int row_l = wid * 16 + g;               // local row (in 0..127)

    // wait for Q+K0, then hoist Q fragments into registers (loop-invariant)
    cp_wait0();
    __syncthreads();
    uint32_t qf[4][4];
    #pragma unroll
    for (int ks = 0; ks < 4; ks++) {
        const float* a0 = Qs + row_l * 36 + ks * 8 + t;
        qf[ks][0] = __float_as_uint(a0[0]);
        qf[ks][1] = __float_as_uint(a0[8 * 36]);
        qf[ks][2] = __float_as_uint(a0[4]);
        qf[ks][3] = __float_as_uint(a0[8 * 36 + 4]);
    }

    float m0r = -1e30f, m1r = -1e30f, l0r = 0.f, l1r = 0.f;
    float o[4][4];
    #pragma unroll
    for (int nf = 0; nf < 4; nf++)
        #pragma unroll
        for (int e = 0; e < 4; e++) o[nf][e] = 0.f;

    for (int kt = 0; kt < 8; kt++) {
        int cur = kt & 1;
        cp_wait0();                 // K[cur] prefetch (no-op at kt=0)
        // transpose-store V tile (loaded last iter) into Vt[d][key]
        {
            int c0 = tid, c1 = tid + 256;
            int key0 = c0 >> 3, seg0 = (c0 & 7) * 4;
            int key1 = c1 >> 3, seg1 = (c1 & 7) * 4;
            Vt[(seg0 + 0) * 68 + key0] = vr0.x;
            Vt[(seg0 + 1) * 68 + key0] = vr0.y;
            Vt[(seg0 + 2) * 68 + key0] = vr0.z;
            Vt[(seg0 + 3) * 68 + key0] = vr0.w;
            Vt[(seg1 + 0) * 68 + key1] = vr1.x;
            Vt[(seg1 + 1) * 68 + key1] = vr1.y;
            Vt[(seg1 + 2) * 68 + key1] = vr1.z;
            Vt[(seg1 + 3) * 68 + key1] = vr1.w;
        }
        __syncthreads();

        if (kt < 7) {
            // prefetch next K tile into other buffer; next V into regs
            int nxt = cur ^ 1;
            const float* ksrc = Kb + (size_t)(kt + 1) * 64 * HDIM;
            #pragma unroll
            for (int i = 0; i < 2; i++) {
                int c = tid + i * 256;
                int r = c >> 3, q = c & 7;
                cp16(kAddr + (uint32_t)(nxt * 2304 + r * 36 + q * 4) * 4,
                     ksrc + (size_t)r * HDIM + q * 4);
            }
            cp_commit();
            const float* vsrc = Vb + (size_t)(kt + 1) * 64 * HDIM;
            int c0 = tid, c1 = tid + 256;
            vr0 = *(const float4*)(vsrc + (size_t)(c0 >> 3) * HDIM + (c0 & 7) * 4);
            vr1 = *(const float4*)(vsrc + (size_t)(c1 >> 3) * HDIM + (c1 & 7) * 4);
        }

        // ---- S = Q @ K^T : warp computes [16 q][64 key] ----
        float s[8][4];
        #pragma unroll
        for (int nf = 0; nf < 8; nf++)
            #pragma unroll
            for (int e = 0; e < 4; e++) s[nf][e] = 0.f;

        const float* kc = Ks + cur * 2304;
        #pragma unroll
        for (int ks = 0; ks < 4; ks++) {
            #pragma unroll
            for (int nf = 0; nf < 8; nf++) {
                const float* bp = kc + (nf * 8 + g) * 36 + ks * 8 + t;
                uint32_t bf[2] = { __float_as_uint(bp[0]), __float_as_uint(bp[4]) };
                mma_tf32(s[nf], qf[ks], bf);
            }
        }

        // ---- fused bias+mask + online softmax ----
        int row0 = q0 + row_l, row1 = row0 + 8;
        int key0 = kt * 64;
        float lm0 = -1e30f, lm1 = -1e30f;
        #pragma unroll
        for (int nf = 0; nf < 8; nf++) {
            int col = key0 + nf * 8 + 2 * t;
            float2 b0 = *(const float2*)(bmb + (size_t)row0 * NTOK + col);
            float2 b1 = *(const float2*)(bmb + (size_t)row1 * NTOK + col);
            s[nf][0] += b0.x;  s[nf][1] += b0.y;
            s[nf][2] += b1.x;  s[nf][3] += b1.y;
            lm0 = fmaxf(lm0, fmaxf(s[nf][0], s[nf][1]));
            lm1 = fmaxf(lm1, fmaxf(s[nf][2], s[nf][3]));
        }
        lm0 = fmaxf(lm0, __shfl_xor_sync(0xffffffffu, lm0, 1));
        lm0 = fmaxf(lm0, __shfl_xor_sync(0xffffffffu, lm0, 2));
        lm1 = fmaxf(lm1, __shfl_xor_sync(0xffffffffu, lm1, 1));
        lm1 = fmaxf(lm1, __shfl_xor_sync(0xffffffffu, lm1, 2));

        float nm0 = fmaxf(m0r, lm0), nm1 = fmaxf(m1r, lm1);
        float cr0 = __expf(m0r - nm0), cr1 = __expf(m1r - nm1);
        m0r = nm0; m1r = nm1;

        float ls0 = 0.f, ls1 = 0.f;
        #pragma unroll
        for (int nf = 0; nf < 8; nf++) {
            float p0 = __expf(s[nf][0] - nm0);
            float p1 = __expf(s[nf][1] - nm0);
            float p2 = __expf(s[nf][2] - nm1);
            float p3 = __expf(s[nf][3] - nm1);
            ls0 += p0 + p1; ls1 += p2 + p3;
            float2 w0, w1;
            w0.x = __uint_as_float(f2tf32(p0));
            w0.y = __uint_as_float(f2tf32(p1));
            w1.x = __uint_as_float(f2tf32(p2));
            w1.y = __uint_as_float(f2tf32(p3));
            *(float2*)(Ps + row_l * 68 + nf * 8 + 2 * t) = w0;
            *(float2*)(Ps + (row_l + 8) * 68 + nf * 8 + 2 * t) = w1;
        }
        ls0 += __shfl_xor_sync(0xffffffffu, ls0, 1);
        ls0 += __shfl_xor_sync(0xffffffffu, ls0, 2);
        ls1 += __shfl_xor_sync(0xffffffffu, ls1, 1);
        ls1 += __shfl_xor_sync(0xffffffffu, ls1, 2);
        l0r = l0r * cr0 + ls0;
        l1r = l1r * cr1 + ls1;

        #pragma unroll
        for (int nf = 0; nf < 4; nf++) {
            o[nf][0] *= cr0; o[nf][1] *= cr0;
            o[nf][2] *= cr1; o[nf][3] *= cr1;
        }
        __syncwarp();   // Ps rows are warp-private

        // ---- O += P @ V : warp computes [16 q][32 d] ----
        #pragma unroll
        for (int ks = 0; ks < 8; ks++) {
            uint32_t af[4];
            const float* pa = Ps + row_l * 68 + ks * 8 + t;
            af[0] = __float_as_uint(pa[0]);
            af[1] = __float_as_uint(pa[8 * 68]);
            af[2] = __float_as_uint(pa[4]);
            af[3] = __float_as_uint(pa[8 * 68 + 4]);
            #pragma unroll
            for (int nf = 0; nf < 4; nf++) {
                const float* vp = Vt + (nf * 8 + g) * 68 + ks * 8 + t;
                uint32_t bf[2] = { __float_as_uint(vp[0]), __float_as_uint(vp[4]) };
                mma_tf32(o[nf], af, bf);
            }
        }
        __syncthreads();   // all PV reads done before next tile overwrites Vt/Ks
    }

    // epilogue
    float inv0 = 1.f / l0r, inv1 = 1.f / l1r;
    int tok0 = q0 + row_l, tok1 = tok0 + 8;
    float* ob0 = g_att + ((size_t)b * NTOK + tok0) * CDIM + h * HDIM;
    float* ob1 = g_att + ((size_t)b * NTOK + tok1) * CDIM + h * HDIM;
    #pragma unroll
    for (int nf = 0; nf < 4; nf++) {
        float2 w0, w1;
        w0.x = __uint_as_float(f2tf32(o[nf][0] * inv0));
        w0.y = __uint_as_float(f2tf32(o[nf][1] * inv0));
        w1.x = __uint_as_float(f2tf32(o[nf][2] * inv1));
        w1.y = __uint_as_float(f2tf32(o[nf][3] * inv1));
        *(float2*)(ob0 + nf * 8 + 2 * t) = w0;
        *(float2*)(ob1 + nf * 8 + 2 * t) = w1;
    }
}

// ---------------------------------------------------------------------------
// Host launch
// ---------------------------------------------------------------------------
extern "C" void kernel_launch(void* const* d_in, const int* in_sizes, int n_in,
                              void* d_out, int out_size)
{
    const float *x = nullptr, *mask = nullptr, *qkv_w = nullptr, *qkv_b = nullptr;
    const float *proj_w = nullptr, *proj_b = nullptr;
    const float *pos_proj_w = nullptr, *pos_proj_b = nullptr;
    const float *ln1_g = nullptr, *ln1_b = nullptr, *pos1_w = nullptr, *pos1_b = nullptr;
    const float *ln2_g = nullptr, *ln2_b = nullptr, *pos2_w = nullptr, *pos2_b = nullptr;
    const float *ln3_g = nullptr, *ln3_b = nullptr, *pos3_w = nullptr, *pos3_b = nullptr;

    int cnt24 = 0, cnt576 = 0;
    for (int i = 0; i < n_in; i++) {
        int sz = in_sizes[i];
        const float* p = (const float*)d_in[i];
        switch (sz) {
            case 12582912: x = p; break;
            case 2097152:  mask = p; break;
            case 442368:   qkv_w = p; break;
            case 1152:     qkv_b = p; break;
            case 147456:   proj_w = p; break;
            case 384:      proj_b = p; break;
            case 72:       pos_proj_w = p; break;
            case 288:      pos3_w = p; break;
            case 12:       pos3_b = p; break;
            case 576:
                if (cnt576 == 0) pos1_w = p; else pos2_w = p;
                cnt576++;
                break;
            case 24: {
                switch (cnt24) {
                    case 0: pos_proj_b = p; break;
                    case 1: ln1_g = p; break;
                    case 2: ln1_b = p; break;
                    case 3: pos1_b = p; break;
                    case 4: ln2_g = p; break;
                    case 5: ln2_b = p; break;
                    case 6: pos2_b = p; break;
                    case 7: ln3_g = p; break;
                    case 8: ln3_b = p; break;
                }
                cnt24++;
                break;
            }
            default: break;
        }
    }

    float* x32;      cudaGetSymbolAddress((void**)&x32, g_x32);
    uint32_t* wqkv;  cudaGetSymbolAddress((void**)&wqkv, g_wqkv);
    uint32_t* wproj; cudaGetSymbolAddress((void**)&wproj, g_wproj);

    const int SMEM_GEMM = (2 * AWORDS + 2 * BWORDS) * 4;
    const int SMEM_ATT = ATT_SMEM_FLOATS * 4;
    cudaFuncSetAttribute(mma_gemm, cudaFuncAttributeMaxDynamicSharedMemorySize,
                         SMEM_GEMM);
    cudaFuncSetAttribute(attn_kernel, cudaFuncAttributeMaxDynamicSharedMemorySize,
                         SMEM_ATT);

    // 1. pos MLP table
    pos_mlp_kernel<<<(LPOS + 127) / 128, 128>>>(
        pos_proj_w, pos_proj_b,
        ln1_g, ln1_b, pos1_w, pos1_b,
        ln2_g, ln2_b, pos2_w, pos2_b,
        ln3_g, ln3_b, pos3_w, pos3_b);

    // 2. fused bias+mask table
    bm_fill_kernel<<<(NTOK * NTOK) / 256, 256>>>(mask);

    // 2b. pre-convert / pre-permute operands
    cvt_tf32_kernel<<<(BWIN * NTOK * CDIM / 4 + 255) / 256, 256>>>(
        x, x32, BWIN * NTOK * CDIM);
    permute_w_kernel<<<(CDIM * 3 * CDIM + 255) / 256, 256>>>(
        qkv_w, wqkv, CDIM, 3 * CDIM);
    permute_w_kernel<<<(CDIM * CDIM + 255) / 256, 256>>>(
        proj_w, wproj, CDIM, CDIM);

    // 3. QKV GEMM + scatter (rounds Q/K/V to tf32)
    mma_gemm<<<dim3(3 * CDIM / 128, (BWIN * NTOK) / 128), 256, SMEM_GEMM>>>(
        x32, wqkv, qkv_b, 3 * CDIM, 0, nullptr);

    // 4. fused attention (tensor cores)
    attn_kernel<<<dim3(NTOK / 128, NHEAD, BWIN), 256, SMEM_ATT>>>();

    // 5. output projection
    mma_gemm<<<dim3(CDIM / 128, (BWIN * NTOK) / 128), 256, SMEM_GEMM>>>(
        nullptr, wproj, proj_b, CDIM, 1, (float*)d_out);

    (void)out_size;
}

// round 8
// speedup vs baseline: 3.2783x; 1.0749x over previous
#include <cuda_runtime.h>
#include <math.h>
#include <stdint.h>

// ---------------------------------------------------------------------------
// Problem constants
// ---------------------------------------------------------------------------
#define BWIN   64
#define NTOK   512
#define CDIM   384
#define NHEAD  12
#define HDIM   32
#define LPOS   3375
#define PDIM   24
#define NGRP   8
#define SCALE  0.17677669529663687f
#define LOG2E  1.4426950408889634f
#define QSCALE (SCALE * LOG2E)
#define NCH    12            // 384 / 32 k-chunks

// ---------------------------------------------------------------------------
// Scratch
// ---------------------------------------------------------------------------
__device__ float    g_pos[LPOS * NHEAD];
__device__ uint32_t g_bmp[(size_t)NGRP * NHEAD * NTOK * (NTOK / 2)]; // bf16x2 (bias+mask)*log2e
__device__ float    g_Q[BWIN * NHEAD * NTOK * HDIM];   // tf32, *SCALE*log2e
__device__ float    g_K[BWIN * NHEAD * NTOK * HDIM];   // tf32
__device__ float    g_V[BWIN * NHEAD * NTOK * HDIM];   // tf32
__device__ float    g_att[BWIN * NTOK * CDIM];         // attn out, tf32
__device__ float    g_x32[BWIN * NTOK * CDIM];         // x pre-rounded to tf32
__device__ uint32_t g_wqkv[CDIM * 3 * CDIM];           // qkv_w permuted tf32
__device__ uint32_t g_wproj[CDIM * CDIM];              // proj_w permuted tf32

// ---------------------------------------------------------------------------
// helpers
// ---------------------------------------------------------------------------
__device__ __forceinline__ uint32_t f2tf32(float f) {
    uint32_t r;
    asm("cvt.rna.tf32.f32 %0, %1;" : "=r"(r) : "f"(f));
    return r;
}
__device__ __forceinline__ float ex2f(float x) {
    float r;
    asm("ex2.approx.ftz.f32 %0, %1;" : "=f"(r) : "f"(x));
    return r;
}
__device__ __forceinline__ uint32_t pack_bf16x2(float lo, float hi) {
    uint32_t r;
    asm("cvt.rn.bf16x2.f32 %0, %1, %2;" : "=r"(r) : "f"(hi), "f"(lo));
    return r;
}
__device__ __forceinline__ void mma_tf32(float c[4], const uint32_t a[4],
                                         const uint32_t b[2]) {
    asm volatile(
        "mma.sync.aligned.m16n8k8.row.col.f32.tf32.tf32.f32 "
        "{%0,%1,%2,%3}, {%4,%5,%6,%7}, {%8,%9}, {%0,%1,%2,%3};"
        : "+f"(c[0]), "+f"(c[1]), "+f"(c[2]), "+f"(c[3])
        : "r"(a[0]), "r"(a[1]), "r"(a[2]), "r"(a[3]),
          "r"(b[0]), "r"(b[1]));
}
__device__ __forceinline__ uint32_t smem_u32(const void* p) {
    uint32_t a;
    asm("{ .reg .u64 t; cvta.to.shared.u64 t, %1; cvt.u32.u64 %0, t; }"
        : "=r"(a) : "l"(p));
    return a;
}
__device__ __forceinline__ void cp16(uint32_t dst, const void* src) {
    asm volatile("cp.async.cg.shared.global [%0], [%1], 16;"
                 :: "r"(dst), "l"(src) : "memory");
}
__device__ __forceinline__ void cp_commit() {
    asm volatile("cp.async.commit_group;" ::: "memory");
}
__device__ __forceinline__ void cp_wait0() {
    asm volatile("cp.async.wait_group 0;" ::: "memory");
}
__device__ __forceinline__ void cp_wait1() {
    asm volatile("cp.async.wait_group 1;" ::: "memory");
}

// ---------------------------------------------------------------------------
// Pre-pass: round fp32 -> tf32 bits
// ---------------------------------------------------------------------------
__global__ void cvt_tf32_kernel(const float* __restrict__ in,
                                float* __restrict__ out, int n) {
    int i = (blockIdx.x * blockDim.x + threadIdx.x) * 4;
    if (i >= n) return;
    float4 v = *(const float4*)(in + i);
    float4 r;
    r.x = __uint_as_float(f2tf32(v.x));
    r.y = __uint_as_float(f2tf32(v.y));
    r.z = __uint_as_float(f2tf32(v.z));
    r.w = __uint_as_float(f2tf32(v.w));
    *(float4*)(out + i) = r;
}

// ---------------------------------------------------------------------------
// Pre-pass: permute weight [K][Ntot] into mma fragment order
// ---------------------------------------------------------------------------
__global__ void permute_w_kernel(const float* __restrict__ W,
                                 uint32_t* __restrict__ out, int K, int Ntot) {
    int idx = blockIdx.x * blockDim.x + threadIdx.x;
    if (idx >= K * Ntot) return;
    int k = idx / Ntot, n = idx % Ntot;
    uint32_t val = f2tf32(W[(size_t)k * Ntot + n]);
    int kc = k >> 5, ks = (k >> 3) & 3, kt = k & 7;
    int t = kt & 3, hi = kt >> 2;
    int n0 = n >> 7, wn = (n >> 5) & 3, nf = (n >> 3) & 3, g = n & 7;
    int lane = g * 4 + t;
    size_t chunk = (size_t)n0 * NCH + kc;
    size_t off = chunk * 4096 + (((wn * 4 + ks) * 4 + nf) * 32 + lane) * 2 + hi;
    out[off] = val;
}

// ---------------------------------------------------------------------------
// Kernel 1: dynamic position-bias MLP
// ---------------------------------------------------------------------------
__device__ __forceinline__ void ln_relu(const float* in, float* t,
                                        const float* g, const float* bt) {
    float m = 0.f;
    #pragma unroll
    for (int i = 0; i < PDIM; i++) m += in[i];
    m *= (1.0f / PDIM);
    float v = 0.f;
    #pragma unroll
    for (int i = 0; i < PDIM; i++) { float d = in[i] - m; v += d * d; }
    v *= (1.0f / PDIM);
    float inv = rsqrtf(v + 1e-5f);
    #pragma unroll
    for (int i = 0; i < PDIM; i++) {
        float y = (in[i] - m) * inv * g[i] + bt[i];
        t[i] = fmaxf(y, 0.f);
    }
}

__global__ void pos_mlp_kernel(
    const float* __restrict__ pw,  const float* __restrict__ pb,
    const float* __restrict__ g1,  const float* __restrict__ b1,
    const float* __restrict__ w1,  const float* __restrict__ wb1,
    const float* __restrict__ g2,  const float* __restrict__ b2,
    const float* __restrict__ w2,  const float* __restrict__ wb2,
    const float* __restrict__ g3,  const float* __restrict__ b3,
    const float* __restrict__ w3,  const float* __restrict__ wb3)
{
    int l = blockIdx.x * blockDim.x + threadIdx.x;
    if (l >= LPOS) return;
    float c0 = (float)(l / 225 - 7);
    float c1 = (float)((l / 15) % 15 - 7);
    float c2 = (float)(l % 15 - 7);

    float v0[PDIM], v1[PDIM], v2[PDIM], t[PDIM];
    #pragma unroll
    for (int o = 0; o < PDIM; o++)
        v0[o] = c0 * pw[o] + c1 * pw[PDIM + o] + c2 * pw[2 * PDIM + o] + pb[o];

    ln_relu(v0, t, g1, b1);
    #pragma unroll
    for (int o = 0; o < PDIM; o++) {
        float s = wb1[o];
        #pragma unroll
        for (int i = 0; i < PDIM; i++) s = fmaf(t[i], w1[i * PDIM + o], s);
        v1[o] = s;
    }
    ln_relu(v1, t, g2, b2);
    #pragma unroll
    for (int o = 0; o < PDIM; o++) {
        float s = wb2[o];
        #pragma unroll
        for (int i = 0; i < PDIM; i++) s = fmaf(t[i], w2[i * PDIM + o], s);
        v2[o] = s;
    }
    ln_relu(v2, t, g3, b3);
    #pragma unroll
    for (int o = 0; o < NHEAD; o++) {
        float s = wb3[o];
        #pragma unroll
        for (int i = 0; i < PDIM; i++) s = fmaf(t[i], w3[i * NHEAD + o], s);
        g_pos[l * NHEAD + o] = s;
    }
}

// ---------------------------------------------------------------------------
// Kernel 2: fused bias+mask table, bf16x2-packed, pre-scaled by log2(e).
// Thread handles one (n, m-pair). bm[grp][h][n][m/2] = bf16x2((pos+mask)*log2e)
// ---------------------------------------------------------------------------
__global__ void bm_fill_kernel(const float* __restrict__ mask) {
    int t = blockIdx.x * blockDim.x + threadIdx.x;   // 512*256 threads
    int n = t >> 8, mt = t & 255;
    int m0 = mt * 2, m1 = m0 + 1;
    int i1 = n >> 6, j1 = (n >> 3) & 7, k1 = n & 7;

    int i20 = m0 >> 6, j20 = (m0 >> 3) & 7, k20 = m0 & 7;
    int i21 = m1 >> 6, j21 = (m1 >> 3) & 7, k21 = m1 & 7;
    int idx0 = ((i1 - i20 + 7) * 15 + (j1 - j20 + 7)) * 15 + (k1 - k20 + 7);
    int idx1 = ((i1 - i21 + 7) * 15 + (j1 - j21 + 7)) * 15 + (k1 - k21 + 7);

    float pv0[NHEAD], pv1[NHEAD];
    #pragma unroll
    for (int h = 0; h < NHEAD; h++) {
        pv0[h] = g_pos[idx0 * NHEAD + h];
        pv1[h] = g_pos[idx1 * NHEAD + h];
    }
    #pragma unroll
    for (int grp = 0; grp < NGRP; grp++) {
        float mv0 = mask[((size_t)grp * NTOK + n) * NTOK + m0];
        float mv1 = mask[((size_t)grp * NTOK + n) * NTOK + m1];
        #pragma unroll
        for (int h = 0; h < NHEAD; h++) {
            float lo = (pv0[h] + mv0) * LOG2E;
            float hi = (pv1[h] + mv1) * LOG2E;
            g_bmp[(((size_t)grp * NHEAD + h) * NTOK + n) * (NTOK / 2) + mt] =
                pack_bf16x2(lo, hi);
        }
    }
}

// ---------------------------------------------------------------------------
// Kernel 3/5: tf32 mma.sync GEMM (pipelined; QKV epilogue rounds to tf32,
// Q additionally scaled by SCALE*log2e for the exp2 softmax domain)
// ---------------------------------------------------------------------------
#define AWORDS 4608   // 128 * 36
#define BWORDS 4096   // 128n * 32k

__global__ __launch_bounds__(256, 2)
void mma_gemm(const float* __restrict__ Aglob, const uint32_t* __restrict__ Wperm,
              const float* __restrict__ bias, int Ntot, int mode,
              float* __restrict__ out)
{
    extern __shared__ uint32_t sbuf[];
    uint32_t* Abuf = sbuf;
    uint32_t* Bbuf = sbuf + 2 * AWORDS;

    const float* A = (mode == 1) ? g_att : Aglob;
    int tid = threadIdx.x;
    int wid = tid >> 5, lane = tid & 31;
    int g = lane >> 2, t = lane & 3;
    int wm = (wid & 1) * 64;
    int wn_idx = wid >> 1;

    int m0 = blockIdx.y * 128;
    int n0t = blockIdx.x;
    int n0 = n0t * 128;

    uint32_t aAddr = smem_u32(Abuf);
    uint32_t bAddr = smem_u32(Bbuf);
    const float* Arow = A + (size_t)m0 * CDIM;
    const uint32_t* Wbase = Wperm + (size_t)n0t * NCH * BWORDS;

    float acc[4][4][4];
    #pragma unroll
    for (int mf = 0; mf < 4; mf++)
        #pragma unroll
        for (int nf = 0; nf < 4; nf++)
            #pragma unroll
            for (int e = 0; e < 4; e++) acc[mf][nf][e] = 0.f;

    {
        uint32_t ad = aAddr;
        #pragma unroll
        for (int i = 0; i < 4; i++) {
            int c = tid + i * 256;
            int r = c >> 3, q = c & 7;
            cp16(ad + (uint32_t)(r * 36 + q * 4) * 4, Arow + (size_t)r * CDIM + q * 4);
        }
        uint32_t bd = bAddr;
        const uint32_t* src = Wbase;
        #pragma unroll
        for (int i = 0; i < 4; i++) {
            int c = tid + i * 256;
            cp16(bd + (uint32_t)c * 16, src + (size_t)c * 4);
        }
        cp_commit();
    }

    for (int kc = 0; kc < NCH; kc++) {
        int cur = kc & 1;
        if (kc + 1 < NCH) {
            int nxt = cur ^ 1;
            uint32_t ad = aAddr + (uint32_t)nxt * AWORDS * 4;
            const float* arow = Arow + (kc + 1) * 32;
            #pragma unroll
            for (int i = 0; i < 4; i++) {
                int c = tid + i * 256;
                int r = c >> 3, q = c & 7;
                cp16(ad + (uint32_t)(r * 36 + q * 4) * 4,
                     arow + (size_t)r * CDIM + q * 4);
            }
            uint32_t bd = bAddr + (uint32_t)nxt * BWORDS * 4;
            const uint32_t* src = Wbase + (size_t)(kc + 1) * BWORDS;
            #pragma unroll
            for (int i = 0; i < 4; i++) {
                int c = tid + i * 256;
                cp16(bd + (uint32_t)c * 16, src + (size_t)c * 4);
            }
            cp_commit();
            cp_wait1();
        } else {
            cp_wait0();
        }
        __syncthreads();

        const uint32_t* ab = Abuf + cur * AWORDS;
        const uint32_t* bb = Bbuf + cur * BWORDS + wn_idx * 1024;

        #pragma unroll
        for (int ks = 0; ks < 4; ks++) {
            uint32_t bf[4][2];
            const uint32_t* bks = bb + ks * 256 + lane * 2;
            #pragma unroll
            for (int nf = 0; nf < 4; nf++) {
                uint2 v = *(const uint2*)(bks + nf * 64);
                bf[nf][0] = v.x; bf[nf][1] = v.y;
            }
            uint32_t af[4][4];
            #pragma unroll
            for (int mf = 0; mf < 4; mf++) {
                int r = wm + mf * 16 + g;
                const uint32_t* a0 = ab + r * 36 + ks * 8 + t;
                af[mf][0] = a0[0];
                af[mf][1] = a0[8 * 36];
                af[mf][2] = a0[4];
                af[mf][3] = a0[8 * 36 + 4];
            }
            #pragma unroll
            for (int mf = 0; mf < 4; mf++)
                #pragma unroll
                for (int nf = 0; nf < 4; nf++)
                    mma_tf32(acc[mf][nf], af[mf], bf[nf]);
        }
        __syncthreads();
    }

    #pragma unroll
    for (int mf = 0; mf < 4; mf++) {
        #pragma unroll
        for (int nf = 0; nf < 4; nf++) {
            int rbase = m0 + wm + mf * 16 + g;
            int cbase = n0 + wn_idx * 32 + nf * 8 + 2 * t;
            #pragma unroll
            for (int e = 0; e < 4; e++) {
                int gm = rbase + (e >> 1) * 8;
                int gn = cbase + (e & 1);
                float val = acc[mf][nf][e] + bias[gn];
                if (mode == 0) {
                    int which = gn / CDIM;
                    int r = gn - which * CDIM;
                    int h = r >> 5, dd = r & 31;
                    int b = gm >> 9, tok = gm & 511;
                    size_t off = (((size_t)b * NHEAD + h) * NTOK + tok) * HDIM + dd;
                    if (which == 0)
                        g_Q[off] = __uint_as_float(f2tf32(val * QSCALE));
                    else if (which == 1)
                        g_K[off] = __uint_as_float(f2tf32(val));
                    else
                        g_V[off] = __uint_as_float(f2tf32(val));
                } else {
                    out[(size_t)gm * CDIM + gn] = val;
                }
            }
        }
    }
}

// ---------------------------------------------------------------------------
// Kernel 4: fused flash attention on tensor cores (tf32 mma.sync).
// Softmax in exp2 domain (scores pre-scaled by log2e). Bias+mask comes
// bf16x2-packed from g_bmp (one LDG.32 per row-pair element).
// SMEM floats: Qs[128][36] @0, Ks 2x[64][36] @4608, Vt[32][68] @9216,
//              Ps[128][68] @11392. Total 20096 floats = 80384 B.
// ---------------------------------------------------------------------------
#define ATT_SMEM_FLOATS 20096

__global__ __launch_bounds__(256, 2)
void attn_kernel()
{
    extern __shared__ float sm[];
    float* Qs = sm;                 // [128][36]
    float* Ks = sm + 4608;          // 2 x [64][36]
    float* Vt = sm + 9216;          // [32][68]
    float* Ps = sm + 11392;         // [128][68]

    int tid = threadIdx.x;
    int wid = tid >> 5, lane = tid & 31;
    int g = lane >> 2, t = lane & 3;
    int q0 = blockIdx.x * 128, h = blockIdx.y, b = blockIdx.z;

    const float* Qb = g_Q + (((size_t)b * NHEAD + h) * NTOK + q0) * HDIM;
    const float* Kb = g_K + ((size_t)b * NHEAD + h) * NTOK * HDIM;
    const float* Vb = g_V + ((size_t)b * NHEAD + h) * NTOK * HDIM;
    const uint32_t* bmb = g_bmp + ((size_t)((b & 7) * NHEAD + h)) * NTOK * (NTOK / 2);

    uint32_t qAddr = smem_u32(Qs);
    uint32_t kAddr = smem_u32(Ks);

    // prime: cp.async Q (128x32) + K tile 0 into buf 0
    #pragma unroll
    for (int i = 0; i < 4; i++) {
        int c = tid + i * 256;
        int r = c >> 3, q = c & 7;
        cp16(qAddr + (uint32_t)(r * 36 + q * 4) * 4, Qb + (size_t)r * HDIM + q * 4);
    }
    #pragma unroll
    for (int i = 0; i < 2; i++) {
        int c = tid + i * 256;
        int r = c >> 3, q = c & 7;
        cp16(kAddr + (uint32_t)(r * 36 + q * 4) * 4, Kb + (size_t)r * HDIM + q * 4);
    }
    cp_commit();

    // preload V tile 0 to regs
    float4 vr0, vr1;
    {
        int c0 = tid, c1 = tid + 256;
        vr0 = *(const float4*)(Vb + (size_t)(c0 >> 3) * HDIM + (c0 & 7) * 4);
        vr1 = *(const float4*)(Vb + (size_t)(c1 >> 3) * HDIM + (c1 & 7) * 4);
    }

    int row_l = wid * 16 + g;               // local row (in 0..127)

    // wait for Q+K0, hoist Q fragments into registers (loop-invariant)
    cp_wait0();
    __syncthreads();
    uint32_t qf[4][4];
    #pragma unroll
    for (int ks = 0; ks < 4; ks++) {
        const float* a0 = Qs + row_l * 36 + ks * 8 + t;
        qf[ks][0] = __float_as_uint(a0[0]);
        qf[ks][1] = __float_as_uint(a0[8 * 36]);
        qf[ks][2] = __float_as_uint(a0[4]);
        qf[ks][3] = __float_as_uint(a0[8 * 36 + 4]);
    }

    float m0r = -1e30f, m1r = -1e30f, l0r = 0.f, l1r = 0.f;
    float o[4][4];
    #pragma unroll
    for (int nf = 0; nf < 4; nf++)
        #pragma unroll
        for (int e = 0; e < 4; e++) o[nf][e] = 0.f;

    for (int kt = 0; kt < 8; kt++) {
        int cur = kt & 1;
        cp_wait0();
        // transpose-store V tile (loaded last iter) into Vt[d][key]
        {
            int c0 = tid, c1 = tid + 256;
            int key0 = c0 >> 3, seg0 = (c0 & 7) * 4;
            int key1 = c1 >> 3, seg1 = (c1 & 7) * 4;
            Vt[(seg0 + 0) * 68 + key0] = vr0.x;
            Vt[(seg0 + 1) * 68 + key0] = vr0.y;
            Vt[(seg0 + 2) * 68 + key0] = vr0.z;
            Vt[(seg0 + 3) * 68 + key0] = vr0.w;
            Vt[(seg1 + 0) * 68 + key1] = vr1.x;
            Vt[(seg1 + 1) * 68 + key1] = vr1.y;
            Vt[(seg1 + 2) * 68 + key1] = vr1.z;
            Vt[(seg1 + 3) * 68 + key1] = vr1.w;
        }
        __syncthreads();

        if (kt < 7) {
            int nxt = cur ^ 1;
            const float* ksrc = Kb + (size_t)(kt + 1) * 64 * HDIM;
            #pragma unroll
            for (int i = 0; i < 2; i++) {
                int c = tid + i * 256;
                int r = c >> 3, q = c & 7;
                cp16(kAddr + (uint32_t)(nxt * 2304 + r * 36 + q * 4) * 4,
                     ksrc + (size_t)r * HDIM + q * 4);
            }
            cp_commit();
            const float* vsrc = Vb + (size_t)(kt + 1) * 64 * HDIM;
            int c0 = tid, c1 = tid + 256;
            vr0 = *(const float4*)(vsrc + (size_t)(c0 >> 3) * HDIM + (c0 & 7) * 4);
            vr1 = *(const float4*)(vsrc + (size_t)(c1 >> 3) * HDIM + (c1 & 7) * 4);
        }

        // ---- S = Q @ K^T : warp computes [16 q][64 key] ----
        float s[8][4];
        #pragma unroll
        for (int nf = 0; nf < 8; nf++)
            #pragma unroll
            for (int e = 0; e < 4; e++) s[nf][e] = 0.f;

        const float* kc = Ks + cur * 2304;
        #pragma unroll
        for (int ks = 0; ks < 4; ks++) {
            #pragma unroll
            for (int nf = 0; nf < 8; nf++) {
                const float* bp = kc + (nf * 8 + g) * 36 + ks * 8 + t;
                uint32_t bf[2] = { __float_as_uint(bp[0]), __float_as_uint(bp[4]) };
                mma_tf32(s[nf], qf[ks], bf);
            }
        }

        // ---- fused bias+mask (bf16x2) + online softmax (exp2 domain) ----
        int row0 = q0 + row_l, row1 = row0 + 8;
        int pbase = (kt * 64) >> 1;
        float lm0 = -1e30f, lm1 = -1e30f;
        #pragma unroll
        for (int nf = 0; nf < 8; nf++) {
            int pidx = pbase + nf * 4 + t;
            uint32_t u0 = bmb[(size_t)row0 * (NTOK / 2) + pidx];
            uint32_t u1 = bmb[(size_t)row1 * (NTOK / 2) + pidx];
            s[nf][0] += __uint_as_float(u0 << 16);
            s[nf][1] += __uint_as_float(u0 & 0xffff0000u);
            s[nf][2] += __uint_as_float(u1 << 16);
            s[nf][3] += __uint_as_float(u1 & 0xffff0000u);
            lm0 = fmaxf(lm0, fmaxf(s[nf][0], s[nf][1]));
            lm1 = fmaxf(lm1, fmaxf(s[nf][2], s[nf][3]));
        }
        lm0 = fmaxf(lm0, __shfl_xor_sync(0xffffffffu, lm0, 1));
        lm0 = fmaxf(lm0, __shfl_xor_sync(0xffffffffu, lm0, 2));
        lm1 = fmaxf(lm1, __shfl_xor_sync(0xffffffffu, lm1, 1));
        lm1 = fmaxf(lm1, __shfl_xor_sync(0xffffffffu, lm1, 2));

        float nm0 = fmaxf(m0r, lm0), nm1 = fmaxf(m1r, lm1);
        float cr0 = ex2f(m0r - nm0), cr1 = ex2f(m1r - nm1);
        m0r = nm0; m1r = nm1;

        float ls0 = 0.f, ls1 = 0.f;
        #pragma unroll
        for (int nf = 0; nf < 8; nf++) {
            float p0 = ex2f(s[nf][0] - nm0);
            float p1 = ex2f(s[nf][1] - nm0);
            float p2 = ex2f(s[nf][2] - nm1);
            float p3 = ex2f(s[nf][3] - nm1);
            ls0 += p0 + p1; ls1 += p2 + p3;
            float2 w0, w1;
            w0.x = __uint_as_float(f2tf32(p0));
            w0.y = __uint_as_float(f2tf32(p1));
            w1.x = __uint_as_float(f2tf32(p2));
            w1.y = __uint_as_float(f2tf32(p3));
            *(float2*)(Ps + row_l * 68 + nf * 8 + 2 * t) = w0;
            *(float2*)(Ps + (row_l + 8) * 68 + nf * 8 + 2 * t) = w1;
        }
        ls0 += __shfl_xor_sync(0xffffffffu, ls0, 1);
        ls0 += __shfl_xor_sync(0xffffffffu, ls0, 2);
        ls1 += __shfl_xor_sync(0xffffffffu, ls1, 1);
        ls1 += __shfl_xor_sync(0xffffffffu, ls1, 2);
        l0r = l0r * cr0 + ls0;
        l1r = l1r * cr1 + ls1;

        #pragma unroll
        for (int nf = 0; nf < 4; nf++) {
            o[nf][0] *= cr0; o[nf][1] *= cr0;
            o[nf][2] *= cr1; o[nf][3] *= cr1;
        }
        __syncwarp();   // Ps rows are warp-private

        // ---- O += P @ V : warp computes [16 q][32 d] ----
        #pragma unroll
        for (int ks = 0; ks < 8; ks++) {
            uint32_t af[4];
            const float* pa = Ps + row_l * 68 + ks * 8 + t;
            af[0] = __float_as_uint(pa[0]);
            af[1] = __float_as_uint(pa[8 * 68]);
            af[2] = __float_as_uint(pa[4]);
            af[3] = __float_as_uint(pa[8 * 68 + 4]);
            #pragma unroll
            for (int nf = 0; nf < 4; nf++) {
                const float* vp = Vt + (nf * 8 + g) * 68 + ks * 8 + t;
                uint32_t bf[2] = { __float_as_uint(vp[0]), __float_as_uint(vp[4]) };
                mma_tf32(o[nf], af, bf);
            }
        }
        __syncthreads();   // all PV reads done before next tile overwrites Vt/Ks
    }

    // epilogue
    float inv0 = 1.f / l0r, inv1 = 1.f / l1r;
    int tok0 = q0 + row_l, tok1 = tok0 + 8;
    float* ob0 = g_att + ((size_t)b * NTOK + tok0) * CDIM + h * HDIM;
    float* ob1 = g_att + ((size_t)b * NTOK + tok1) * CDIM + h * HDIM;
    #pragma unroll
    for (int nf = 0; nf < 4; nf++) {
        float2 w0, w1;
        w0.x = __uint_as_float(f2tf32(o[nf][0] * inv0));
        w0.y = __uint_as_float(f2tf32(o[nf][1] * inv0));
        w1.x = __uint_as_float(f2tf32(o[nf][2] * inv1));
        w1.y = __uint_as_float(f2tf32(o[nf][3] * inv1));
        *(float2*)(ob0 + nf * 8 + 2 * t) = w0;
        *(float2*)(ob1 + nf * 8 + 2 * t) = w1;
    }
}

// ---------------------------------------------------------------------------
// Host launch
// ---------------------------------------------------------------------------
extern "C" void kernel_launch(void* const* d_in, const int* in_sizes, int n_in,
                              void* d_out, int out_size)
{
    const float *x = nullptr, *mask = nullptr, *qkv_w = nullptr, *qkv_b = nullptr;
    const float *proj_w = nullptr, *proj_b = nullptr;
    const float *pos_proj_w = nullptr, *pos_proj_b = nullptr;
    const float *ln1_g = nullptr, *ln1_b = nullptr, *pos1_w = nullptr, *pos1_b = nullptr;
    const float *ln2_g = nullptr, *ln2_b = nullptr, *pos2_w = nullptr, *pos2_b = nullptr;
    const float *ln3_g = nullptr, *ln3_b = nullptr, *pos3_w = nullptr, *pos3_b = nullptr;

    int cnt24 = 0, cnt576 = 0;
    for (int i = 0; i < n_in; i++) {
        int sz = in_sizes[i];
        const float* p = (const float*)d_in[i];
        switch (sz) {
            case 12582912: x = p; break;
            case 2097152:  mask = p; break;
            case 442368:   qkv_w = p; break;
            case 1152:     qkv_b = p; break;
            case 147456:   proj_w = p; break;
            case 384:      proj_b = p; break;
            case 72:       pos_proj_w = p; break;
            case 288:      pos3_w = p; break;
            case 12:       pos3_b = p; break;
            case 576:
                if (cnt576 == 0) pos1_w = p; else pos2_w = p;
                cnt576++;
                break;
            case 24: {
                switch (cnt24) {
                    case 0: pos_proj_b = p; break;
                    case 1: ln1_g = p; break;
                    case 2: ln1_b = p; break;
                    case 3: pos1_b = p; break;
                    case 4: ln2_g = p; break;
                    case 5: ln2_b = p; break;
                    case 6: pos2_b = p; break;
                    case 7: ln3_g = p; break;
                    case 8: ln3_b = p; break;
                }
                cnt24++;
                break;
            }
            default: break;
        }
    }

    float* x32;      cudaGetSymbolAddress((void**)&x32, g_x32);
    uint32_t* wqkv;  cudaGetSymbolAddress((void**)&wqkv, g_wqkv);
    uint32_t* wproj; cudaGetSymbolAddress((void**)&wproj, g_wproj);

    const int SMEM_GEMM = (2 * AWORDS + 2 * BWORDS) * 4;
    const int SMEM_ATT = ATT_SMEM_FLOATS * 4;
    cudaFuncSetAttribute(mma_gemm, cudaFuncAttributeMaxDynamicSharedMemorySize,
                         SMEM_GEMM);
    cudaFuncSetAttribute(attn_kernel, cudaFuncAttributeMaxDynamicSharedMemorySize,
                         SMEM_ATT);

    // 1. pos MLP table
    pos_mlp_kernel<<<(LPOS + 127) / 128, 128>>>(
        pos_proj_w, pos_proj_b,
        ln1_g, ln1_b, pos1_w, pos1_b,
        ln2_g, ln2_b, pos2_w, pos2_b,
        ln3_g, ln3_b, pos3_w, pos3_b);

    // 2. fused bias+mask table (bf16x2, log2e-scaled)
    bm_fill_kernel<<<(NTOK * NTOK / 2) / 256, 256>>>(mask);

    // 2b. pre-convert / pre-permute operands
    cvt_tf32_kernel<<<(BWIN * NTOK * CDIM / 4 + 255) / 256, 256>>>(
        x, x32, BWIN * NTOK * CDIM);
    permute_w_kernel<<<(CDIM * 3 * CDIM + 255) / 256, 256>>>(
        qkv_w, wqkv, CDIM, 3 * CDIM);
    permute_w_kernel<<<(CDIM * CDIM + 255) / 256, 256>>>(
        proj_w, wproj, CDIM, CDIM);

    // 3. QKV GEMM + scatter (rounds Q/K/V to tf32; Q scaled for exp2 domain)
    mma_gemm<<<dim3(3 * CDIM / 128, (BWIN * NTOK) / 128), 256, SMEM_GEMM>>>(
        x32, wqkv, qkv_b, 3 * CDIM, 0, nullptr);

    // 4. fused attention (tensor cores)
    attn_kernel<<<dim3(NTOK / 128, NHEAD, BWIN), 256, SMEM_ATT>>>();

    // 5. output projection
    mma_gemm<<<dim3(CDIM / 128, (BWIN * NTOK) / 128), 256, SMEM_GEMM>>>(
        nullptr, wproj, proj_b, CDIM, 1, (float*)d_out);

    (void)out_size;
}

// round 9
// speedup vs baseline: 3.5892x; 1.0948x over previous
#include <cuda_runtime.h>
#include <math.h>
#include <stdint.h>

// ---------------------------------------------------------------------------
// Problem constants
// ---------------------------------------------------------------------------
#define BWIN   64
#define NTOK   512
#define CDIM   384
#define NHEAD  12
#define HDIM   32
#define LPOS   3375
#define PDIM   24
#define NGRP   8
#define SCALE  0.17677669529663687f
#define LOG2E  1.4426950408889634f
#define QSCALE (SCALE * LOG2E)
#define NCH    12            // 384 / 32 k-chunks

// ---------------------------------------------------------------------------
// Scratch
// ---------------------------------------------------------------------------
__device__ float    g_pos[LPOS * NHEAD];
__device__ uint32_t g_bmp[(size_t)NGRP * NHEAD * NTOK * (NTOK / 2)]; // bf16x2 (bias+mask)*log2e
__device__ float    g_Q[BWIN * NHEAD * NTOK * HDIM];   // tf32, *SCALE*log2e
__device__ float    g_K[BWIN * NHEAD * NTOK * HDIM];   // tf32
__device__ float    g_V[BWIN * NHEAD * NTOK * HDIM];   // tf32
__device__ float    g_att[BWIN * NTOK * CDIM];         // attn out, tf32
__device__ float    g_x32[BWIN * NTOK * CDIM];         // x pre-rounded to tf32
__device__ uint32_t g_wqkv[CDIM * 3 * CDIM];           // qkv_w permuted tf32
__device__ uint32_t g_wproj[CDIM * CDIM];              // proj_w permuted tf32

// ---------------------------------------------------------------------------
// helpers
// ---------------------------------------------------------------------------
__device__ __forceinline__ uint32_t f2tf32(float f) {
    uint32_t r;
    asm("cvt.rna.tf32.f32 %0, %1;" : "=r"(r) : "f"(f));
    return r;
}
__device__ __forceinline__ float ex2f(float x) {
    float r;
    asm("ex2.approx.ftz.f32 %0, %1;" : "=f"(r) : "f"(x));
    return r;
}
__device__ __forceinline__ uint32_t pack_bf16x2(float lo, float hi) {
    uint32_t r;
    asm("cvt.rn.bf16x2.f32 %0, %1, %2;" : "=r"(r) : "f"(hi), "f"(lo));
    return r;
}
__device__ __forceinline__ void mma_tf32(float c[4], const uint32_t a[4],
                                         const uint32_t b[2]) {
    asm volatile(
        "mma.sync.aligned.m16n8k8.row.col.f32.tf32.tf32.f32 "
        "{%0,%1,%2,%3}, {%4,%5,%6,%7}, {%8,%9}, {%0,%1,%2,%3};"
        : "+f"(c[0]), "+f"(c[1]), "+f"(c[2]), "+f"(c[3])
        : "r"(a[0]), "r"(a[1]), "r"(a[2]), "r"(a[3]),
          "r"(b[0]), "r"(b[1]));
}
__device__ __forceinline__ uint32_t smem_u32(const void* p) {
    uint32_t a;
    asm("{ .reg .u64 t; cvta.to.shared.u64 t, %1; cvt.u32.u64 %0, t; }"
        : "=r"(a) : "l"(p));
    return a;
}
__device__ __forceinline__ void cp16(uint32_t dst, const void* src) {
    asm volatile("cp.async.cg.shared.global [%0], [%1], 16;"
                 :: "r"(dst), "l"(src) : "memory");
}
__device__ __forceinline__ void cp_commit() {
    asm volatile("cp.async.commit_group;" ::: "memory");
}
__device__ __forceinline__ void cp_wait0() {
    asm volatile("cp.async.wait_group 0;" ::: "memory");
}
__device__ __forceinline__ void cp_wait1() {
    asm volatile("cp.async.wait_group 1;" ::: "memory");
}

// ---------------------------------------------------------------------------
// Pre-pass: round fp32 -> tf32 bits
// ---------------------------------------------------------------------------
__global__ void cvt_tf32_kernel(const float* __restrict__ in,
                                float* __restrict__ out, int n) {
    int i = (blockIdx.x * blockDim.x + threadIdx.x) * 4;
    if (i >= n) return;
    float4 v = *(const float4*)(in + i);
    float4 r;
    r.x = __uint_as_float(f2tf32(v.x));
    r.y = __uint_as_float(f2tf32(v.y));
    r.z = __uint_as_float(f2tf32(v.z));
    r.w = __uint_as_float(f2tf32(v.w));
    *(float4*)(out + i) = r;
}

// ---------------------------------------------------------------------------
// Pre-pass: permute weight [K][Ntot] into mma fragment order
// ---------------------------------------------------------------------------
__global__ void permute_w_kernel(const float* __restrict__ W,
                                 uint32_t* __restrict__ out, int K, int Ntot) {
    int idx = blockIdx.x * blockDim.x + threadIdx.x;
    if (idx >= K * Ntot) return;
    int k = idx / Ntot, n = idx % Ntot;
    uint32_t val = f2tf32(W[(size_t)k * Ntot + n]);
    int kc = k >> 5, ks = (k >> 3) & 3, kt = k & 7;
    int t = kt & 3, hi = kt >> 2;
    int n0 = n >> 7, wn = (n >> 5) & 3, nf = (n >> 3) & 3, g = n & 7;
    int lane = g * 4 + t;
    size_t chunk = (size_t)n0 * NCH + kc;
    size_t off = chunk * 4096 + (((wn * 4 + ks) * 4 + nf) * 32 + lane) * 2 + hi;
    out[off] = val;
}

// ---------------------------------------------------------------------------
// Kernel 1: dynamic position-bias MLP
// ---------------------------------------------------------------------------
__device__ __forceinline__ void ln_relu(const float* in, float* t,
                                        const float* g, const float* bt) {
    float m = 0.f;
    #pragma unroll
    for (int i = 0; i < PDIM; i++) m += in[i];
    m *= (1.0f / PDIM);
    float v = 0.f;
    #pragma unroll
    for (int i = 0; i < PDIM; i++) { float d = in[i] - m; v += d * d; }
    v *= (1.0f / PDIM);
    float inv = rsqrtf(v + 1e-5f);
    #pragma unroll
    for (int i = 0; i < PDIM; i++) {
        float y = (in[i] - m) * inv * g[i] + bt[i];
        t[i] = fmaxf(y, 0.f);
    }
}

__global__ void pos_mlp_kernel(
    const float* __restrict__ pw,  const float* __restrict__ pb,
    const float* __restrict__ g1,  const float* __restrict__ b1,
    const float* __restrict__ w1,  const float* __restrict__ wb1,
    const float* __restrict__ g2,  const float* __restrict__ b2,
    const float* __restrict__ w2,  const float* __restrict__ wb2,
    const float* __restrict__ g3,  const float* __restrict__ b3,
    const float* __restrict__ w3,  const float* __restrict__ wb3)
{
    int l = blockIdx.x * blockDim.x + threadIdx.x;
    if (l >= LPOS) return;
    float c0 = (float)(l / 225 - 7);
    float c1 = (float)((l / 15) % 15 - 7);
    float c2 = (float)(l % 15 - 7);

    float v0[PDIM], v1[PDIM], v2[PDIM], t[PDIM];
    #pragma unroll
    for (int o = 0; o < PDIM; o++)
        v0[o] = c0 * pw[o] + c1 * pw[PDIM + o] + c2 * pw[2 * PDIM + o] + pb[o];

    ln_relu(v0, t, g1, b1);
    #pragma unroll
    for (int o = 0; o < PDIM; o++) {
        float s = wb1[o];
        #pragma unroll
        for (int i = 0; i < PDIM; i++) s = fmaf(t[i], w1[i * PDIM + o], s);
        v1[o] = s;
    }
    ln_relu(v1, t, g2, b2);
    #pragma unroll
    for (int o = 0; o < PDIM; o++) {
        float s = wb2[o];
        #pragma unroll
        for (int i = 0; i < PDIM; i++) s = fmaf(t[i], w2[i * PDIM + o], s);
        v2[o] = s;
    }
    ln_relu(v2, t, g3, b3);
    #pragma unroll
    for (int o = 0; o < NHEAD; o++) {
        float s = wb3[o];
        #pragma unroll
        for (int i = 0; i < PDIM; i++) s = fmaf(t[i], w3[i * NHEAD + o], s);
        g_pos[l * NHEAD + o] = s;
    }
}

// ---------------------------------------------------------------------------
// Kernel 2: fused bias+mask table, bf16x2-packed, pre-scaled by log2(e).
// ---------------------------------------------------------------------------
__global__ void bm_fill_kernel(const float* __restrict__ mask) {
    int t = blockIdx.x * blockDim.x + threadIdx.x;   // 512*256 threads
    int n = t >> 8, mt = t & 255;
    int m0 = mt * 2, m1 = m0 + 1;
    int i1 = n >> 6, j1 = (n >> 3) & 7, k1 = n & 7;

    int i20 = m0 >> 6, j20 = (m0 >> 3) & 7, k20 = m0 & 7;
    int i21 = m1 >> 6, j21 = (m1 >> 3) & 7, k21 = m1 & 7;
    int idx0 = ((i1 - i20 + 7) * 15 + (j1 - j20 + 7)) * 15 + (k1 - k20 + 7);
    int idx1 = ((i1 - i21 + 7) * 15 + (j1 - j21 + 7)) * 15 + (k1 - k21 + 7);

    float pv0[NHEAD], pv1[NHEAD];
    #pragma unroll
    for (int h = 0; h < NHEAD; h++) {
        pv0[h] = g_pos[idx0 * NHEAD + h];
        pv1[h] = g_pos[idx1 * NHEAD + h];
    }
    #pragma unroll
    for (int grp = 0; grp < NGRP; grp++) {
        float mv0 = mask[((size_t)grp * NTOK + n) * NTOK + m0];
        float mv1 = mask[((size_t)grp * NTOK + n) * NTOK + m1];
        #pragma unroll
        for (int h = 0; h < NHEAD; h++) {
            float lo = (pv0[h] + mv0) * LOG2E;
            float hi = (pv1[h] + mv1) * LOG2E;
            g_bmp[(((size_t)grp * NHEAD + h) * NTOK + n) * (NTOK / 2) + mt] =
                pack_bf16x2(lo, hi);
        }
    }
}

// ---------------------------------------------------------------------------
// Kernel 3/5: tf32 mma.sync GEMM (pipelined; QKV epilogue rounds to tf32,
// Q additionally scaled by SCALE*log2e for the exp2 softmax domain)
// ---------------------------------------------------------------------------
#define AWORDS 4608   // 128 * 36
#define BWORDS 4096   // 128n * 32k

__global__ __launch_bounds__(256, 2)
void mma_gemm(const float* __restrict__ Aglob, const uint32_t* __restrict__ Wperm,
              const float* __restrict__ bias, int Ntot, int mode,
              float* __restrict__ out)
{
    extern __shared__ uint32_t sbuf[];
    uint32_t* Abuf = sbuf;
    uint32_t* Bbuf = sbuf + 2 * AWORDS;

    const float* A = (mode == 1) ? g_att : Aglob;
    int tid = threadIdx.x;
    int wid = tid >> 5, lane = tid & 31;
    int g = lane >> 2, t = lane & 3;
    int wm = (wid & 1) * 64;
    int wn_idx = wid >> 1;

    int m0 = blockIdx.y * 128;
    int n0t = blockIdx.x;
    int n0 = n0t * 128;

    uint32_t aAddr = smem_u32(Abuf);
    uint32_t bAddr = smem_u32(Bbuf);
    const float* Arow = A + (size_t)m0 * CDIM;
    const uint32_t* Wbase = Wperm + (size_t)n0t * NCH * BWORDS;

    float acc[4][4][4];
    #pragma unroll
    for (int mf = 0; mf < 4; mf++)
        #pragma unroll
        for (int nf = 0; nf < 4; nf++)
            #pragma unroll
            for (int e = 0; e < 4; e++) acc[mf][nf][e] = 0.f;

    {
        uint32_t ad = aAddr;
        #pragma unroll
        for (int i = 0; i < 4; i++) {
            int c = tid + i * 256;
            int r = c >> 3, q = c & 7;
            cp16(ad + (uint32_t)(r * 36 + q * 4) * 4, Arow + (size_t)r * CDIM + q * 4);
        }
        uint32_t bd = bAddr;
        const uint32_t* src = Wbase;
        #pragma unroll
        for (int i = 0; i < 4; i++) {
            int c = tid + i * 256;
            cp16(bd + (uint32_t)c * 16, src + (size_t)c * 4);
        }
        cp_commit();
    }

    for (int kc = 0; kc < NCH; kc++) {
        int cur = kc & 1;
        if (kc + 1 < NCH) {
            int nxt = cur ^ 1;
            uint32_t ad = aAddr + (uint32_t)nxt * AWORDS * 4;
            const float* arow = Arow + (kc + 1) * 32;
            #pragma unroll
            for (int i = 0; i < 4; i++) {
                int c = tid + i * 256;
                int r = c >> 3, q = c & 7;
                cp16(ad + (uint32_t)(r * 36 + q * 4) * 4,
                     arow + (size_t)r * CDIM + q * 4);
            }
            uint32_t bd = bAddr + (uint32_t)nxt * BWORDS * 4;
            const uint32_t* src = Wbase + (size_t)(kc + 1) * BWORDS;
            #pragma unroll
            for (int i = 0; i < 4; i++) {
                int c = tid + i * 256;
                cp16(bd + (uint32_t)c * 16, src + (size_t)c * 4);
            }
            cp_commit();
            cp_wait1();
        } else {
            cp_wait0();
        }
        __syncthreads();

        const uint32_t* ab = Abuf + cur * AWORDS;
        const uint32_t* bb = Bbuf + cur * BWORDS + wn_idx * 1024;

        #pragma unroll
        for (int ks = 0; ks < 4; ks++) {
            uint32_t bf[4][2];
            const uint32_t* bks = bb + ks * 256 + lane * 2;
            #pragma unroll
            for (int nf = 0; nf < 4; nf++) {
                uint2 v = *(const uint2*)(bks + nf * 64);
                bf[nf][0] = v.x; bf[nf][1] = v.y;
            }
            uint32_t af[4][4];
            #pragma unroll
            for (int mf = 0; mf < 4; mf++) {
                int r = wm + mf * 16 + g;
                const uint32_t* a0 = ab + r * 36 + ks * 8 + t;
                af[mf][0] = a0[0];
                af[mf][1] = a0[8 * 36];
                af[mf][2] = a0[4];
                af[mf][3] = a0[8 * 36 + 4];
            }
            #pragma unroll
            for (int mf = 0; mf < 4; mf++)
                #pragma unroll
                for (int nf = 0; nf < 4; nf++)
                    mma_tf32(acc[mf][nf], af[mf], bf[nf]);
        }
        __syncthreads();
    }

    #pragma unroll
    for (int mf = 0; mf < 4; mf++) {
        #pragma unroll
        for (int nf = 0; nf < 4; nf++) {
            int rbase = m0 + wm + mf * 16 + g;
            int cbase = n0 + wn_idx * 32 + nf * 8 + 2 * t;
            #pragma unroll
            for (int e = 0; e < 4; e++) {
                int gm = rbase + (e >> 1) * 8;
                int gn = cbase + (e & 1);
                float val = acc[mf][nf][e] + bias[gn];
                if (mode == 0) {
                    int which = gn / CDIM;
                    int r = gn - which * CDIM;
                    int h = r >> 5, dd = r & 31;
                    int b = gm >> 9, tok = gm & 511;
                    size_t off = (((size_t)b * NHEAD + h) * NTOK + tok) * HDIM + dd;
                    if (which == 0)
                        g_Q[off] = __uint_as_float(f2tf32(val * QSCALE));
                    else if (which == 1)
                        g_K[off] = __uint_as_float(f2tf32(val));
                    else
                        g_V[off] = __uint_as_float(f2tf32(val));
                } else {
                    out[(size_t)gm * CDIM + gn] = val;
                }
            }
        }
    }
}

// ---------------------------------------------------------------------------
// Kernel 4: fused flash attention on tensor cores (tf32 mma.sync).
// All operands cp.async-prefetched, including the bf16x2 bias+mask tile.
// SMEM words: [0..4608)      Qs (dead after qf hoist) -> bm buffer 0
//             [4608..9216)   Ks 2 x [64][36]
//             [9216..11392)  Vt [32][68]
//             [11392..20096) Ps [128][68]
//             [20096..24704) bm buffer 1
// bm tile layout: [128 rows][36 words] (stride 36 -> 16B-aligned rows +
// conflict-free LDS: bank = (4g + 4nf + t) mod 32).
// ---------------------------------------------------------------------------
#define ATT_SMEM_FLOATS 24704
#define BM_BUF1 20096

__global__ __launch_bounds__(256, 2)
void attn_kernel()
{
    extern __shared__ float sm[];
    float* Qs = sm;                 // [128][36]; becomes bm buf 0
    float* Ks = sm + 4608;          // 2 x [64][36]
    float* Vt = sm + 9216;          // [32][68]
    float* Ps = sm + 11392;         // [128][68]

    int tid = threadIdx.x;
    int wid = tid >> 5, lane = tid & 31;
    int g = lane >> 2, t = lane & 3;
    int q0 = blockIdx.x * 128, h = blockIdx.y, b = blockIdx.z;

    const float* Qb = g_Q + (((size_t)b * NHEAD + h) * NTOK + q0) * HDIM;
    const float* Kb = g_K + ((size_t)b * NHEAD + h) * NTOK * HDIM;
    const float* Vb = g_V + ((size_t)b * NHEAD + h) * NTOK * HDIM;
    const uint32_t* bmb = g_bmp + ((size_t)((b & 7) * NHEAD + h)) * NTOK * (NTOK / 2)
                        + (size_t)q0 * (NTOK / 2);

    uint32_t smAddr = smem_u32(sm);
    uint32_t kAddr = smAddr + 4608 * 4;

    // prime: cp.async Q (128x32) + K tile 0 into buf 0
    #pragma unroll
    for (int i = 0; i < 4; i++) {
        int c = tid + i * 256;
        int r = c >> 3, q = c & 7;
        cp16(smAddr + (uint32_t)(r * 36 + q * 4) * 4, Qb + (size_t)r * HDIM + q * 4);
    }
    #pragma unroll
    for (int i = 0; i < 2; i++) {
        int c = tid + i * 256;
        int r = c >> 3, q = c & 7;
        cp16(kAddr + (uint32_t)(r * 36 + q * 4) * 4, Kb + (size_t)r * HDIM + q * 4);
    }
    cp_commit();

    // preload V tile 0 to regs
    float4 vr0, vr1;
    {
        int c0 = tid, c1 = tid + 256;
        vr0 = *(const float4*)(Vb + (size_t)(c0 >> 3) * HDIM + (c0 & 7) * 4);
        vr1 = *(const float4*)(Vb + (size_t)(c1 >> 3) * HDIM + (c1 & 7) * 4);
    }

    int row_l = wid * 16 + g;               // local row (in 0..127)

    // wait for Q+K0, hoist Q fragments into registers (loop-invariant)
    cp_wait0();
    __syncthreads();
    uint32_t qf[4][4];
    #pragma unroll
    for (int ks = 0; ks < 4; ks++) {
        const float* a0 = Qs + row_l * 36 + ks * 8 + t;
        qf[ks][0] = __float_as_uint(a0[0]);
        qf[ks][1] = __float_as_uint(a0[8 * 36]);
        qf[ks][2] = __float_as_uint(a0[4]);
        qf[ks][3] = __float_as_uint(a0[8 * 36 + 4]);
    }
    __syncthreads();   // all Qs reads done before bm tile 0 overwrites it

    // prefetch bm tile 0 into buffer 0 (Qs region)
    #pragma unroll
    for (int i = 0; i < 4; i++) {
        int c = tid + i * 256;
        int r = c >> 3, seg = (c & 7) * 4;
        cp16(smAddr + (uint32_t)(r * 36 + seg) * 4,
             bmb + (size_t)r * (NTOK / 2) + seg);
    }
    cp_commit();

    float m0r = -1e30f, m1r = -1e30f, l0r = 0.f, l1r = 0.f;
    float o[4][4];
    #pragma unroll
    for (int nf = 0; nf < 4; nf++)
        #pragma unroll
        for (int e = 0; e < 4; e++) o[nf][e] = 0.f;

    for (int kt = 0; kt < 8; kt++) {
        int cur = kt & 1;
        cp_wait0();     // K[cur] (kt>0) and bm[cur] complete
        // transpose-store V tile (loaded last iter) into Vt[d][key]
        {
            int c0 = tid, c1 = tid + 256;
            int key0 = c0 >> 3, seg0 = (c0 & 7) * 4;
            int key1 = c1 >> 3, seg1 = (c1 & 7) * 4;
            Vt[(seg0 + 0) * 68 + key0] = vr0.x;
            Vt[(seg0 + 1) * 68 + key0] = vr0.y;
            Vt[(seg0 + 2) * 68 + key0] = vr0.z;
            Vt[(seg0 + 3) * 68 + key0] = vr0.w;
            Vt[(seg1 + 0) * 68 + key1] = vr1.x;
            Vt[(seg1 + 1) * 68 + key1] = vr1.y;
            Vt[(seg1 + 2) * 68 + key1] = vr1.z;
            Vt[(seg1 + 3) * 68 + key1] = vr1.w;
        }
        __syncthreads();

        if (kt < 7) {
            int nxt = cur ^ 1;
            // prefetch next K tile
            const float* ksrc = Kb + (size_t)(kt + 1) * 64 * HDIM;
            #pragma unroll
            for (int i = 0; i < 2; i++) {
                int c = tid + i * 256;
                int r = c >> 3, q = c & 7;
                cp16(kAddr + (uint32_t)(nxt * 2304 + r * 36 + q * 4) * 4,
                     ksrc + (size_t)r * HDIM + q * 4);
            }
            // prefetch next bm tile into other buffer
            uint32_t bmo = nxt ? (uint32_t)BM_BUF1 : 0u;
            int pb = (kt + 1) * 32;
            #pragma unroll
            for (int i = 0; i < 4; i++) {
                int c = tid + i * 256;
                int r = c >> 3, seg = (c & 7) * 4;
                cp16(smAddr + (bmo + (uint32_t)(r * 36 + seg)) * 4,
                     bmb + (size_t)r * (NTOK / 2) + pb + seg);
            }
            cp_commit();
            // prefetch next V into regs
            const float* vsrc = Vb + (size_t)(kt + 1) * 64 * HDIM;
            int c0 = tid, c1 = tid + 256;
            vr0 = *(const float4*)(vsrc + (size_t)(c0 >> 3) * HDIM + (c0 & 7) * 4);
            vr1 = *(const float4*)(vsrc + (size_t)(c1 >> 3) * HDIM + (c1 & 7) * 4);
        }

        // ---- S = Q @ K^T : warp computes [16 q][64 key] ----
        float s[8][4];
        #pragma unroll
        for (int nf = 0; nf < 8; nf++)
            #pragma unroll
            for (int e = 0; e < 4; e++) s[nf][e] = 0.f;

        const float* kc = Ks + cur * 2304;
        #pragma unroll
        for (int ks = 0; ks < 4; ks++) {
            #pragma unroll
            for (int nf = 0; nf < 8; nf++) {
                const float* bp = kc + (nf * 8 + g) * 36 + ks * 8 + t;
                uint32_t bf[2] = { __float_as_uint(bp[0]), __float_as_uint(bp[4]) };
                mma_tf32(s[nf], qf[ks], bf);
            }
        }

        // ---- fused bias+mask (bf16x2 from SMEM) + online softmax (exp2) ----
        const uint32_t* bmS = (const uint32_t*)(sm + (cur ? BM_BUF1 : 0));
        float lm0 = -1e30f, lm1 = -1e30f;
        #pragma unroll
        for (int nf = 0; nf < 8; nf++) {
            uint32_t u0 = bmS[row_l * 36 + nf * 4 + t];
            uint32_t u1 = bmS[(row_l + 8) * 36 + nf * 4 + t];
            s[nf][0] += __uint_as_float(u0 << 16);
            s[nf][1] += __uint_as_float(u0 & 0xffff0000u);
            s[nf][2] += __uint_as_float(u1 << 16);
            s[nf][3] += __uint_as_float(u1 & 0xffff0000u);
            lm0 = fmaxf(lm0, fmaxf(s[nf][0], s[nf][1]));
            lm1 = fmaxf(lm1, fmaxf(s[nf][2], s[nf][3]));
        }
        lm0 = fmaxf(lm0, __shfl_xor_sync(0xffffffffu, lm0, 1));
        lm0 = fmaxf(lm0, __shfl_xor_sync(0xffffffffu, lm0, 2));
        lm1 = fmaxf(lm1, __shfl_xor_sync(0xffffffffu, lm1, 1));
        lm1 = fmaxf(lm1, __shfl_xor_sync(0xffffffffu, lm1, 2));

        float nm0 = fmaxf(m0r, lm0), nm1 = fmaxf(m1r, lm1);
        float cr0 = ex2f(m0r - nm0), cr1 = ex2f(m1r - nm1);
        m0r = nm0; m1r = nm1;

        float ls0 = 0.f, ls1 = 0.f;
        #pragma unroll
        for (int nf = 0; nf < 8; nf++) {
            float p0 = ex2f(s[nf][0] - nm0);
            float p1 = ex2f(s[nf][1] - nm0);
            float p2 = ex2f(s[nf][2] - nm1);
            float p3 = ex2f(s[nf][3] - nm1);
            ls0 += p0 + p1; ls1 += p2 + p3;
            float2 w0, w1;
            w0.x = __uint_as_float(f2tf32(p0));
            w0.y = __uint_as_float(f2tf32(p1));
            w1.x = __uint_as_float(f2tf32(p2));
            w1.y = __uint_as_float(f2tf32(p3));
            *(float2*)(Ps + row_l * 68 + nf * 8 + 2 * t) = w0;
            *(float2*)(Ps + (row_l + 8) * 68 + nf * 8 + 2 * t) = w1;
        }
        ls0 += __shfl_xor_sync(0xffffffffu, ls0, 1);
        ls0 += __shfl_xor_sync(0xffffffffu, ls0, 2);
        ls1 += __shfl_xor_sync(0xffffffffu, ls1, 1);
        ls1 += __shfl_xor_sync(0xffffffffu, ls1, 2);
        l0r = l0r * cr0 + ls0;
        l1r = l1r * cr1 + ls1;

        #pragma unroll
        for (int nf = 0; nf < 4; nf++) {
            o[nf][0] *= cr0; o[nf][1] *= cr0;
            o[nf][2] *= cr1; o[nf][3] *= cr1;
        }
        __syncwarp();   // Ps rows are warp-private

        // ---- O += P @ V : warp computes [16 q][32 d] ----
        #pragma unroll
        for (int ks = 0; ks < 8; ks++) {
            uint32_t af[4];
            const float* pa = Ps + row_l * 68 + ks * 8 + t;
            af[0] = __float_as_uint(pa[0]);
            af[1] = __float_as_uint(pa[8 * 68]);
            af[2] = __float_as_uint(pa[4]);
            af[3] = __float_as_uint(pa[8 * 68 + 4]);
            #pragma unroll
            for (int nf = 0; nf < 4; nf++) {
                const float* vp = Vt + (nf * 8 + g) * 68 + ks * 8 + t;
                uint32_t bf[2] = { __float_as_uint(vp[0]), __float_as_uint(vp[4]) };
                mma_tf32(o[nf], af, bf);
            }
        }
        __syncthreads();   // all PV/bm reads done before next tile overwrites
    }

    // epilogue
    float inv0 = 1.f / l0r, inv1 = 1.f / l1r;
    int tok0 = q0 + row_l, tok1 = tok0 + 8;
    float* ob0 = g_att + ((size_t)b * NTOK + tok0) * CDIM + h * HDIM;
    float* ob1 = g_att + ((size_t)b * NTOK + tok1) * CDIM + h * HDIM;
    #pragma unroll
    for (int nf = 0; nf < 4; nf++) {
        float2 w0, w1;
        w0.x = __uint_as_float(f2tf32(o[nf][0] * inv0));
        w0.y = __uint_as_float(f2tf32(o[nf][1] * inv0));
        w1.x = __uint_as_float(f2tf32(o[nf][2] * inv1));
        w1.y = __uint_as_float(f2tf32(o[nf][3] * inv1));
        *(float2*)(ob0 + nf * 8 + 2 * t) = w0;
        *(float2*)(ob1 + nf * 8 + 2 * t) = w1;
    }
}

// ---------------------------------------------------------------------------
// Host launch
// ---------------------------------------------------------------------------
extern "C" void kernel_launch(void* const* d_in, const int* in_sizes, int n_in,
                              void* d_out, int out_size)
{
    const float *x = nullptr, *mask = nullptr, *qkv_w = nullptr, *qkv_b = nullptr;
    const float *proj_w = nullptr, *proj_b = nullptr;
    const float *pos_proj_w = nullptr, *pos_proj_b = nullptr;
    const float *ln1_g = nullptr, *ln1_b = nullptr, *pos1_w = nullptr, *pos1_b = nullptr;
    const float *ln2_g = nullptr, *ln2_b = nullptr, *pos2_w = nullptr, *pos2_b = nullptr;
    const float *ln3_g = nullptr, *ln3_b = nullptr, *pos3_w = nullptr, *pos3_b = nullptr;

    int cnt24 = 0, cnt576 = 0;
    for (int i = 0; i < n_in; i++) {
        int sz = in_sizes[i];
        const float* p = (const float*)d_in[i];
        switch (sz) {
            case 12582912: x = p; break;
            case 2097152:  mask = p; break;
            case 442368:   qkv_w = p; break;
            case 1152:     qkv_b = p; break;
            case 147456:   proj_w = p; break;
            case 384:      proj_b = p; break;
            case 72:       pos_proj_w = p; break;
            case 288:      pos3_w = p; break;
            case 12:       pos3_b = p; break;
            case 576:
                if (cnt576 == 0) pos1_w = p; else pos2_w = p;
                cnt576++;
                break;
            case 24: {
                switch (cnt24) {
                    case 0: pos_proj_b = p; break;
                    case 1: ln1_g = p; break;
                    case 2: ln1_b = p; break;
                    case 3: pos1_b = p; break;
                    case 4: ln2_g = p; break;
                    case 5: ln2_b = p; break;
                    case 6: pos2_b = p; break;
                    case 7: ln3_g = p; break;
                    case 8: ln3_b = p; break;
                }
                cnt24++;
                break;
            }
            default: break;
        }
    }

    float* x32;      cudaGetSymbolAddress((void**)&x32, g_x32);
    uint32_t* wqkv;  cudaGetSymbolAddress((void**)&wqkv, g_wqkv);
    uint32_t* wproj; cudaGetSymbolAddress((void**)&wproj, g_wproj);

    const int SMEM_GEMM = (2 * AWORDS + 2 * BWORDS) * 4;
    const int SMEM_ATT = ATT_SMEM_FLOATS * 4;
    cudaFuncSetAttribute(mma_gemm, cudaFuncAttributeMaxDynamicSharedMemorySize,
                         SMEM_GEMM);
    cudaFuncSetAttribute(attn_kernel, cudaFuncAttributeMaxDynamicSharedMemorySize,
                         SMEM_ATT);

    // 1. pos MLP table
    pos_mlp_kernel<<<(LPOS + 127) / 128, 128>>>(
        pos_proj_w, pos_proj_b,
        ln1_g, ln1_b, pos1_w, pos1_b,
        ln2_g, ln2_b, pos2_w, pos2_b,
        ln3_g, ln3_b, pos3_w, pos3_b);

    // 2. fused bias+mask table (bf16x2, log2e-scaled)
    bm_fill_kernel<<<(NTOK * NTOK / 2) / 256, 256>>>(mask);

    // 2b. pre-convert / pre-permute operands
    cvt_tf32_kernel<<<(BWIN * NTOK * CDIM / 4 + 255) / 256, 256>>>(
        x, x32, BWIN * NTOK * CDIM);
    permute_w_kernel<<<(CDIM * 3 * CDIM + 255) / 256, 256>>>(
        qkv_w, wqkv, CDIM, 3 * CDIM);
    permute_w_kernel<<<(CDIM * CDIM + 255) / 256, 256>>>(
        proj_w, wproj, CDIM, CDIM);

    // 3. QKV GEMM + scatter (rounds Q/K/V to tf32; Q scaled for exp2 domain)
    mma_gemm<<<dim3(3 * CDIM / 128, (BWIN * NTOK) / 128), 256, SMEM_GEMM>>>(
        x32, wqkv, qkv_b, 3 * CDIM, 0, nullptr);

    // 4. fused attention (tensor cores, fully cp.async-prefetched)
    attn_kernel<<<dim3(NTOK / 128, NHEAD, BWIN), 256, SMEM_ATT>>>();

    // 5. output projection
    mma_gemm<<<dim3(CDIM / 128, (BWIN * NTOK) / 128), 256, SMEM_GEMM>>>(
        nullptr, wproj, proj_b, CDIM, 1, (float*)d_out);

    (void)out_size;
}

// round 15
// speedup vs baseline: 3.7029x; 1.0317x over previous
#include <cuda_runtime.h>
#include <math.h>
#include <stdint.h>

// ---------------------------------------------------------------------------
// Problem constants
// ---------------------------------------------------------------------------
#define BWIN   64
#define NTOK   512
#define CDIM   384
#define NHEAD  12
#define HDIM   32
#define LPOS   3375
#define PDIM   24
#define NGRP   8
#define SCALE  0.17677669529663687f
#define LOG2E  1.4426950408889634f
#define QSCALE (SCALE * LOG2E)
#define CSHIFT 8.0f          // fixed softmax shift, applied EXACTLY via mma acc init
#define NCH    12            // 384 / 32 k-chunks

// ---------------------------------------------------------------------------
// Scratch
// ---------------------------------------------------------------------------
__device__ float    g_pos[LPOS * NHEAD];
__device__ uint32_t g_bmp[(size_t)NGRP * NHEAD * NTOK * (NTOK / 2)]; // bf16x2 (b+m)*log2e
__device__ float    g_Q[BWIN * NHEAD * NTOK * HDIM];   // tf32, *SCALE*log2e
__device__ float    g_K[BWIN * NHEAD * NTOK * HDIM];   // tf32
__device__ float    g_V[BWIN * NHEAD * NTOK * HDIM];   // tf32
__device__ float    g_att[BWIN * NTOK * CDIM];         // attn out, tf32
__device__ float    g_x32[BWIN * NTOK * CDIM];         // x pre-rounded to tf32
__device__ uint32_t g_wqkv[CDIM * 3 * CDIM];           // qkv_w permuted tf32
__device__ uint32_t g_wproj[CDIM * CDIM];              // proj_w permuted tf32

// ---------------------------------------------------------------------------
// helpers
// ---------------------------------------------------------------------------
__device__ __forceinline__ uint32_t f2tf32(float f) {
    uint32_t r;
    asm("cvt.rna.tf32.f32 %0, %1;" : "=r"(r) : "f"(f));
    return r;
}
__device__ __forceinline__ float ex2f(float x) {
    float r;
    asm("ex2.approx.ftz.f32 %0, %1;" : "=f"(r) : "f"(x));
    return r;
}
__device__ __forceinline__ uint32_t pack_bf16x2(float lo, float hi) {
    uint32_t r;
    asm("cvt.rn.bf16x2.f32 %0, %1, %2;" : "=r"(r) : "f"(hi), "f"(lo));
    return r;
}
__device__ __forceinline__ void mma_tf32(float c[4], const uint32_t a[4],
                                         const uint32_t b[2]) {
    asm volatile(
        "mma.sync.aligned.m16n8k8.row.col.f32.tf32.tf32.f32 "
        "{%0,%1,%2,%3}, {%4,%5,%6,%7}, {%8,%9}, {%0,%1,%2,%3};"
        : "+f"(c[0]), "+f"(c[1]), "+f"(c[2]), "+f"(c[3])
        : "r"(a[0]), "r"(a[1]), "r"(a[2]), "r"(a[3]),
          "r"(b[0]), "r"(b[1]));
}
__device__ __forceinline__ uint32_t smem_u32(const void* p) {
    uint32_t a;
    asm("{ .reg .u64 t; cvta.to.shared.u64 t, %1; cvt.u32.u64 %0, t; }"
        : "=r"(a) : "l"(p));
    return a;
}
__device__ __forceinline__ void cp16(uint32_t dst, const void* src) {
    asm volatile("cp.async.cg.shared.global [%0], [%1], 16;"
                 :: "r"(dst), "l"(src) : "memory");
}
__device__ __forceinline__ void cp_commit() {
    asm volatile("cp.async.commit_group;" ::: "memory");
}
__device__ __forceinline__ void cp_wait0() {
    asm volatile("cp.async.wait_group 0;" ::: "memory");
}
__device__ __forceinline__ void cp_wait1() {
    asm volatile("cp.async.wait_group 1;" ::: "memory");
}

// ---------------------------------------------------------------------------
// Pre-pass: round fp32 -> tf32 bits
// ---------------------------------------------------------------------------
__global__ void cvt_tf32_kernel(const float* __restrict__ in,
                                float* __restrict__ out, int n) {
    int i = (blockIdx.x * blockDim.x + threadIdx.x) * 4;
    if (i >= n) return;
    float4 v = *(const float4*)(in + i);
    float4 r;
    r.x = __uint_as_float(f2tf32(v.x));
    r.y = __uint_as_float(f2tf32(v.y));
    r.z = __uint_as_float(f2tf32(v.z));
    r.w = __uint_as_float(f2tf32(v.w));
    *(float4*)(out + i) = r;
}

// ---------------------------------------------------------------------------
// Pre-pass: permute weight [K][Ntot] into mma fragment order
// ---------------------------------------------------------------------------
__global__ void permute_w_kernel(const float* __restrict__ W,
                                 uint32_t* __restrict__ out, int K, int Ntot) {
    int idx = blockIdx.x * blockDim.x + threadIdx.x;
    if (idx >= K * Ntot) return;
    int k = idx / Ntot, n = idx % Ntot;
    uint32_t val = f2tf32(W[(size_t)k * Ntot + n]);
    int kc = k >> 5, ks = (k >> 3) & 3, kt = k & 7;
    int t = kt & 3, hi = kt >> 2;
    int n0 = n >> 7, wn = (n >> 5) & 3, nf = (n >> 3) & 3, g = n & 7;
    int lane = g * 4 + t;
    size_t chunk = (size_t)n0 * NCH + kc;
    size_t off = chunk * 4096 + (((wn * 4 + ks) * 4 + nf) * 32 + lane) * 2 + hi;
    out[off] = val;
}

// ---------------------------------------------------------------------------
// Kernel 1: dynamic position-bias MLP
// ---------------------------------------------------------------------------
__device__ __forceinline__ void ln_relu(const float* in, float* t,
                                        const float* g, const float* bt) {
    float m = 0.f;
    #pragma unroll
    for (int i = 0; i < PDIM; i++) m += in[i];
    m *= (1.0f / PDIM);
    float v = 0.f;
    #pragma unroll
    for (int i = 0; i < PDIM; i++) { float d = in[i] - m; v += d * d; }
    v *= (1.0f / PDIM);
    float inv = rsqrtf(v + 1e-5f);
    #pragma unroll
    for (int i = 0; i < PDIM; i++) {
        float y = (in[i] - m) * inv * g[i] + bt[i];
        t[i] = fmaxf(y, 0.f);
    }
}

__global__ void pos_mlp_kernel(
    const float* __restrict__ pw,  const float* __restrict__ pb,
    const float* __restrict__ g1,  const float* __restrict__ b1,
    const float* __restrict__ w1,  const float* __restrict__ wb1,
    const float* __restrict__ g2,  const float* __restrict__ b2,
    const float* __restrict__ w2,  const float* __restrict__ wb2,
    const float* __restrict__ g3,  const float* __restrict__ b3,
    const float* __restrict__ w3,  const float* __restrict__ wb3)
{
    int l = blockIdx.x * blockDim.x + threadIdx.x;
    if (l >= LPOS) return;
    float c0 = (float)(l / 225 - 7);
    float c1 = (float)((l / 15) % 15 - 7);
    float c2 = (float)(l % 15 - 7);

    float v0[PDIM], v1[PDIM], v2[PDIM], t[PDIM];
    #pragma unroll
    for (int o = 0; o < PDIM; o++)
        v0[o] = c0 * pw[o] + c1 * pw[PDIM + o] + c2 * pw[2 * PDIM + o] + pb[o];

    ln_relu(v0, t, g1, b1);
    #pragma unroll
    for (int o = 0; o < PDIM; o++) {
        float s = wb1[o];
        #pragma unroll
        for (int i = 0; i < PDIM; i++) s = fmaf(t[i], w1[i * PDIM + o], s);
        v1[o] = s;
    }
    ln_relu(v1, t, g2, b2);
    #pragma unroll
    for (int o = 0; o < PDIM; o++) {
        float s = wb2[o];
        #pragma unroll
        for (int i = 0; i < PDIM; i++) s = fmaf(t[i], w2[i * PDIM + o], s);
        v2[o] = s;
    }
    ln_relu(v2, t, g3, b3);
    #pragma unroll
    for (int o = 0; o < NHEAD; o++) {
        float s = wb3[o];
        #pragma unroll
        for (int i = 0; i < PDIM; i++) s = fmaf(t[i], w3[i * NHEAD + o], s);
        g_pos[l * NHEAD + o] = s;
    }
}

// ---------------------------------------------------------------------------
// Kernel 2: fused bias+mask table, bf16x2, scaled by log2e.
// NOTE: no shift folded here -- bm values stay small so bf16 abs error ~4e-4.
// ---------------------------------------------------------------------------
__global__ void bm_fill_kernel(const float* __restrict__ mask) {
    int t = blockIdx.x * blockDim.x + threadIdx.x;   // 512*256 threads
    int n = t >> 8, mt = t & 255;
    int m0 = mt * 2, m1 = m0 + 1;
    int i1 = n >> 6, j1 = (n >> 3) & 7, k1 = n & 7;

    int i20 = m0 >> 6, j20 = (m0 >> 3) & 7, k20 = m0 & 7;
    int i21 = m1 >> 6, j21 = (m1 >> 3) & 7, k21 = m1 & 7;
    int idx0 = ((i1 - i20 + 7) * 15 + (j1 - j20 + 7)) * 15 + (k1 - k20 + 7);
    int idx1 = ((i1 - i21 + 7) * 15 + (j1 - j21 + 7)) * 15 + (k1 - k21 + 7);

    float pv0[NHEAD], pv1[NHEAD];
    #pragma unroll
    for (int h = 0; h < NHEAD; h++) {
        pv0[h] = g_pos[idx0 * NHEAD + h];
        pv1[h] = g_pos[idx1 * NHEAD + h];
    }
    #pragma unroll
    for (int grp = 0; grp < NGRP; grp++) {
        float mv0 = mask[((size_t)grp * NTOK + n) * NTOK + m0];
        float mv1 = mask[((size_t)grp * NTOK + n) * NTOK + m1];
        #pragma unroll
        for (int h = 0; h < NHEAD; h++) {
            float lo = (pv0[h] + mv0) * LOG2E;
            float hi = (pv1[h] + mv1) * LOG2E;
            g_bmp[(((size_t)grp * NHEAD + h) * NTOK + n) * (NTOK / 2) + mt] =
                pack_bf16x2(lo, hi);
        }
    }
}

// ---------------------------------------------------------------------------
// Kernel 3/5: tf32 mma.sync GEMM (pipelined; QKV epilogue rounds to tf32,
// Q additionally scaled by SCALE*log2e for the exp2 softmax domain)
// ---------------------------------------------------------------------------
#define AWORDS 4608   // 128 * 36
#define BWORDS 4096   // 128n * 32k

__global__ __launch_bounds__(256, 2)
void mma_gemm(const float* __restrict__ Aglob, const uint32_t* __restrict__ Wperm,
              const float* __restrict__ bias, int Ntot, int mode,
              float* __restrict__ out)
{
    extern __shared__ uint32_t sbuf[];
    uint32_t* Abuf = sbuf;
    uint32_t* Bbuf = sbuf + 2 * AWORDS;

    const float* A = (mode == 1) ? g_att : Aglob;
    int tid = threadIdx.x;
    int wid = tid >> 5, lane = tid & 31;
    int g = lane >> 2, t = lane & 3;
    int wm = (wid & 1) * 64;
    int wn_idx = wid >> 1;

    int m0 = blockIdx.y * 128;
    int n0t = blockIdx.x;
    int n0 = n0t * 128;

    uint32_t aAddr = smem_u32(Abuf);
    uint32_t bAddr = smem_u32(Bbuf);
    const float* Arow = A + (size_t)m0 * CDIM;
    const uint32_t* Wbase = Wperm + (size_t)n0t * NCH * BWORDS;

    float acc[4][4][4];
    #pragma unroll
    for (int mf = 0; mf < 4; mf++)
        #pragma unroll
        for (int nf = 0; nf < 4; nf++)
            #pragma unroll
            for (int e = 0; e < 4; e++) acc[mf][nf][e] = 0.f;

    {
        uint32_t ad = aAddr;
        #pragma unroll
        for (int i = 0; i < 4; i++) {
            int c = tid + i * 256;
            int r = c >> 3, q = c & 7;
            cp16(ad + (uint32_t)(r * 36 + q * 4) * 4, Arow + (size_t)r * CDIM + q * 4);
        }
        uint32_t bd = bAddr;
        const uint32_t* src = Wbase;
        #pragma unroll
        for (int i = 0; i < 4; i++) {
            int c = tid + i * 256;
            cp16(bd + (uint32_t)c * 16, src + (size_t)c * 4);
        }
        cp_commit();
    }

    for (int kc = 0; kc < NCH; kc++) {
        int cur = kc & 1;
        if (kc + 1 < NCH) {
            int nxt = cur ^ 1;
            uint32_t ad = aAddr + (uint32_t)nxt * AWORDS * 4;
            const float* arow = Arow + (kc + 1) * 32;
            #pragma unroll
            for (int i = 0; i < 4; i++) {
                int c = tid + i * 256;
                int r = c >> 3, q = c & 7;
                cp16(ad + (uint32_t)(r * 36 + q * 4) * 4,
                     arow + (size_t)r * CDIM + q * 4);
            }
            uint32_t bd = bAddr + (uint32_t)nxt * BWORDS * 4;
            const uint32_t* src = Wbase + (size_t)(kc + 1) * BWORDS;
            #pragma unroll
            for (int i = 0; i < 4; i++) {
                int c = tid + i * 256;
                cp16(bd + (uint32_t)c * 16, src + (size_t)c * 4);
            }
            cp_commit();
            cp_wait1();
        } else {
            cp_wait0();
        }
        __syncthreads();

        const uint32_t* ab = Abuf + cur * AWORDS;
        const uint32_t* bb = Bbuf + cur * BWORDS + wn_idx * 1024;

        #pragma unroll
        for (int ks = 0; ks < 4; ks++) {
            uint32_t bf[4][2];
            const uint32_t* bks = bb + ks * 256 + lane * 2;
            #pragma unroll
            for (int nf = 0; nf < 4; nf++) {
                uint2 v = *(const uint2*)(bks + nf * 64);
                bf[nf][0] = v.x; bf[nf][1] = v.y;
            }
            uint32_t af[4][4];
            #pragma unroll
            for (int mf = 0; mf < 4; mf++) {
                int r = wm + mf * 16 + g;
                const uint32_t* a0 = ab + r * 36 + ks * 8 + t;
                af[mf][0] = a0[0];
                af[mf][1] = a0[8 * 36];
                af[mf][2] = a0[4];
                af[mf][3] = a0[8 * 36 + 4];
            }
            #pragma unroll
            for (int mf = 0; mf < 4; mf++)
                #pragma unroll
                for (int nf = 0; nf < 4; nf++)
                    mma_tf32(acc[mf][nf], af[mf], bf[nf]);
        }
        __syncthreads();
    }

    #pragma unroll
    for (int mf = 0; mf < 4; mf++) {
        #pragma unroll
        for (int nf = 0; nf < 4; nf++) {
            int rbase = m0 + wm + mf * 16 + g;
            int cbase = n0 + wn_idx * 32 + nf * 8 + 2 * t;
            #pragma unroll
            for (int e = 0; e < 4; e++) {
                int gm = rbase + (e >> 1) * 8;
                int gn = cbase + (e & 1);
                float val = acc[mf][nf][e] + bias[gn];
                if (mode == 0) {
                    int which = gn / CDIM;
                    int r = gn - which * CDIM;
                    int h = r >> 5, dd = r & 31;
                    int b = gm >> 9, tok = gm & 511;
                    size_t off = (((size_t)b * NHEAD + h) * NTOK + tok) * HDIM + dd;
                    if (which == 0)
                        g_Q[off] = __uint_as_float(f2tf32(val * QSCALE));
                    else if (which == 1)
                        g_K[off] = __uint_as_float(f2tf32(val));
                    else
                        g_V[off] = __uint_as_float(f2tf32(val));
                } else {
                    out[(size_t)gm * CDIM + gn] = val;
                }
            }
        }
    }
}

// ---------------------------------------------------------------------------
// Kernel 4: fused flash attention, tensor cores, FIXED-SHIFT softmax.
// The -8 shift is applied EXACTLY by initializing the S mma accumulators to
// -8.0f (uniform across all elements -> cancels in normalization). bm table
// stays small-valued (bf16-safe). No running max, no correction multiplies;
// l accumulates across tiles, reduced once at the end.
// SMEM words: [0..4608)      Qs (dead after qf hoist) -> bm buffer 0
//             [4608..9216)   Ks 2 x [64][36]
//             [9216..11392)  Vt [32][68]
//             [11392..20096) Ps [128][68]
//             [20096..24704) bm buffer 1
// ---------------------------------------------------------------------------
#define ATT_SMEM_FLOATS 24704
#define BM_BUF1 20096

__global__ __launch_bounds__(256, 2)
void attn_kernel()
{
    extern __shared__ float sm[];
    float* Qs = sm;                 // [128][36]; becomes bm buf 0
    float* Ks = sm + 4608;          // 2 x [64][36]
    float* Vt = sm + 9216;          // [32][68]
    float* Ps = sm + 11392;         // [128][68]

    int tid = threadIdx.x;
    int wid = tid >> 5, lane = tid & 31;
    int g = lane >> 2, t = lane & 3;
    int q0 = blockIdx.x * 128, h = blockIdx.y, b = blockIdx.z;

    const float* Qb = g_Q + (((size_t)b * NHEAD + h) * NTOK + q0) * HDIM;
    const float* Kb = g_K + ((size_t)b * NHEAD + h) * NTOK * HDIM;
    const float* Vb = g_V + ((size_t)b * NHEAD + h) * NTOK * HDIM;
    const uint32_t* bmb = g_bmp + ((size_t)((b & 7) * NHEAD + h)) * NTOK * (NTOK / 2)
                        + (size_t)q0 * (NTOK / 2);

    uint32_t smAddr = smem_u32(sm);
    uint32_t kAddr = smAddr + 4608 * 4;

    // prime: cp.async Q (128x32) + K tile 0 into buf 0
    #pragma unroll
    for (int i = 0; i < 4; i++) {
        int c = tid + i * 256;
        int r = c >> 3, q = c & 7;
        cp16(smAddr + (uint32_t)(r * 36 + q * 4) * 4, Qb + (size_t)r * HDIM + q * 4);
    }
    #pragma unroll
    for (int i = 0; i < 2; i++) {
        int c = tid + i * 256;
        int r = c >> 3, q = c & 7;
        cp16(kAddr + (uint32_t)(r * 36 + q * 4) * 4, Kb + (size_t)r * HDIM + q * 4);
    }
    cp_commit();

    // preload V tile 0 to regs
    float4 vr0, vr1;
    {
        int c0 = tid, c1 = tid + 256;
        vr0 = *(const float4*)(Vb + (size_t)(c0 >> 3) * HDIM + (c0 & 7) * 4);
        vr1 = *(const float4*)(Vb + (size_t)(c1 >> 3) * HDIM + (c1 & 7) * 4);
    }

    int row_l = wid * 16 + g;               // local row (in 0..127)

    // wait for Q+K0, hoist Q fragments into registers (loop-invariant)
    cp_wait0();
    __syncthreads();
    uint32_t qf[4][4];
    #pragma unroll
    for (int ks = 0; ks < 4; ks++) {
        const float* a0 = Qs + row_l * 36 + ks * 8 + t;
        qf[ks][0] = __float_as_uint(a0[0]);
        qf[ks][1] = __float_as_uint(a0[8 * 36]);
        qf[ks][2] = __float_as_uint(a0[4]);
        qf[ks][3] = __float_as_uint(a0[8 * 36 + 4]);
    }
    __syncthreads();   // all Qs reads done before bm tile 0 overwrites it

    // prefetch bm tile 0 into buffer 0 (Qs region)
    #pragma unroll
    for (int i = 0; i < 4; i++) {
        int c = tid + i * 256;
        int r = c >> 3, seg = (c & 7) * 4;
        cp16(smAddr + (uint32_t)(r * 36 + seg) * 4,
             bmb + (size_t)r * (NTOK / 2) + seg);
    }
    cp_commit();

    float l0r = 0.f, l1r = 0.f;
    float o[4][4];
    #pragma unroll
    for (int nf = 0; nf < 4; nf++)
        #pragma unroll
        for (int e = 0; e < 4; e++) o[nf][e] = 0.f;

    for (int kt = 0; kt < 8; kt++) {
        int cur = kt & 1;
        cp_wait0();     // K[cur] (kt>0) and bm[cur] complete
        // transpose-store V tile (loaded last iter) into Vt[d][key]
        {
            int c0 = tid, c1 = tid + 256;
            int key0 = c0 >> 3, seg0 = (c0 & 7) * 4;
            int key1 = c1 >> 3, seg1 = (c1 & 7) * 4;
            Vt[(seg0 + 0) * 68 + key0] = vr0.x;
            Vt[(seg0 + 1) * 68 + key0] = vr0.y;
            Vt[(seg0 + 2) * 68 + key0] = vr0.z;
            Vt[(seg0 + 3) * 68 + key0] = vr0.w;
            Vt[(seg1 + 0) * 68 + key1] = vr1.x;
            Vt[(seg1 + 1) * 68 + key1] = vr1.y;
            Vt[(seg1 + 2) * 68 + key1] = vr1.z;
            Vt[(seg1 + 3) * 68 + key1] = vr1.w;
        }
        __syncthreads();

        if (kt < 7) {
            int nxt = cur ^ 1;
            // prefetch next K tile
            const float* ksrc = Kb + (size_t)(kt + 1) * 64 * HDIM;
            #pragma unroll
            for (int i = 0; i < 2; i++) {
                int c = tid + i * 256;
                int r = c >> 3, q = c & 7;
                cp16(kAddr + (uint32_t)(nxt * 2304 + r * 36 + q * 4) * 4,
                     ksrc + (size_t)r * HDIM + q * 4);
            }
            // prefetch next bm tile into other buffer
            uint32_t bmo = nxt ? (uint32_t)BM_BUF1 : 0u;
            int pb = (kt + 1) * 32;
            #pragma unroll
            for (int i = 0; i < 4; i++) {
                int c = tid + i * 256;
                int r = c >> 3, seg = (c & 7) * 4;
                cp16(smAddr + (bmo + (uint32_t)(r * 36 + seg)) * 4,
                     bmb + (size_t)r * (NTOK / 2) + pb + seg);
            }
            cp_commit();
            // prefetch next V into regs
            const float* vsrc = Vb + (size_t)(kt + 1) * 64 * HDIM;
            int c0 = tid, c1 = tid + 256;
            vr0 = *(const float4*)(vsrc + (size_t)(c0 >> 3) * HDIM + (c0 & 7) * 4);
            vr1 = *(const float4*)(vsrc + (size_t)(c1 >> 3) * HDIM + (c1 & 7) * 4);
        }

        // ---- S = Q @ K^T - 8 : accumulators INIT to -CSHIFT (exact shift) ----
        float s[8][4];
        #pragma unroll
        for (int nf = 0; nf < 8; nf++)
            #pragma unroll
            for (int e = 0; e < 4; e++) s[nf][e] = -CSHIFT;

        const float* kc = Ks + cur * 2304;
        #pragma unroll
        for (int ks = 0; ks < 4; ks++) {
            #pragma unroll
            for (int nf = 0; nf < 8; nf++) {
                const float* bp = kc + (nf * 8 + g) * 36 + ks * 8 + t;
                uint32_t bf[2] = { __float_as_uint(bp[0]), __float_as_uint(bp[4]) };
                mma_tf32(s[nf], qf[ks], bf);
            }
        }

        // ---- fixed-shift softmax: p = exp2(s + bm) ----
        const uint32_t* bmS = (const uint32_t*)(sm + (cur ? BM_BUF1 : 0));
        #pragma unroll
        for (int nf = 0; nf < 8; nf++) {
            uint32_t u0 = bmS[row_l * 36 + nf * 4 + t];
            uint32_t u1 = bmS[(row_l + 8) * 36 + nf * 4 + t];
            float p0 = ex2f(s[nf][0] + __uint_as_float(u0 << 16));
            float p1 = ex2f(s[nf][1] + __uint_as_float(u0 & 0xffff0000u));
            float p2 = ex2f(s[nf][2] + __uint_as_float(u1 << 16));
            float p3 = ex2f(s[nf][3] + __uint_as_float(u1 & 0xffff0000u));
            l0r += p0 + p1;
            l1r += p2 + p3;
            float2 w0, w1;
            w0.x = __uint_as_float(f2tf32(p0));
            w0.y = __uint_as_float(f2tf32(p1));
            w1.x = __uint_as_float(f2tf32(p2));
            w1.y = __uint_as_float(f2tf32(p3));
            *(float2*)(Ps + row_l * 68 + nf * 8 + 2 * t) = w0;
            *(float2*)(Ps + (row_l + 8) * 68 + nf * 8 + 2 * t) = w1;
        }
        __syncwarp();   // Ps rows are warp-private

        // ---- O += P @ V : warp computes [16 q][32 d] ----
        #pragma unroll
        for (int ks = 0; ks < 8; ks++) {
            uint32_t af[4];
            const float* pa = Ps + row_l * 68 + ks * 8 + t;
            af[0] = __float_as_uint(pa[0]);
            af[1] = __float_as_uint(pa[8 * 68]);
            af[2] = __float_as_uint(pa[4]);
            af[3] = __float_as_uint(pa[8 * 68 + 4]);
            #pragma unroll
            for (int nf = 0; nf < 4; nf++) {
                const float* vp = Vt + (nf * 8 + g) * 68 + ks * 8 + t;
                uint32_t bf[2] = { __float_as_uint(vp[0]), __float_as_uint(vp[4]) };
                mma_tf32(o[nf], af, bf);
            }
        }
        __syncthreads();   // all PV/bm reads done before next tile overwrites
    }

    // epilogue: reduce l across the quad ONCE, then normalize
    l0r += __shfl_xor_sync(0xffffffffu, l0r, 1);
    l0r += __shfl_xor_sync(0xffffffffu, l0r, 2);
    l1r += __shfl_xor_sync(0xffffffffu, l1r, 1);
    l1r += __shfl_xor_sync(0xffffffffu, l1r, 2);
    float inv0 = 1.f / l0r, inv1 = 1.f / l1r;
    int tok0 = q0 + row_l, tok1 = tok0 + 8;
    float* ob0 = g_att + ((size_t)b * NTOK + tok0) * CDIM + h * HDIM;
    float* ob1 = g_att + ((size_t)b * NTOK + tok1) * CDIM + h * HDIM;
    #pragma unroll
    for (int nf = 0; nf < 4; nf++) {
        float2 w0, w1;
        w0.x = __uint_as_float(f2tf32(o[nf][0] * inv0));
        w0.y = __uint_as_float(f2tf32(o[nf][1] * inv0));
        w1.x = __uint_as_float(f2tf32(o[nf][2] * inv1));
        w1.y = __uint_as_float(f2tf32(o[nf][3] * inv1));
        *(float2*)(ob0 + nf * 8 + 2 * t) = w0;
        *(float2*)(ob1 + nf * 8 + 2 * t) = w1;
    }
}

// ---------------------------------------------------------------------------
// Host launch
// ---------------------------------------------------------------------------
extern "C" void kernel_launch(void* const* d_in, const int* in_sizes, int n_in,
                              void* d_out, int out_size)
{
    const float *x = nullptr, *mask = nullptr, *qkv_w = nullptr, *qkv_b = nullptr;
    const float *proj_w = nullptr, *proj_b = nullptr;
    const float *pos_proj_w = nullptr, *pos_proj_b = nullptr;
    const float *ln1_g = nullptr, *ln1_b = nullptr, *pos1_w = nullptr, *pos1_b = nullptr;
    const float *ln2_g = nullptr, *ln2_b = nullptr, *pos2_w = nullptr, *pos2_b = nullptr;
    const float *ln3_g = nullptr, *ln3_b = nullptr, *pos3_w = nullptr, *pos3_b = nullptr;

    int cnt24 = 0, cnt576 = 0;
    for (int i = 0; i < n_in; i++) {
        int sz = in_sizes[i];
        const float* p = (const float*)d_in[i];
        switch (sz) {
            case 12582912: x = p; break;
            case 2097152:  mask = p; break;
            case 442368:   qkv_w = p; break;
            case 1152:     qkv_b = p; break;
            case 147456:   proj_w = p; break;
            case 384:      proj_b = p; break;
            case 72:       pos_proj_w = p; break;
            case 288:      pos3_w = p; break;
            case 12:       pos3_b = p; break;
            case 576:
                if (cnt576 == 0) pos1_w = p; else pos2_w = p;
                cnt576++;
                break;
            case 24: {
                switch (cnt24) {
                    case 0: pos_proj_b = p; break;
                    case 1: ln1_g = p; break;
                    case 2: ln1_b = p; break;
                    case 3: pos1_b = p; break;
                    case 4: ln2_g = p; break;
                    case 5: ln2_b = p; break;
                    case 6: pos2_b = p; break;
                    case 7: ln3_g = p; break;
                    case 8: ln3_b = p; break;
                }
                cnt24++;
                break;
            }
            default: break;
        }
    }

    float* x32;      cudaGetSymbolAddress((void**)&x32, g_x32);
    uint32_t* wqkv;  cudaGetSymbolAddress((void**)&wqkv, g_wqkv);
    uint32_t* wproj; cudaGetSymbolAddress((void**)&wproj, g_wproj);

    const int SMEM_GEMM = (2 * AWORDS + 2 * BWORDS) * 4;
    const int SMEM_ATT = ATT_SMEM_FLOATS * 4;
    cudaFuncSetAttribute(mma_gemm, cudaFuncAttributeMaxDynamicSharedMemorySize,
                         SMEM_GEMM);
    cudaFuncSetAttribute(attn_kernel, cudaFuncAttributeMaxDynamicSharedMemorySize,
                         SMEM_ATT);

    // 1. pos MLP table
    pos_mlp_kernel<<<(LPOS + 127) / 128, 128>>>(
        pos_proj_w, pos_proj_b,
        ln1_g, ln1_b, pos1_w, pos1_b,
        ln2_g, ln2_b, pos2_w, pos2_b,
        ln3_g, ln3_b, pos3_w, pos3_b);

    // 2. fused bias+mask table (bf16x2, log2e-scaled, small values)
    bm_fill_kernel<<<(NTOK * NTOK / 2) / 256, 256>>>(mask);

    // 2b. pre-convert / pre-permute operands
    cvt_tf32_kernel<<<(BWIN * NTOK * CDIM / 4 + 255) / 256, 256>>>(
        x, x32, BWIN * NTOK * CDIM);
    permute_w_kernel<<<(CDIM * 3 * CDIM + 255) / 256, 256>>>(
        qkv_w, wqkv, CDIM, 3 * CDIM);
    permute_w_kernel<<<(CDIM * CDIM + 255) / 256, 256>>>(
        proj_w, wproj, CDIM, CDIM);

    // 3. QKV GEMM + scatter (rounds Q/K/V to tf32; Q scaled for exp2 domain)
    mma_gemm<<<dim3(3 * CDIM / 128, (BWIN * NTOK) / 128), 256, SMEM_GEMM>>>(
        x32, wqkv, qkv_b, 3 * CDIM, 0, nullptr);

    // 4. fused attention (tensor cores, exact fixed-shift softmax)
    attn_kernel<<<dim3(NTOK / 128, NHEAD, BWIN), 256, SMEM_ATT>>>();

    // 5. output projection
    mma_gemm<<<dim3(CDIM / 128, (BWIN * NTOK) / 128), 256, SMEM_GEMM>>>(
        nullptr, wproj, proj_b, CDIM, 1, (float*)d_out);

    (void)out_size;
}

// round 17
// speedup vs baseline: 5.3484x; 1.4444x over previous
#include <cuda_runtime.h>
#include <cuda_fp16.h>
#include <math.h>
#include <stdint.h>

// ---------------------------------------------------------------------------
// Problem constants
// ---------------------------------------------------------------------------
#define BWIN   64
#define NTOK   512
#define CDIM   384
#define NHEAD  12
#define HDIM   32
#define LPOS   3375
#define PDIM   24
#define NGRP   8
#define SCALE  0.17677669529663687f
#define LOG2E  1.4426950408889634f
#define QSCALE (SCALE * LOG2E)
#define CSHIFT 8.0f
#define NCH    12            // 384 / 32 k-chunks

// ---------------------------------------------------------------------------
// Scratch (fp16 operands everywhere on mma paths)
// ---------------------------------------------------------------------------
__device__ float    g_pos[LPOS * NHEAD];
__device__ uint32_t g_bmp[(size_t)NGRP * NHEAD * NTOK * (NTOK / 2)]; // bf16x2 (b+m)*log2e
__device__ __half   g_Qh[BWIN * NHEAD * NTOK * HDIM];  // fp16, *SCALE*log2e
__device__ __half   g_Kh[BWIN * NHEAD * NTOK * HDIM];
__device__ __half   g_Vh[BWIN * NHEAD * NTOK * HDIM];
__device__ __half   g_atth[BWIN * NTOK * CDIM];        // attn out fp16
__device__ __half   g_xh[BWIN * NTOK * CDIM];          // x fp16
__device__ __half   g_wqkvh[CDIM * 3 * CDIM];          // qkv_w permuted fp16 frag order
__device__ __half   g_wprojh[CDIM * CDIM];             // proj_w permuted fp16 frag order

// ---------------------------------------------------------------------------
// helpers
// ---------------------------------------------------------------------------
__device__ __forceinline__ float ex2f(float x) {
    float r;
    asm("ex2.approx.ftz.f32 %0, %1;" : "=f"(r) : "f"(x));
    return r;
}
__device__ __forceinline__ uint32_t pack_bf16x2(float lo, float hi) {
    uint32_t r;
    asm("cvt.rn.bf16x2.f32 %0, %1, %2;" : "=r"(r) : "f"(hi), "f"(lo));
    return r;
}
__device__ __forceinline__ uint32_t pack_f16x2(float lo, float hi) {
    uint32_t r;
    asm("cvt.rn.f16x2.f32 %0, %1, %2;" : "=r"(r) : "f"(hi), "f"(lo));
    return r;
}
__device__ __forceinline__ uint32_t prmt(uint32_t a, uint32_t b, uint32_t sel) {
    uint32_t r;
    asm("prmt.b32 %0, %1, %2, %3;" : "=r"(r) : "r"(a), "r"(b), "r"(sel));
    return r;
}
__device__ __forceinline__ void mma_f16(float c[4], const uint32_t a[4],
                                        const uint32_t b[2]) {
    asm volatile(
        "mma.sync.aligned.m16n8k16.row.col.f32.f16.f16.f32 "
        "{%0,%1,%2,%3}, {%4,%5,%6,%7}, {%8,%9}, {%0,%1,%2,%3};"
        : "+f"(c[0]), "+f"(c[1]), "+f"(c[2]), "+f"(c[3])
        : "r"(a[0]), "r"(a[1]), "r"(a[2]), "r"(a[3]),
          "r"(b[0]), "r"(b[1]));
}
__device__ __forceinline__ uint32_t smem_u32(const void* p) {
    uint32_t a;
    asm("{ .reg .u64 t; cvta.to.shared.u64 t, %1; cvt.u32.u64 %0, t; }"
        : "=r"(a) : "l"(p));
    return a;
}
__device__ __forceinline__ void cp16(uint32_t dst, const void* src) {
    asm volatile("cp.async.cg.shared.global [%0], [%1], 16;"
                 :: "r"(dst), "l"(src) : "memory");
}
__device__ __forceinline__ void cp_commit() {
    asm volatile("cp.async.commit_group;" ::: "memory");
}
__device__ __forceinline__ void cp_wait0() {
    asm volatile("cp.async.wait_group 0;" ::: "memory");
}
__device__ __forceinline__ void cp_wait1() {
    asm volatile("cp.async.wait_group 1;" ::: "memory");
}

// ---------------------------------------------------------------------------
// Pre-pass: fp32 -> fp16
// ---------------------------------------------------------------------------
__global__ void cvt_f16_kernel(const float* __restrict__ in,
                               __half* __restrict__ out, int n) {
    int i = (blockIdx.x * blockDim.x + threadIdx.x) * 4;
    if (i >= n) return;
    float4 v = *(const float4*)(in + i);
    uint2 w;
    w.x = pack_f16x2(v.x, v.y);
    w.y = pack_f16x2(v.z, v.w);
    *(uint2*)(out + i) = w;
}

// ---------------------------------------------------------------------------
// Pre-pass: permute weight [K][Ntot] into m16n8k16 fp16 fragment order.
// Per (ntile 128, kchunk 32): [wn(4)][ks(2)][nf(4)][lane(32)][wslot(2)] words.
// ---------------------------------------------------------------------------
__global__ void permute_w_kernel(const float* __restrict__ W,
                                 __half* __restrict__ out, int K, int Ntot) {
    int idx = blockIdx.x * blockDim.x + threadIdx.x;
    if (idx >= K * Ntot) return;
    int k = idx / Ntot, n = idx % Ntot;
    int kc = k >> 5, kk = k & 31;
    int ks = kk >> 4, kr = kk & 15;
    int wslot = kr >> 3, t = (kr >> 1) & 3, hi = kr & 1;
    int n0 = n >> 7, wn = (n >> 5) & 3, nf = (n >> 3) & 3, g = n & 7;
    int lane = g * 4 + t;
    size_t chunk = (size_t)n0 * NCH + kc;
    size_t word = chunk * 2048 + (((wn * 2 + ks) * 4 + nf) * 32 + lane) * 2 + wslot;
    out[word * 2 + hi] = __float2half_rn(W[(size_t)k * Ntot + n]);
}

// ---------------------------------------------------------------------------
// Kernel 1: dynamic position-bias MLP
// ---------------------------------------------------------------------------
__device__ __forceinline__ void ln_relu(const float* in, float* t,
                                        const float* g, const float* bt) {
    float m = 0.f;
    #pragma unroll
    for (int i = 0; i < PDIM; i++) m += in[i];
    m *= (1.0f / PDIM);
    float v = 0.f;
    #pragma unroll
    for (int i = 0; i < PDIM; i++) { float d = in[i] - m; v += d * d; }
    v *= (1.0f / PDIM);
    float inv = rsqrtf(v + 1e-5f);
    #pragma unroll
    for (int i = 0; i < PDIM; i++) {
        float y = (in[i] - m) * inv * g[i] + bt[i];
        t[i] = fmaxf(y, 0.f);
    }
}

__global__ void pos_mlp_kernel(
    const float* __restrict__ pw,  const float* __restrict__ pb,
    const float* __restrict__ g1,  const float* __restrict__ b1,
    const float* __restrict__ w1,  const float* __restrict__ wb1,
    const float* __restrict__ g2,  const float* __restrict__ b2,
    const float* __restrict__ w2,  const float* __restrict__ wb2,
    const float* __restrict__ g3,  const float* __restrict__ b3,
    const float* __restrict__ w3,  const float* __restrict__ wb3)
{
    int l = blockIdx.x * blockDim.x + threadIdx.x;
    if (l >= LPOS) return;
    float c0 = (float)(l / 225 - 7);
    float c1 = (float)((l / 15) % 15 - 7);
    float c2 = (float)(l % 15 - 7);

    float v0[PDIM], v1[PDIM], v2[PDIM], t[PDIM];
    #pragma unroll
    for (int o = 0; o < PDIM; o++)
        v0[o] = c0 * pw[o] + c1 * pw[PDIM + o] + c2 * pw[2 * PDIM + o] + pb[o];

    ln_relu(v0, t, g1, b1);
    #pragma unroll
    for (int o = 0; o < PDIM; o++) {
        float s = wb1[o];
        #pragma unroll
        for (int i = 0; i < PDIM; i++) s = fmaf(t[i], w1[i * PDIM + o], s);
        v1[o] = s;
    }
    ln_relu(v1, t, g2, b2);
    #pragma unroll
    for (int o = 0; o < PDIM; o++) {
        float s = wb2[o];
        #pragma unroll
        for (int i = 0; i < PDIM; i++) s = fmaf(t[i], w2[i * PDIM + o], s);
        v2[o] = s;
    }
    ln_relu(v2, t, g3, b3);
    #pragma unroll
    for (int o = 0; o < NHEAD; o++) {
        float s = wb3[o];
        #pragma unroll
        for (int i = 0; i < PDIM; i++) s = fmaf(t[i], w3[i * NHEAD + o], s);
        g_pos[l * NHEAD + o] = s;
    }
}

// ---------------------------------------------------------------------------
// Kernel 2: fused bias+mask table, bf16x2, scaled by log2e (small values).
// ---------------------------------------------------------------------------
__global__ void bm_fill_kernel(const float* __restrict__ mask) {
    int t = blockIdx.x * blockDim.x + threadIdx.x;
    int n = t >> 8, mt = t & 255;
    int m0 = mt * 2, m1 = m0 + 1;
    int i1 = n >> 6, j1 = (n >> 3) & 7, k1 = n & 7;

    int i20 = m0 >> 6, j20 = (m0 >> 3) & 7, k20 = m0 & 7;
    int i21 = m1 >> 6, j21 = (m1 >> 3) & 7, k21 = m1 & 7;
    int idx0 = ((i1 - i20 + 7) * 15 + (j1 - j20 + 7)) * 15 + (k1 - k20 + 7);
    int idx1 = ((i1 - i21 + 7) * 15 + (j1 - j21 + 7)) * 15 + (k1 - k21 + 7);

    float pv0[NHEAD], pv1[NHEAD];
    #pragma unroll
    for (int h = 0; h < NHEAD; h++) {
        pv0[h] = g_pos[idx0 * NHEAD + h];
        pv1[h] = g_pos[idx1 * NHEAD + h];
    }
    #pragma unroll
    for (int grp = 0; grp < NGRP; grp++) {
        float mv0 = mask[((size_t)grp * NTOK + n) * NTOK + m0];
        float mv1 = mask[((size_t)grp * NTOK + n) * NTOK + m1];
        #pragma unroll
        for (int h = 0; h < NHEAD; h++) {
            float lo = (pv0[h] + mv0) * LOG2E;
            float hi = (pv1[h] + mv1) * LOG2E;
            g_bmp[(((size_t)grp * NHEAD + h) * NTOK + n) * (NTOK / 2) + mt] =
                pack_bf16x2(lo, hi);
        }
    }
}

// ---------------------------------------------------------------------------
// Kernel 3/5: fp16 m16n8k16 GEMM, pipelined cp.async, fragment-order B.
// A SMEM: [128 rows][20 words] (16 data + 4 pad -> conflict-free frags).
// mode 0: A=g_xh, W=g_wqkvh (Ntot=1152) -> scatter g_Qh/g_Kh/g_Vh
// mode 1: A=g_atth, W=g_wprojh (Ntot=384) -> out fp32 row-major
// ---------------------------------------------------------------------------
#define AW16 2560    // 128 * 20 words per buffer
#define BW16 2048    // words per chunk per ntile

__global__ __launch_bounds__(256, 2)
void mma_gemm(const __half* __restrict__ Aglob, const __half* __restrict__ Wperm,
              const float* __restrict__ bias, int Ntot, int mode,
              float* __restrict__ out)
{
    extern __shared__ uint32_t sbuf[];
    uint32_t* Abuf = sbuf;               // 2 * AW16
    uint32_t* Bbuf = sbuf + 2 * AW16;    // 2 * BW16

    const __half* A = (mode == 1) ? g_atth : Aglob;
    int tid = threadIdx.x;
    int wid = tid >> 5, lane = tid & 31;
    int g = lane >> 2, t = lane & 3;
    int wm = (wid & 1) * 64;
    int wn_idx = wid >> 1;

    int m0 = blockIdx.y * 128;
    int n0t = blockIdx.x;
    int n0 = n0t * 128;

    uint32_t aAddr = smem_u32(Abuf);
    uint32_t bAddr = smem_u32(Bbuf);
    const __half* Arow = A + (size_t)m0 * CDIM;
    const __half* Wbase = Wperm + (size_t)n0t * NCH * BW16 * 2;

    float acc[4][4][4];
    #pragma unroll
    for (int mf = 0; mf < 4; mf++)
        #pragma unroll
        for (int nf = 0; nf < 4; nf++)
            #pragma unroll
            for (int e = 0; e < 4; e++) acc[mf][nf][e] = 0.f;

    // stage chunk 0
    {
        #pragma unroll
        for (int i = 0; i < 2; i++) {
            int c = tid + i * 256;           // 0..511
            int r = c >> 2, q = c & 3;
            cp16(aAddr + (uint32_t)(r * 20 + q * 4) * 4,
                 Arow + (size_t)r * CDIM + q * 8);
        }
        #pragma unroll
        for (int i = 0; i < 2; i++) {
            int c = tid + i * 256;
            cp16(bAddr + (uint32_t)c * 16, Wbase + (size_t)c * 8);
        }
        cp_commit();
    }

    for (int kc = 0; kc < NCH; kc++) {
        int cur = kc & 1;
        if (kc + 1 < NCH) {
            int nxt = cur ^ 1;
            uint32_t ad = aAddr + (uint32_t)nxt * AW16 * 4;
            const __half* arow = Arow + (kc + 1) * 32;
            #pragma unroll
            for (int i = 0; i < 2; i++) {
                int c = tid + i * 256;
                int r = c >> 2, q = c & 3;
                cp16(ad + (uint32_t)(r * 20 + q * 4) * 4,
                     arow + (size_t)r * CDIM + q * 8);
            }
            uint32_t bd = bAddr + (uint32_t)nxt * BW16 * 4;
            const __half* src = Wbase + (size_t)(kc + 1) * BW16 * 2;
            #pragma unroll
            for (int i = 0; i < 2; i++) {
                int c = tid + i * 256;
                cp16(bd + (uint32_t)c * 16, src + (size_t)c * 8);
            }
            cp_commit();
            cp_wait1();
        } else {
            cp_wait0();
        }
        __syncthreads();

        const uint32_t* ab = Abuf + cur * AW16;
        const uint32_t* bb = Bbuf + cur * BW16 + wn_idx * 512;

        #pragma unroll
        for (int ks = 0; ks < 2; ks++) {
            uint32_t bf[4][2];
            const uint32_t* bks = bb + ks * 256 + lane * 2;
            #pragma unroll
            for (int nf = 0; nf < 4; nf++) {
                uint2 v = *(const uint2*)(bks + nf * 64);
                bf[nf][0] = v.x; bf[nf][1] = v.y;
            }
            uint32_t af[4][4];
            #pragma unroll
            for (int mf = 0; mf < 4; mf++) {
                int r = wm + mf * 16 + g;
                const uint32_t* a0 = ab + r * 20 + ks * 8 + t;
                af[mf][0] = a0[0];
                af[mf][1] = a0[8 * 20];
                af[mf][2] = a0[4];
                af[mf][3] = a0[8 * 20 + 4];
            }
            #pragma unroll
            for (int mf = 0; mf < 4; mf++)
                #pragma unroll
                for (int nf = 0; nf < 4; nf++)
                    mma_f16(acc[mf][nf], af[mf], bf[nf]);
        }
        __syncthreads();
    }

    #pragma unroll
    for (int mf = 0; mf < 4; mf++) {
        #pragma unroll
        for (int nf = 0; nf < 4; nf++) {
            int rbase = m0 + wm + mf * 16 + g;
            int cbase = n0 + wn_idx * 32 + nf * 8 + 2 * t;
            #pragma unroll
            for (int e = 0; e < 4; e++) {
                int gm = rbase + (e >> 1) * 8;
                int gn = cbase + (e & 1);
                float val = acc[mf][nf][e] + bias[gn];
                if (mode == 0) {
                    int which = gn / CDIM;
                    int r = gn - which * CDIM;
                    int h = r >> 5, dd = r & 31;
                    int b = gm >> 9, tok = gm & 511;
                    size_t off = (((size_t)b * NHEAD + h) * NTOK + tok) * HDIM + dd;
                    if (which == 0)
                        g_Qh[off] = __float2half_rn(val * QSCALE);
                    else if (which == 1)
                        g_Kh[off] = __float2half_rn(val);
                    else
                        g_Vh[off] = __float2half_rn(val);
                } else {
                    out[(size_t)gm * CDIM + gn] = val;
                }
            }
        }
    }
}

// ---------------------------------------------------------------------------
// Kernel 4: fused flash attention, full fp16 mma (m16n8k16).
// S = QK^T with acc init -8 (exact fixed shift); p = exp2(s + bm);
// P packed fp16x2 at softmax output; V transposed+packed via PRMT.
// SMEM words: [0..2560)       Qs [128][20] (dead after hoist)
//             [2560..5120)    Ks 2 x [64][20]
//             [5120..6272)    Vt [32][36] fp16x2 key-pairs
//             [6272..10880)   Ps [128][36] fp16x2
//             [10880..15488)  bm buf 0
//             [15488..20096)  bm buf 1
// ---------------------------------------------------------------------------
#define ATT_SMEM_WORDS 20096
#define KS_OFF 2560
#define VT_OFF 5120
#define PS_OFF 6272
#define BM0_OFF 10880
#define BM1_OFF 15488

__global__ __launch_bounds__(256, 2)
void attn_kernel()
{
    extern __shared__ uint32_t smw[];
    uint32_t* Qs = smw;
    uint32_t* Ks = smw + KS_OFF;
    uint32_t* Vtw = smw + VT_OFF;
    uint32_t* Psw = smw + PS_OFF;

    int tid = threadIdx.x;
    int wid = tid >> 5, lane = tid & 31;
    int g = lane >> 2, t = lane & 3;
    int q0 = blockIdx.x * 128, h = blockIdx.y, b = blockIdx.z;

    const __half* Qb = g_Qh + (((size_t)b * NHEAD + h) * NTOK + q0) * HDIM;
    const __half* Kb = g_Kh + ((size_t)b * NHEAD + h) * NTOK * HDIM;
    const __half* Vb = g_Vh + ((size_t)b * NHEAD + h) * NTOK * HDIM;
    const uint32_t* bmb = g_bmp + ((size_t)((b & 7) * NHEAD + h)) * NTOK * (NTOK / 2)
                        + (size_t)q0 * (NTOK / 2);

    uint32_t smAddr = smem_u32(smw);
    uint32_t kAddr = smAddr + KS_OFF * 4;

    // prime: Q (128x32 halfs) + K tile 0
    #pragma unroll
    for (int i = 0; i < 2; i++) {
        int c = tid + i * 256;
        int r = c >> 2, q = c & 3;
        cp16(smAddr + (uint32_t)(r * 20 + q * 4) * 4, Qb + (size_t)r * HDIM + q * 8);
    }
    {
        int r = tid >> 2, q = tid & 3;
        cp16(kAddr + (uint32_t)(r * 20 + q * 4) * 4, Kb + (size_t)r * HDIM + q * 8);
    }
    cp_commit();

    // preload V tile 0 to regs (key-pair layout)
    int kp = tid >> 3;          // 0..31 key-pair
    int db = (tid & 7) * 4;     // d block
    uint2 va, vb2;
    {
        const __half* vp = Vb + (size_t)(2 * kp) * HDIM + db;
        va  = *(const uint2*)vp;
        vb2 = *(const uint2*)(vp + HDIM);
    }

    int row_l = wid * 16 + g;

    // wait for Q+K0, hoist Q fragments (2 k-steps x 4 regs)
    cp_wait0();
    __syncthreads();
    uint32_t qf[2][4];
    #pragma unroll
    for (int ks = 0; ks < 2; ks++) {
        const uint32_t* a0 = Qs + row_l * 20 + ks * 8 + t;
        qf[ks][0] = a0[0];
        qf[ks][1] = a0[8 * 20];
        qf[ks][2] = a0[4];
        qf[ks][3] = a0[8 * 20 + 4];
    }

    // prefetch bm tile 0
    #pragma unroll
    for (int i = 0; i < 4; i++) {
        int c = tid + i * 256;
        int r = c >> 3, seg = (c & 7) * 4;
        cp16(smAddr + (uint32_t)(BM0_OFF + r * 36 + seg) * 4,
             bmb + (size_t)r * (NTOK / 2) + seg);
    }
    cp_commit();

    float l0r = 0.f, l1r = 0.f;
    float o[4][4];
    #pragma unroll
    for (int nf = 0; nf < 4; nf++)
        #pragma unroll
        for (int e = 0; e < 4; e++) o[nf][e] = 0.f;

    for (int kt = 0; kt < 8; kt++) {
        int cur = kt & 1;
        cp_wait0();
        // transpose-pack V tile into Vt[d][keypair] via PRMT
        {
            Vtw[(db + 0) * 36 + kp] = prmt(va.x, vb2.x, 0x5410);
            Vtw[(db + 1) * 36 + kp] = prmt(va.x, vb2.x, 0x7632);
            Vtw[(db + 2) * 36 + kp] = prmt(va.y, vb2.y, 0x5410);
            Vtw[(db + 3) * 36 + kp] = prmt(va.y, vb2.y, 0x7632);
        }
        __syncthreads();

        if (kt < 7) {
            int nxt = cur ^ 1;
            const __half* ksrc = Kb + (size_t)(kt + 1) * 64 * HDIM;
            {
                int r = tid >> 2, q = tid & 3;
                cp16(kAddr + (uint32_t)(nxt * 1280 + r * 20 + q * 4) * 4,
                     ksrc + (size_t)r * HDIM + q * 8);
            }
            uint32_t bmo = nxt ? (uint32_t)BM1_OFF : (uint32_t)BM0_OFF;
            int pb = (kt + 1) * 32;
            #pragma unroll
            for (int i = 0; i < 4; i++) {
                int c = tid + i * 256;
                int r = c >> 3, seg = (c & 7) * 4;
                cp16(smAddr + (bmo + (uint32_t)(r * 36 + seg)) * 4,
                     bmb + (size_t)r * (NTOK / 2) + pb + seg);
            }
            cp_commit();
            const __half* vsrc = Vb + (size_t)(kt + 1) * 64 * HDIM
                               + (size_t)(2 * kp) * HDIM + db;
            va  = *(const uint2*)vsrc;
            vb2 = *(const uint2*)(vsrc + HDIM);
        }

        // ---- S = Q @ K^T - 8 ----
        float s[8][4];
        #pragma unroll
        for (int nf = 0; nf < 8; nf++)
            #pragma unroll
            for (int e = 0; e < 4; e++) s[nf][e] = -CSHIFT;

        const uint32_t* kc = Ks + cur * 1280;
        #pragma unroll
        for (int ks = 0; ks < 2; ks++) {
            #pragma unroll
            for (int nf = 0; nf < 8; nf++) {
                const uint32_t* bp = kc + (nf * 8 + g) * 20 + ks * 8 + t;
                uint32_t bf[2] = { bp[0], bp[4] };
                mma_f16(s[nf], qf[ks], bf);
            }
        }

        // ---- fixed-shift softmax: p = exp2(s + bm), store P packed fp16 ----
        const uint32_t* bmS = smw + (cur ? BM1_OFF : BM0_OFF);
        #pragma unroll
        for (int nf = 0; nf < 8; nf++) {
            uint32_t u0 = bmS[row_l * 36 + nf * 4 + t];
            uint32_t u1 = bmS[(row_l + 8) * 36 + nf * 4 + t];
            float p0 = ex2f(s[nf][0] + __uint_as_float(u0 << 16));
            float p1 = ex2f(s[nf][1] + __uint_as_float(u0 & 0xffff0000u));
            float p2 = ex2f(s[nf][2] + __uint_as_float(u1 << 16));
            float p3 = ex2f(s[nf][3] + __uint_as_float(u1 & 0xffff0000u));
            l0r += p0 + p1;
            l1r += p2 + p3;
            Psw[row_l * 36 + nf * 4 + t]       = pack_f16x2(p0, p1);
            Psw[(row_l + 8) * 36 + nf * 4 + t] = pack_f16x2(p2, p3);
        }
        __syncwarp();   // Ps rows are warp-private

        // ---- O += P @ V : fp16 m16n8k16, 4 k-steps of 16 keys ----
        #pragma unroll
        for (int ks = 0; ks < 4; ks++) {
            uint32_t af[4];
            const uint32_t* pa = Psw + row_l * 36 + ks * 8 + t;
            af[0] = pa[0];
            af[1] = pa[8 * 36];
            af[2] = pa[4];
            af[3] = pa[8 * 36 + 4];
            #pragma unroll
            for (int nf = 0; nf < 4; nf++) {
                const uint32_t* vp = Vtw + (nf * 8 + g) * 36 + ks * 8 + t;
                uint32_t bf[2] = { vp[0], vp[4] };
                mma_f16(o[nf], af, bf);
            }
        }
        __syncthreads();
    }

    // epilogue: reduce l once, normalize, write fp16 pairs
    l0r += __shfl_xor_sync(0xffffffffu, l0r, 1);
    l0r += __shfl_xor_sync(0xffffffffu, l0r, 2);
    l1r += __shfl_xor_sync(0xffffffffu, l1r, 1);
    l1r += __shfl_xor_sync(0xffffffffu, l1r, 2);
    float inv0 = 1.f / l0r, inv1 = 1.f / l1r;
    int tok0 = q0 + row_l, tok1 = tok0 + 8;
    __half* ob0 = g_atth + ((size_t)b * NTOK + tok0) * CDIM + h * HDIM;
    __half* ob1 = g_atth + ((size_t)b * NTOK + tok1) * CDIM + h * HDIM;
    #pragma unroll
    for (int nf = 0; nf < 4; nf++) {
        *(uint32_t*)(ob0 + nf * 8 + 2 * t) = pack_f16x2(o[nf][0] * inv0, o[nf][1] * inv0);
        *(uint32_t*)(ob1 + nf * 8 + 2 * t) = pack_f16x2(o[nf][2] * inv1, o[nf][3] * inv1);
    }
}

// ---------------------------------------------------------------------------
// Host launch
// ---------------------------------------------------------------------------
extern "C" void kernel_launch(void* const* d_in, const int* in_sizes, int n_in,
                              void* d_out, int out_size)
{
    const float *x = nullptr, *mask = nullptr, *qkv_w = nullptr, *qkv_b = nullptr;
    const float *proj_w = nullptr, *proj_b = nullptr;
    const float *pos_proj_w = nullptr, *pos_proj_b = nullptr;
    const float *ln1_g = nullptr, *ln1_b = nullptr, *pos1_w = nullptr, *pos1_b = nullptr;
    const float *ln2_g = nullptr, *ln2_b = nullptr, *pos2_w = nullptr, *pos2_b = nullptr;
    const float *ln3_g = nullptr, *ln3_b = nullptr, *pos3_w = nullptr, *pos3_b = nullptr;

    int cnt24 = 0, cnt576 = 0;
    for (int i = 0; i < n_in; i++) {
        int sz = in_sizes[i];
        const float* p = (const float*)d_in[i];
        switch (sz) {
            case 12582912: x = p; break;
            case 2097152:  mask = p; break;
            case 442368:   qkv_w = p; break;
            case 1152:     qkv_b = p; break;
            case 147456:   proj_w = p; break;
            case 384:      proj_b = p; break;
            case 72:       pos_proj_w = p; break;
            case 288:      pos3_w = p; break;
            case 12:       pos3_b = p; break;
            case 576:
                if (cnt576 == 0) pos1_w = p; else pos2_w = p;
                cnt576++;
                break;
            case 24: {
                switch (cnt24) {
                    case 0: pos_proj_b = p; break;
                    case 1: ln1_g = p; break;
                    case 2: ln1_b = p; break;
                    case 3: pos1_b = p; break;
                    case 4: ln2_g = p; break;
                    case 5: ln2_b = p; break;
                    case 6: pos2_b = p; break;
                    case 7: ln3_g = p; break;
                    case 8: ln3_b = p; break;
                }
                cnt24++;
                break;
            }
            default: break;
        }
    }

    __half* xh;     cudaGetSymbolAddress((void**)&xh, g_xh);
    __half* wqkvh;  cudaGetSymbolAddress((void**)&wqkvh, g_wqkvh);
    __half* wprojh; cudaGetSymbolAddress((void**)&wprojh, g_wprojh);

    const int SMEM_GEMM = (2 * AW16 + 2 * BW16) * 4;
    const int SMEM_ATT = ATT_SMEM_WORDS * 4;
    cudaFuncSetAttribute(mma_gemm, cudaFuncAttributeMaxDynamicSharedMemorySize,
                         SMEM_GEMM);
    cudaFuncSetAttribute(attn_kernel, cudaFuncAttributeMaxDynamicSharedMemorySize,
                         SMEM_ATT);

    // 1. pos MLP table
    pos_mlp_kernel<<<(LPOS + 127) / 128, 128>>>(
        pos_proj_w, pos_proj_b,
        ln1_g, ln1_b, pos1_w, pos1_b,
        ln2_g, ln2_b, pos2_w, pos2_b,
        ln3_g, ln3_b, pos3_w, pos3_b);

    // 2. fused bias+mask table (bf16x2, log2e-scaled)
    bm_fill_kernel<<<(NTOK * NTOK / 2) / 256, 256>>>(mask);

    // 2b. convert x to fp16; permute weights to fp16 fragment order
    cvt_f16_kernel<<<(BWIN * NTOK * CDIM / 4 + 255) / 256, 256>>>(
        x, xh, BWIN * NTOK * CDIM);
    permute_w_kernel<<<(CDIM * 3 * CDIM + 255) / 256, 256>>>(
        qkv_w, wqkvh, CDIM, 3 * CDIM);
    permute_w_kernel<<<(CDIM * CDIM + 255) / 256, 256>>>(
        proj_w, wprojh, CDIM, CDIM);

    // 3. QKV GEMM (fp16) + scatter (Q scaled for exp2 domain)
    mma_gemm<<<dim3(3 * CDIM / 128, (BWIN * NTOK) / 128), 256, SMEM_GEMM>>>(
        xh, wqkvh, qkv_b, 3 * CDIM, 0, nullptr);

    // 4. fused attention (full fp16 mma, exact fixed-shift softmax)
    attn_kernel<<<dim3(NTOK / 128, NHEAD, BWIN), 256, SMEM_ATT>>>();

    // 5. output projection (fp16 mma, fp32 out)
    mma_gemm<<<dim3(CDIM / 128, (BWIN * NTOK) / 128), 256, SMEM_GEMM>>>(
        nullptr, wprojh, proj_b, CDIM, 1, (float*)d_out);

    (void)out_size;
}